// round 3
// baseline (speedup 1.0000x reference)
#include <cuda_runtime.h>
#include <cuda_bf16.h>
#include <math.h>

// ---------------- problem constants ----------------
#define BB 64
#define NN 512
#define RR 1024
#define EE 1024
#define KTOP 256
#define BR (BB*RR)          // 65536

// ---------------- device scratch (no allocations allowed) ----------------
__device__ float g_bufA[(long)BB*NN*RR];   // 134MB: masked GE, later X2, X3
__device__ float g_bufB[(long)BB*NN*RR];   // E1, later Y0, X2...
__device__ float g_bufC[(long)BB*NN*RR];   // E2, later X1, Y2
__device__ float g_adj [(long)BB*NN*NN];   // 67MB
__device__ float g_xcat[BB*3072];
__device__ float g_gates[BB*4096];
__device__ float g_gates2[BB*4096];
__device__ float g_hterm1[BB*RR];
__device__ float g_hterm2[BB*RR];
__device__ float g_pvec[BB*RR];
__device__ float g_srow[BB*NN];
__device__ float g_dvec[BB*NN];
__device__ float g_minv[BB];
__device__ float g_attv[BB*RR];
__device__ float g_xl[BB*2048];
__device__ float g_hatt[BR];
__device__ float g_catt[BR];
__device__ float g_hlang[BR];
__device__ float g_clang[BR];

// ---------------- generic tiled GEMM ----------------
// C[M,N] = A[M,K] @ op(B) (+ epilogue), op(B)=B^T if BT (B is [N,K]) else B [K,N].
// All of M%BM==0, N%BN==0, K%BK==0 guaranteed by construction.
template<int BM,int BN,int BK,int TM,int TN,bool BT>
__global__ void __launch_bounds__(256) gemm_kernel(
    const float* __restrict__ A,int lda,long sA,
    const float* __restrict__ B,int ldb,long sB,
    float* __restrict__ C,int ldc,long sC,
    int K,
    const float* __restrict__ bias,
    const float* __restrict__ addv,int addv_ld,int addv_shift,
    const float* __restrict__ rs,const float* __restrict__ ps,
    int relu,int accum)
{
    __shared__ float As[BK][BM];
    __shared__ float Bs[BK][BN];
    const int tid = threadIdx.x;
    const float* Ab = A + blockIdx.z * sA;
    const float* Bb = B + blockIdx.z * sB;
    float* Cb = C + blockIdx.z * sC;
    const int rowBase = blockIdx.y * BM;
    const int colBase = blockIdx.x * BN;
    const int tx = tid % (BN/TN);
    const int ty = tid / (BN/TN);

    float acc[TM][TN];
#pragma unroll
    for (int i=0;i<TM;i++)
#pragma unroll
        for (int j=0;j<TN;j++) acc[i][j]=0.f;

    for (int k0=0;k0<K;k0+=BK) {
        // A tile -> As[k][m]
#pragma unroll
        for (int i=tid*4;i<BM*BK;i+=256*4) {
            int r=i/BK, kk=i%BK;
            float4 v = *(const float4*)(Ab + (long)(rowBase+r)*lda + k0 + kk);
            As[kk+0][r]=v.x; As[kk+1][r]=v.y; As[kk+2][r]=v.z; As[kk+3][r]=v.w;
        }
        if (BT) {
#pragma unroll
            for (int i=tid*4;i<BN*BK;i+=256*4) {
                int r=i/BK, kk=i%BK;
                float4 v = *(const float4*)(Bb + (long)(colBase+r)*ldb + k0 + kk);
                Bs[kk+0][r]=v.x; Bs[kk+1][r]=v.y; Bs[kk+2][r]=v.z; Bs[kk+3][r]=v.w;
            }
        } else {
#pragma unroll
            for (int i=tid*4;i<BK*BN;i+=256*4) {
                int r=i/BN, cc=i%BN;
                *(float4*)&Bs[r][cc] = *(const float4*)(Bb + (long)(k0+r)*ldb + colBase + cc);
            }
        }
        __syncthreads();
#pragma unroll
        for (int k=0;k<BK;k++) {
            float a[TM], b[TN];
#pragma unroll
            for (int i=0;i<TM;i+=4) *(float4*)&a[i] = *(const float4*)&As[k][ty*TM+i];
#pragma unroll
            for (int j=0;j<TN;j+=4) *(float4*)&b[j] = *(const float4*)&Bs[k][tx*TN+j];
#pragma unroll
            for (int i=0;i<TM;i++)
#pragma unroll
                for (int j=0;j<TN;j++) acc[i][j] = fmaf(a[i], b[j], acc[i][j]);
        }
        __syncthreads();
    }

    const int vb = rowBase >> addv_shift;  // rows of a tile never straddle a batch
#pragma unroll
    for (int i=0;i<TM;i++) {
        int r = rowBase + ty*TM + i;
        float rsv = rs ? rs[r] : 1.f;
        float psv = ps ? ps[r] : 1.f;
#pragma unroll
        for (int j=0;j<TN;j++) {
            int c = colBase + tx*TN + j;
            float v = acc[i][j];
            if (addv)  v += rsv * addv[(long)vb*addv_ld + c];
            if (bias)  v += bias[c];
            if (accum) v += Cb[(long)r*ldc + c];
            if (relu)  v = fmaxf(v, 0.f);
            if (ps)    v *= psv;
            Cb[(long)r*ldc + c] = v;
        }
    }
}

template<int BM,int BN,int BK,int TM,int TN,bool BT>
static void launch_gemm(const float* A,int lda,long sA,const float* B,int ldb,long sB,
                        float* C,int ldc,long sC,int M,int N,int K,int batch,
                        const float* bias=nullptr,const float* addv=nullptr,int addv_ld=1,int addv_shift=0,
                        const float* rs=nullptr,const float* ps=nullptr,int relu=0,int accum=0)
{
    dim3 g(N/BN, M/BM, batch);
    gemm_kernel<BM,BN,BK,TM,TN,BT><<<g,256>>>(A,lda,sA,B,ldb,sB,C,ldc,sC,K,
                                              bias,addv,addv_ld,addv_shift,rs,ps,relu,accum);
}

// ---------------- pointwise / reduction kernels ----------------
__device__ __forceinline__ float sigm(float x){ return 1.f/(1.f+__expf(-x)); }

__global__ void concat3_kernel(const float* a,const float* b,const float* c,float* out){
    int idx = blockIdx.x*blockDim.x+threadIdx.x;
    if (idx >= BB*3072) return;
    int bb = idx/3072, j = idx%3072;
    float v;
    if (j < 1024) v = a[bb*1024 + j];
    else if (j < 2048) v = b[bb*1024 + (j-1024)];
    else v = c[bb*1024 + (j-2048)];
    out[idx] = v;
}

__global__ void concat2_kernel(const float* a,const float* b,float* out){
    int idx = blockIdx.x*blockDim.x+threadIdx.x;
    if (idx >= BB*2048) return;
    int bb = idx/2048, j = idx%2048;
    out[idx] = (j<1024) ? a[bb*1024+j] : b[bb*1024+(j-1024)];
}

__global__ void lstm_kernel(const float* gates,const float* c_prev,
                            float* h_out,float* c_out){
    int idx = blockIdx.x*blockDim.x+threadIdx.x;
    if (idx >= BR) return;
    int bb = idx >> 10, r = idx & 1023;
    const float* g = gates + bb*4096;
    float ig = sigm(g[r]);
    float fg = sigm(g[1024+r]);
    float gg = tanhf(g[2048+r]);
    float og = sigm(g[3072+r]);
    float c = fg * c_prev[idx] + ig * gg;
    h_out[idx] = og * tanhf(c);
    c_out[idx] = c;
}

__global__ void maskmul_kernel(const float* ge,const float* mask,float* gem){
    long i = (long)blockIdx.x*blockDim.x+threadIdx.x;   // float4 index
    long total = (long)BB*NN*RR/4;
    if (i >= total) return;
    int row = (int)(i >> 8);                             // 256 float4 per 1024-row
    float m = mask[row];
    float4 v = ((const float4*)ge)[i];
    v.x*=m; v.y*=m; v.z*=m; v.w*=m;
    ((float4*)gem)[i] = v;
}

__global__ void batchmin_kernel(const float* Adj,float* minv){
    __shared__ float sm[1024];
    const float* a = Adj + (long)blockIdx.x*NN*NN;
    float mn = INFINITY;
    for (int i=threadIdx.x;i<NN*NN;i+=1024) mn = fminf(mn, a[i]);
    sm[threadIdx.x]=mn; __syncthreads();
    for (int s=512;s>0;s>>=1){ if (threadIdx.x<s) sm[threadIdx.x]=fminf(sm[threadIdx.x],sm[threadIdx.x+s]); __syncthreads(); }
    if (threadIdx.x==0) minv[blockIdx.x]=sm[0];
}

// Per row: v=(Adj-min)*m_row (>=0), exact top-256 (lax.top_k tie semantics:
// equal values -> lower index first), write kept back, zero rest, and emit
// d = rowsum^{-1/2} (0 if rowsum==0).
__global__ void __launch_bounds__(512) topk_kernel(float* Adj,const float* minv,
                                                   const float* mask,float* dvec){
    __shared__ unsigned long long keys[NN];
    __shared__ float red[NN];
    int row = blockIdx.x;
    int t = threadIdx.x;
    int bb = row >> 9;
    float mrow = mask[row];
    float* arow = Adj + (long)row*NN;
    float v = (arow[t] - minv[bb]) * mrow;               // >= 0
    keys[t] = ((unsigned long long)__float_as_uint(v) << 32) | (unsigned)(NN-1-t);
    __syncthreads();
    // bitonic sort descending (ties: larger low-bits = smaller index first)
    for (unsigned k2=2;k2<=NN;k2<<=1)
        for (unsigned j=k2>>1;j>0;j>>=1){
            unsigned ixj = t ^ j;
            if (ixj > (unsigned)t){
                unsigned long long x=keys[t], y=keys[ixj];
                bool desc = ((t & k2) == 0);
                if (desc ? (x<y) : (x>y)){ keys[t]=y; keys[ixj]=x; }
            }
            __syncthreads();
        }
    unsigned long long kk = keys[t];
    arow[t] = 0.f;
    __syncthreads();
    float s = 0.f;
    if (t < KTOP){
        int col = (NN-1) - (int)(unsigned)(kk & 0xffffffffu);
        float val = __uint_as_float((unsigned)(kk >> 32));
        arow[col] = val;
        s = val;
    }
    red[t]=s; __syncthreads();
    for (int st=NN/2;st>0;st>>=1){ if (t<st) red[t]+=red[t+st]; __syncthreads(); }
    if (t==0) dvec[row] = (red[0] > 0.f) ? rsqrtf(red[0]) : 0.f;
}

__global__ void dscale_kernel(float* Adj,const float* d){
    long idx = (long)blockIdx.x*blockDim.x+threadIdx.x;
    if (idx >= (long)BB*NN*NN) return;
    int row = (int)(idx >> 9);
    int col = (int)(idx & (NN-1));
    int bb = row >> 9;
    Adj[idx] *= d[row] * d[(bb<<9)+col];
}

__global__ void srow_kernel(const float* Adj,const float* mask,float* srow){
    int warp = (blockIdx.x*blockDim.x+threadIdx.x) >> 5;
    int lane = threadIdx.x & 31;
    if (warp >= BB*NN) return;
    int bb = warp >> 9;
    const float* a = Adj + (long)warp*NN;
    const float* m = mask + bb*NN;
    float s = 0.f;
    for (int k=lane;k<NN;k+=32) s += a[k]*m[k];
    for (int o=16;o;o>>=1) s += __shfl_xor_sync(0xffffffffu, s, o);
    if (lane==0) srow[warp] = s;
}

__global__ void colmax_kernel(const float* X,float* att){
    int idx = blockIdx.x*blockDim.x+threadIdx.x;
    if (idx >= BB*RR) return;
    int bb = idx >> 10, j = idx & 1023;
    const float* x = X + (long)bb*NN*RR + j;
    float mx = -INFINITY;
    for (int n=0;n<NN;n++) mx = fmaxf(mx, x[(long)n*RR]);
    att[idx] = mx;
}

__global__ void pack_kernel(const float* hatt,const float* catt,
                            const float* hlang,const float* clang,
                            float* out,int out_size){
    int i = blockIdx.x*blockDim.x+threadIdx.x;
    if (i >= BR) return;
    out[i] = hlang[i];
    if (out_size >= 5*BR){
        out[1*BR+i] = hatt[i];
        out[2*BR+i] = hlang[i];
        out[3*BR+i] = catt[i];
        out[4*BR+i] = clang[i];
    }
}

// ---------------- host driver ----------------
extern "C" void kernel_launch(void* const* d_in, const int* in_sizes, int n_in,
                              void* d_out, int out_size)
{
    const float* xt      = (const float*)d_in[0];
    const float* fc      = (const float*)d_in[1];
    const float* ge      = (const float*)d_in[2];
    const float* sh      = (const float*)d_in[4];   // (2,B,R)
    const float* sc      = (const float*)d_in[5];
    const float* mask    = (const float*)d_in[6];   // (B,N)
    const float* aWih    = (const float*)d_in[7];   // (4096,3072)
    const float* aWhh    = (const float*)d_in[8];   // (4096,1024)
    const float* abih    = (const float*)d_in[9];
    const float* abhh    = (const float*)d_in[10];
    const float* lWih    = (const float*)d_in[11];  // (4096,2048)
    const float* lWhh    = (const float*)d_in[12];
    const float* lbih    = (const float*)d_in[13];
    const float* lbhh    = (const float*)d_in[14];
    const float* e1W     = (const float*)d_in[15];  // (1024,2048)
    const float* e1b     = (const float*)d_in[16];
    const float* e2W     = (const float*)d_in[17];
    const float* e2b     = (const float*)d_in[18];
    const float* gW0     = (const float*)d_in[19];  // (2048,1024)
    const float* gb0     = (const float*)d_in[20];
    const float* gW1     = (const float*)d_in[21];  // (1024,1024)
    const float* gb1     = (const float*)d_in[22];
    const float* gW2     = (const float*)d_in[23];
    const float* gb2     = (const float*)d_in[24];
    (void)in_sizes; (void)n_in;
    float* out = (float*)d_out;

    static float *bufA=nullptr,*bufB=nullptr,*bufC=nullptr,*adj=nullptr,*xcat=nullptr,
                 *gates=nullptr,*gates2=nullptr,*ht1=nullptr,*ht2=nullptr,*pvec=nullptr,
                 *srow=nullptr,*dvec=nullptr,*minv=nullptr,*attv=nullptr,*xl=nullptr,
                 *hatt=nullptr,*catt=nullptr,*hlang=nullptr,*clang=nullptr;
    if (!bufA){
        cudaGetSymbolAddress((void**)&bufA,  g_bufA);
        cudaGetSymbolAddress((void**)&bufB,  g_bufB);
        cudaGetSymbolAddress((void**)&bufC,  g_bufC);
        cudaGetSymbolAddress((void**)&adj,   g_adj);
        cudaGetSymbolAddress((void**)&xcat,  g_xcat);
        cudaGetSymbolAddress((void**)&gates, g_gates);
        cudaGetSymbolAddress((void**)&gates2,g_gates2);
        cudaGetSymbolAddress((void**)&ht1,   g_hterm1);
        cudaGetSymbolAddress((void**)&ht2,   g_hterm2);
        cudaGetSymbolAddress((void**)&pvec,  g_pvec);
        cudaGetSymbolAddress((void**)&srow,  g_srow);
        cudaGetSymbolAddress((void**)&dvec,  g_dvec);
        cudaGetSymbolAddress((void**)&minv,  g_minv);
        cudaGetSymbolAddress((void**)&attv,  g_attv);
        cudaGetSymbolAddress((void**)&xl,    g_xl);
        cudaGetSymbolAddress((void**)&hatt,  g_hatt);
        cudaGetSymbolAddress((void**)&catt,  g_catt);
        cudaGetSymbolAddress((void**)&hlang, g_hlang);
        cudaGetSymbolAddress((void**)&clang, g_clang);
    }

    const float* prev_h = sh + BR;   // state_h[1]
    const float* h0     = sh;        // state_h[0]
    const float* c0     = sc;
    const float* c1     = sc + BR;

    // ---- attention LSTM ----
    concat3_kernel<<<(BB*3072+255)/256,256>>>(prev_h, fc, xt, xcat);
    launch_gemm<64,64,16,4,4,true >(xcat,3072,0, aWih,3072,0, gates,4096,0, BB,4096,3072,1, abih);
    launch_gemm<64,64,16,4,4,true >(h0,1024,0,   aWhh,1024,0, gates,4096,0, BB,4096,1024,1, abhh,
                                    nullptr,1,0,nullptr,nullptr,0,/*accum=*/1);
    lstm_kernel<<<(BR+255)/256,256>>>(gates, c0, hatt, catt);

    // ---- masked graph embedding ----
    maskmul_kernel<<<(int)(((long)BB*NN*RR/4+255)/256),256>>>(ge, mask, bufA);

    // ---- e1 / e2 (split concat: (m*GE)@Wa^T + m*(h_att@Wb^T) + b) ----
    launch_gemm<64,64,16,4,4,true >(hatt,1024,0, e1W+1024,2048,0, ht1,1024,0, BB,1024,1024,1);
    launch_gemm<64,64,16,4,4,true >(hatt,1024,0, e2W+1024,2048,0, ht2,1024,0, BB,1024,1024,1);
    launch_gemm<128,128,16,8,8,true>(bufA,1024,0, e1W,2048,0, bufB,1024,0, BB*NN,1024,1024,1,
                                     e1b, ht1,1024,9, mask);
    launch_gemm<128,128,16,8,8,true>(bufA,1024,0, e2W,2048,0, bufC,1024,0, BB*NN,1024,1024,1,
                                     e2b, ht2,1024,9, mask);

    // ---- Adj = e1 @ e2^T (batched) ----
    launch_gemm<128,128,16,8,8,true>(bufB,1024,(long)NN*RR, bufC,1024,(long)NN*RR,
                                     adj,NN,(long)NN*NN, NN,NN,1024,BB);

    // ---- min-shift, mask, exact top-K, d = rowsum^-1/2 ----
    batchmin_kernel<<<BB,1024>>>(adj, minv);
    topk_kernel<<<BB*NN,512>>>(adj, minv, mask, dvec);
    dscale_kernel<<<(int)(((long)BB*NN*NN+255)/256),256>>>(adj, dvec);

    // ---- GCN layer 0 (split concat trick) ----
    srow_kernel<<<(BB*NN*32+255)/256,256>>>(adj, mask, srow);
    launch_gemm<64,64,16,4,4,false>(prev_h,1024,0, gW0+1024*1024,1024,0, pvec,1024,0, BB,1024,1024,1);
    // Y0 = Adj @ GEM  (batched)
    launch_gemm<128,128,16,8,8,false>(adj,NN,(long)NN*NN, bufA,1024,(long)NN*RR,
                                      bufB,1024,(long)NN*RR, NN,1024,NN,BB);
    // X1 = relu(Y0@W0a + srow*pvec + b0) * m
    launch_gemm<128,128,16,8,8,false>(bufB,1024,0, gW0,1024,0, bufC,1024,0, BB*NN,1024,1024,1,
                                      gb0, pvec,1024,9, srow, mask, /*relu=*/1);

    // ---- GCN layer 1 ----
    launch_gemm<128,128,16,8,8,false>(adj,NN,(long)NN*NN, bufC,1024,(long)NN*RR,
                                      bufA,1024,(long)NN*RR, NN,1024,NN,BB);
    launch_gemm<128,128,16,8,8,false>(bufA,1024,0, gW1,1024,0, bufB,1024,0, BB*NN,1024,1024,1,
                                      gb1, nullptr,1,0, nullptr, mask, /*relu=*/1);

    // ---- GCN layer 2 ----
    launch_gemm<128,128,16,8,8,false>(adj,NN,(long)NN*NN, bufB,1024,(long)NN*RR,
                                      bufC,1024,(long)NN*RR, NN,1024,NN,BB);
    launch_gemm<128,128,16,8,8,false>(bufC,1024,0, gW2,1024,0, bufA,1024,0, BB*NN,1024,1024,1,
                                      gb2, nullptr,1,0, nullptr, mask, /*relu=*/1);

    // ---- att = max over N ----
    colmax_kernel<<<(BB*RR+255)/256,256>>>(bufA, attv);

    // ---- language LSTM ----
    concat2_kernel<<<(BB*2048+255)/256,256>>>(attv, hatt, xl);
    launch_gemm<64,64,16,4,4,true >(xl,2048,0, lWih,2048,0, gates2,4096,0, BB,4096,2048,1, lbih);
    launch_gemm<64,64,16,4,4,true >(prev_h,1024,0, lWhh,1024,0, gates2,4096,0, BB,4096,1024,1, lbhh,
                                    nullptr,1,0,nullptr,nullptr,0,/*accum=*/1);
    lstm_kernel<<<(BR+255)/256,256>>>(gates2, c1, hlang, clang);

    // ---- pack outputs: (output, stack[h_att,h_lang], stack[c_att,c_lang]) ----
    pack_kernel<<<(BR+255)/256,256>>>(hatt, catt, hlang, clang, out, out_size);
}

// round 5
// speedup vs baseline: 2.2802x; 2.2802x over previous
#include <cuda_runtime.h>
#include <cuda_bf16.h>
#include <math.h>
#include <stdint.h>

#define BB 64
#define NN 512
#define RR 1024
#define KTOP 256
#define BR (BB*RR)
#define NGE ((long)BB*NN*RR)

// ---------------- device scratch ----------------
__device__ float g_adj[(long)BB*NN*NN];
__device__ float g_xcat[BB*3072];
__device__ float g_gates[BB*4096];
__device__ float g_gates2[BB*4096];
__device__ float g_ht1[BB*RR];
__device__ float g_ht2[BB*RR];
__device__ float g_pvec[BB*RR];
__device__ float g_srow[BB*NN];
__device__ float g_dvec[BB*NN];
__device__ float g_minv[BB];
__device__ float g_attv[BB*RR];
__device__ float g_xl[BB*2048];
__device__ float g_hatt[BR];
__device__ float g_catt[BR];
__device__ float g_hlang[BR];
__device__ float g_clang[BR];

__device__ __nv_bfloat16 g_Ph[NGE], g_Pl[NGE];   // masked GE, later X2^T
__device__ __nv_bfloat16 g_Qh[NGE], g_Ql[NGE];   // E1, later Y
__device__ __nv_bfloat16 g_Sh[NGE], g_Sl[NGE];   // E2, later X1^T / X3^T
__device__ __nv_bfloat16 g_Th[NGE], g_Tl[NGE];   // GE^T (masked)
__device__ __nv_bfloat16 g_ADJh[(long)BB*NN*NN], g_ADJl[(long)BB*NN*NN];
__device__ __nv_bfloat16 g_W1h[1048576], g_W1l[1048576];
__device__ __nv_bfloat16 g_W2h[1048576], g_W2l[1048576];
__device__ __nv_bfloat16 g_G0h[1048576], g_G0l[1048576];
__device__ __nv_bfloat16 g_G1h[1048576], g_G1l[1048576];
__device__ __nv_bfloat16 g_G2h[1048576], g_G2l[1048576];

// ---------------- warp MMA helpers (sm_80-compatible) ----------------
__device__ __forceinline__ uint32_t smem_u32(const void* p){
    uint32_t a;
    asm("{ .reg .u64 t; cvta.to.shared.u64 t, %1; cvt.u32.u64 %0, t; }" : "=r"(a) : "l"(p));
    return a;
}
__device__ __forceinline__ uint32_t swz(uint32_t x){ return x ^ ((x>>3)&0x70u); }
__device__ __forceinline__ void ldm4(uint32_t* r, uint32_t addr){
    asm volatile("ldmatrix.sync.aligned.m8n8.x4.shared.b16 {%0,%1,%2,%3}, [%4];"
        : "=r"(r[0]),"=r"(r[1]),"=r"(r[2]),"=r"(r[3]) : "r"(addr));
}
__device__ __forceinline__ void mma16816(float* d, const uint32_t* a, const uint32_t* b){
    asm volatile("mma.sync.aligned.m16n8k16.row.col.f32.bf16.bf16.f32 "
        "{%0,%1,%2,%3}, {%4,%5,%6,%7}, {%8,%9}, {%0,%1,%2,%3};"
        : "+f"(d[0]),"+f"(d[1]),"+f"(d[2]),"+f"(d[3])
        : "r"(a[0]),"r"(a[1]),"r"(a[2]),"r"(a[3]), "r"(b[0]),"r"(b[1]));
}

// ---------------- bf16 hi/lo tensor-core GEMM ----------------
// C[128x128 tile] = (Ah+Al)[M,K] @ (Bh+Bl)[N,K]^T, K-major, fp32 accum.
// 8 warps: warp tile 32x64. 64-wide K chunks in smem (single buffer, 2 CTA/SM).
#define MMA_SMEM (65536+1024)

__global__ void __launch_bounds__(256,2) hmma_gemm(
    const __nv_bfloat16* __restrict__ Ah, const __nv_bfloat16* __restrict__ Al, int lda, long sA,
    const __nv_bfloat16* __restrict__ Bh, const __nv_bfloat16* __restrict__ Bl, int ldb, long sB,
    int K, int rowsPerZ, int outMode, int relu,
    float* Cf, int ldc,
    __nv_bfloat16* Ch, __nv_bfloat16* Cl, int ldch,
    const float* __restrict__ bias, const float* __restrict__ addv,
    const float* __restrict__ rs, const float* __restrict__ ps)
{
    extern __shared__ char smraw[];
    uint32_t sb0 = smem_u32(smraw);
    uint32_t sb  = (sb0 + 1023u) & ~1023u;
    char* smem = smraw + (sb - sb0);
    const int tid = threadIdx.x, wid = tid>>5, lane = tid&31;

    const __nv_bfloat16* A0 = Ah + blockIdx.z*sA;
    const __nv_bfloat16* A1 = Al + blockIdx.z*sA;
    const __nv_bfloat16* B0 = Bh + blockIdx.z*sB;
    const __nv_bfloat16* B1 = Bl + blockIdx.z*sB;
    const int rowBase = blockIdx.y*128, colBase = blockIdx.x*128;
    const int NC = K >> 6;

    const int wr = wid>>1, wc = wid&1;
    const int lr = lane&7, q = lane>>3;
    const int aRowOff = ((q&1)<<3) + lr;   // within m16 block
    const int aKbOff  = (q>>1)<<4;         // 0 or 16 bytes
    const int bRowOff = ((q>>1)<<3) + lr;  // within n16 block
    const int bKbOff  = (q&1)<<4;

    float acc[2][8][4];
    #pragma unroll
    for (int a=0;a<2;a++)
        #pragma unroll
        for (int b=0;b<8;b++)
            #pragma unroll
            for (int c=0;c<4;c++) acc[a][b][c]=0.f;

    auto load_chunk = [&](int ci){
        const int k0 = ci<<6;
        #pragma unroll
        for (int u=tid; u<1024; u+=256){
            int r = u>>3, kq = u&7;
            uint32_t off = swz((uint32_t)(r*128 + kq*16));
            *(uint4*)(smem + off)         = *(const uint4*)(A0 + (long)(rowBase+r)*lda + k0 + kq*8);
            *(uint4*)(smem + 16384 + off) = *(const uint4*)(A1 + (long)(rowBase+r)*lda + k0 + kq*8);
            *(uint4*)(smem + 32768 + off) = *(const uint4*)(B0 + (long)(colBase+r)*ldb + k0 + kq*8);
            *(uint4*)(smem + 49152 + off) = *(const uint4*)(B1 + (long)(colBase+r)*ldb + k0 + kq*8);
        }
    };

    for (int i=0;i<NC;i++){
        load_chunk(i);
        __syncthreads();
        #pragma unroll
        for (int ks=0;ks<4;ks++){
            const uint32_t kbyte = ks<<5;
            uint32_t ah[2][4], al[2][4], bb[4][4];
            #pragma unroll
            for (int mi=0;mi<2;mi++){
                uint32_t ro = (uint32_t)((wr*32 + mi*16 + aRowOff)*128) + kbyte + aKbOff;
                ldm4(ah[mi], sb + swz(ro));
                ldm4(al[mi], sb + 16384 + swz(ro));
            }
            // B hi
            #pragma unroll
            for (int t=0;t<4;t++){
                uint32_t ro = (uint32_t)((wc*64 + t*16 + bRowOff)*128) + kbyte + bKbOff;
                ldm4(bb[t], sb + 32768 + swz(ro));
            }
            #pragma unroll
            for (int mi=0;mi<2;mi++)
                #pragma unroll
                for (int t=0;t<4;t++){
                    mma16816(acc[mi][2*t],   ah[mi], &bb[t][0]);
                    mma16816(acc[mi][2*t+1], ah[mi], &bb[t][2]);
                }
            #pragma unroll
            for (int mi=0;mi<2;mi++)
                #pragma unroll
                for (int t=0;t<4;t++){
                    mma16816(acc[mi][2*t],   al[mi], &bb[t][0]);
                    mma16816(acc[mi][2*t+1], al[mi], &bb[t][2]);
                }
            // B lo (reuse regs)
            #pragma unroll
            for (int t=0;t<4;t++){
                uint32_t ro = (uint32_t)((wc*64 + t*16 + bRowOff)*128) + kbyte + bKbOff;
                ldm4(bb[t], sb + 49152 + swz(ro));
            }
            #pragma unroll
            for (int mi=0;mi<2;mi++)
                #pragma unroll
                for (int t=0;t<4;t++){
                    mma16816(acc[mi][2*t],   ah[mi], &bb[t][0]);
                    mma16816(acc[mi][2*t+1], ah[mi], &bb[t][2]);
                }
        }
        __syncthreads();
    }

    // ---- epilogue ----
    const int cpair = (lane&3)*2;
    #pragma unroll
    for (int mi=0;mi<2;mi++){
        #pragma unroll
        for (int rr=0;rr<2;rr++){
            const int r  = rowBase + wr*32 + mi*16 + (lane>>2) + rr*8;
            const int gr = blockIdx.z*rowsPerZ + r;
            const float rsv = rs ? rs[gr] : 1.f;
            const float psv = ps ? ps[gr] : 1.f;
            const float* avp = addv ? addv + (long)(gr>>9)*RR : nullptr;
            #pragma unroll
            for (int ni=0;ni<8;ni++){
                const int c = colBase + wc*64 + ni*8 + cpair;
                float x0 = acc[mi][ni][rr*2+0];
                float x1 = acc[mi][ni][rr*2+1];
                if (avp){ x0 += rsv*avp[c]; x1 += rsv*avp[c+1]; }
                if (bias){ x0 += bias[c]; x1 += bias[c+1]; }
                if (relu){ x0 = fmaxf(x0,0.f); x1 = fmaxf(x1,0.f); }
                x0 *= psv; x1 *= psv;
                if (outMode==0){
                    *(float2*)(Cf + (long)gr*ldc + c) = make_float2(x0,x1);
                } else {
                    __nv_bfloat16 h0 = __float2bfloat16(x0);
                    __nv_bfloat16 l0 = __float2bfloat16(x0-__bfloat162float(h0));
                    __nv_bfloat16 h1 = __float2bfloat16(x1);
                    __nv_bfloat16 l1 = __float2bfloat16(x1-__bfloat162float(h1));
                    if (outMode==1){
                        long o = (long)gr*ldch + c;
                        __nv_bfloat162 hp; hp.x=h0; hp.y=h1;
                        __nv_bfloat162 lp; lp.x=l0; lp.y=l1;
                        *(__nv_bfloat162*)(Ch+o) = hp;
                        *(__nv_bfloat162*)(Cl+o) = lp;
                    } else { // transposed: XT[b][feat][node]
                        long base = (long)(gr>>9)*((long)RR*NN) + (gr&511);
                        long o0 = base + (long)c*NN;
                        Ch[o0]=h0; Cl[o0]=l0;
                        Ch[o0+NN]=h1; Cl[o0+NN]=l1;
                    }
                }
            }
        }
    }
}

// ---------------- FFMA GEMM for small (B=64) matmuls ----------------
template<int BM,int BN,int BK,int TM,int TN,bool BT>
__global__ void __launch_bounds__(256) gemm_kernel(
    const float* __restrict__ A,int lda,
    const float* __restrict__ B,int ldb,
    float* __restrict__ C,int ldc,
    int K, const float* __restrict__ bias, int accum)
{
    __shared__ float As[BK][BM];
    __shared__ float Bs[BK][BN];
    const int tid = threadIdx.x;
    const int rowBase = blockIdx.y*BM, colBase = blockIdx.x*BN;
    const int tx = tid % (BN/TN), ty = tid / (BN/TN);
    float acc[TM][TN];
#pragma unroll
    for (int i=0;i<TM;i++)
#pragma unroll
        for (int j=0;j<TN;j++) acc[i][j]=0.f;

    for (int k0=0;k0<K;k0+=BK){
#pragma unroll
        for (int i=tid*4;i<BM*BK;i+=256*4){
            int r=i/BK, kk=i%BK;
            float4 v = *(const float4*)(A + (long)(rowBase+r)*lda + k0 + kk);
            As[kk+0][r]=v.x; As[kk+1][r]=v.y; As[kk+2][r]=v.z; As[kk+3][r]=v.w;
        }
        if (BT){
#pragma unroll
            for (int i=tid*4;i<BN*BK;i+=256*4){
                int r=i/BK, kk=i%BK;
                float4 v = *(const float4*)(B + (long)(colBase+r)*ldb + k0 + kk);
                Bs[kk+0][r]=v.x; Bs[kk+1][r]=v.y; Bs[kk+2][r]=v.z; Bs[kk+3][r]=v.w;
            }
        } else {
#pragma unroll
            for (int i=tid*4;i<BK*BN;i+=256*4){
                int r=i/BN, cc=i%BN;
                *(float4*)&Bs[r][cc] = *(const float4*)(B + (long)(k0+r)*ldb + colBase + cc);
            }
        }
        __syncthreads();
#pragma unroll
        for (int k=0;k<BK;k++){
            float a[TM], b[TN];
#pragma unroll
            for (int i=0;i<TM;i+=4) *(float4*)&a[i] = *(const float4*)&As[k][ty*TM+i];
#pragma unroll
            for (int j=0;j<TN;j+=4) *(float4*)&b[j] = *(const float4*)&Bs[k][tx*TN+j];
#pragma unroll
            for (int i=0;i<TM;i++)
#pragma unroll
                for (int j=0;j<TN;j++) acc[i][j] = fmaf(a[i], b[j], acc[i][j]);
        }
        __syncthreads();
    }
#pragma unroll
    for (int i=0;i<TM;i++){
        int r = rowBase + ty*TM + i;
#pragma unroll
        for (int j=0;j<TN;j++){
            int c = colBase + tx*TN + j;
            float v = acc[i][j];
            if (bias)  v += bias[c];
            if (accum) v += C[(long)r*ldc + c];
            C[(long)r*ldc + c] = v;
        }
    }
}
template<bool BT>
static void small_gemm(const float* A,int lda,const float* B,int ldb,float* C,int ldc,
                       int M,int N,int K,const float* bias=nullptr,int accum=0){
    dim3 g(N/64, M/64, 1);
    gemm_kernel<64,64,16,4,4,BT><<<g,256>>>(A,lda,B,ldb,C,ldc,K,bias,accum);
}

// ---------------- conversions ----------------
__device__ __forceinline__ void split1(float v, __nv_bfloat16& h, __nv_bfloat16& l){
    h = __float2bfloat16(v);
    l = __float2bfloat16(v - __bfloat162float(h));
}

__global__ void conv_mask_kernel(const float* __restrict__ src, const float* __restrict__ mask,
                                 __nv_bfloat16* __restrict__ dh, __nv_bfloat16* __restrict__ dl, long n4){
    long i = (long)blockIdx.x*blockDim.x + threadIdx.x;
    if (i >= n4) return;
    float4 v = ((const float4*)src)[i];
    float m = mask[i >> 8];
    v.x*=m; v.y*=m; v.z*=m; v.w*=m;
    __align__(8) __nv_bfloat16 h[4], l[4];
    split1(v.x,h[0],l[0]); split1(v.y,h[1],l[1]); split1(v.z,h[2],l[2]); split1(v.w,h[3],l[3]);
    ((uint2*)dh)[i] = *(uint2*)h;
    ((uint2*)dl)[i] = *(uint2*)l;
}

__global__ void conv_slice_kernel(const float* __restrict__ src, int ldsrc,
                                  __nv_bfloat16* __restrict__ dh, __nv_bfloat16* __restrict__ dl,
                                  int cols, int n4){
    int i = blockIdx.x*blockDim.x + threadIdx.x;
    if (i >= n4) return;
    int c4pr = cols/4;
    int r = i / c4pr, c4 = i % c4pr;
    float4 v = *(const float4*)(src + (long)r*ldsrc + c4*4);
    __align__(8) __nv_bfloat16 h[4], l[4];
    split1(v.x,h[0],l[0]); split1(v.y,h[1],l[1]); split1(v.z,h[2],l[2]); split1(v.w,h[3],l[3]);
    long o = (long)r*c4pr + c4;
    ((uint2*)dh)[o] = *(uint2*)h;
    ((uint2*)dl)[o] = *(uint2*)l;
}

// per-batch transpose+convert: src [rows,cols] fp32 -> dst [cols,rows] bf16 hi/lo
__global__ void tconv_kernel(const float* __restrict__ src, long sS, int rows, int cols,
                             __nv_bfloat16* __restrict__ dh, __nv_bfloat16* __restrict__ dl, long sD,
                             const float* __restrict__ mask){
    __shared__ float t[32][33];
    int b = blockIdx.z;
    const float* S = src + (long)b*sS;
    int r0 = blockIdx.y*32, c0 = blockIdx.x*32;
    int tx = threadIdx.x, ty = threadIdx.y;
    for (int i=ty;i<32;i+=8){
        float v = S[(long)(r0+i)*cols + c0+tx];
        if (mask) v *= mask[(long)b*rows + r0+i];
        t[i][tx] = v;
    }
    __syncthreads();
    __nv_bfloat16* DH = dh + (long)b*sD;
    __nv_bfloat16* DL = dl + (long)b*sD;
    for (int i=ty;i<32;i+=8){
        float v = t[tx][i];
        __nv_bfloat16 h, l; split1(v, h, l);
        long o = (long)(c0+i)*rows + r0+tx;
        DH[o] = h; DL[o] = l;
    }
}

// ---------------- pointwise / reductions ----------------
__device__ __forceinline__ float sigm(float x){ return 1.f/(1.f+__expf(-x)); }

__global__ void concat3_kernel(const float* a,const float* b,const float* c,float* out){
    int idx = blockIdx.x*blockDim.x+threadIdx.x;
    if (idx >= BB*3072) return;
    int bb = idx/3072, j = idx%3072;
    out[idx] = (j<1024) ? a[bb*1024+j] : (j<2048 ? b[bb*1024+j-1024] : c[bb*1024+j-2048]);
}
__global__ void concat2_kernel(const float* a,const float* b,float* out){
    int idx = blockIdx.x*blockDim.x+threadIdx.x;
    if (idx >= BB*2048) return;
    int bb = idx/2048, j = idx%2048;
    out[idx] = (j<1024) ? a[bb*1024+j] : b[bb*1024+j-1024];
}
__global__ void lstm_kernel(const float* gates,const float* c_prev,float* h_out,float* c_out){
    int idx = blockIdx.x*blockDim.x+threadIdx.x;
    if (idx >= BR) return;
    int bb = idx >> 10, r = idx & 1023;
    const float* g = gates + bb*4096;
    float c = sigm(g[1024+r])*c_prev[idx] + sigm(g[r])*tanhf(g[2048+r]);
    h_out[idx] = sigm(g[3072+r])*tanhf(c);
    c_out[idx] = c;
}
__global__ void batchmin_kernel(const float* Adj,float* minv){
    __shared__ float sm[1024];
    const float* a = Adj + (long)blockIdx.x*NN*NN;
    float mn = INFINITY;
    for (int i=threadIdx.x;i<NN*NN;i+=1024) mn = fminf(mn, a[i]);
    sm[threadIdx.x]=mn; __syncthreads();
    for (int s=512;s>0;s>>=1){ if (threadIdx.x<s) sm[threadIdx.x]=fminf(sm[threadIdx.x],sm[threadIdx.x+s]); __syncthreads(); }
    if (threadIdx.x==0) minv[blockIdx.x]=sm[0];
}
__global__ void __launch_bounds__(512) topk_kernel(float* Adj,const float* minv,
                                                   const float* mask,float* dvec){
    __shared__ unsigned long long keys[NN];
    __shared__ float red[NN];
    int row = blockIdx.x, t = threadIdx.x, bb = row >> 9;
    float mrow = mask[row];
    float* arow = Adj + (long)row*NN;
    float v = (arow[t] - minv[bb]) * mrow;
    keys[t] = ((unsigned long long)__float_as_uint(v) << 32) | (unsigned)(NN-1-t);
    __syncthreads();
    for (unsigned k2=2;k2<=NN;k2<<=1)
        for (unsigned j=k2>>1;j>0;j>>=1){
            unsigned ixj = t ^ j;
            if (ixj > (unsigned)t){
                unsigned long long x=keys[t], y=keys[ixj];
                bool desc = ((t & k2) == 0);
                if (desc ? (x<y) : (x>y)){ keys[t]=y; keys[ixj]=x; }
            }
            __syncthreads();
        }
    unsigned long long kk = keys[t];
    arow[t] = 0.f;
    __syncthreads();
    float s = 0.f;
    if (t < KTOP){
        int col = (NN-1) - (int)(unsigned)(kk & 0xffffffffu);
        float val = __uint_as_float((unsigned)(kk >> 32));
        arow[col] = val;
        s = val;
    }
    red[t]=s; __syncthreads();
    for (int st=NN/2;st>0;st>>=1){ if (t<st) red[t]+=red[t+st]; __syncthreads(); }
    if (t==0) dvec[row] = (red[0] > 0.f) ? rsqrtf(red[0]) : 0.f;
}
__global__ void dscale_conv_kernel(float* Adj,const float* d,
                                   __nv_bfloat16* Ah,__nv_bfloat16* Al){
    long idx = (long)blockIdx.x*blockDim.x+threadIdx.x;
    if (idx >= (long)BB*NN*NN) return;
    int row = (int)(idx >> 9), col = (int)(idx & (NN-1)), bb = row >> 9;
    float v = Adj[idx] * d[row] * d[(bb<<9)+col];
    Adj[idx] = v;
    __nv_bfloat16 h,l; split1(v,h,l);
    Ah[idx]=h; Al[idx]=l;
}
__global__ void srow_kernel(const float* Adj,const float* mask,float* srow){
    int warp = (blockIdx.x*blockDim.x+threadIdx.x) >> 5;
    int lane = threadIdx.x & 31;
    if (warp >= BB*NN) return;
    int bb = warp >> 9;
    const float* a = Adj + (long)warp*NN;
    const float* m = mask + bb*NN;
    float s = 0.f;
    for (int k=lane;k<NN;k+=32) s += a[k]*m[k];
    for (int o=16;o;o>>=1) s += __shfl_xor_sync(0xffffffffu, s, o);
    if (lane==0) srow[warp] = s;
}
// XT layout [b][feat][node] -> att[b][feat] = max over node
__global__ void colmaxT_kernel(const __nv_bfloat16* Xh,const __nv_bfloat16* Xl,float* att){
    int warp = (blockIdx.x*blockDim.x+threadIdx.x) >> 5;
    int lane = threadIdx.x & 31;
    if (warp >= BB*RR) return;
    long base = (long)warp*NN;
    float mx = -INFINITY;
    for (int k=lane;k<NN;k+=32)
        mx = fmaxf(mx, __bfloat162float(Xh[base+k]) + __bfloat162float(Xl[base+k]));
    for (int o=16;o;o>>=1) mx = fmaxf(mx, __shfl_xor_sync(0xffffffffu, mx, o));
    if (lane==0) att[warp] = mx;
}
__global__ void pack_kernel(const float* hatt,const float* catt,
                            const float* hlang,const float* clang,float* out,int out_size){
    int i = blockIdx.x*blockDim.x+threadIdx.x;
    if (i >= BR) return;
    out[i] = hlang[i];
    if (out_size >= 5*BR){
        out[1*BR+i] = hatt[i];
        out[2*BR+i] = hlang[i];
        out[3*BR+i] = catt[i];
        out[4*BR+i] = clang[i];
    }
}

// ---------------- host driver ----------------
struct Ptrs {
    float *adj,*xcat,*gates,*gates2,*ht1,*ht2,*pvec,*srow,*dvec,*minv,*attv,*xl,*hatt,*catt,*hlang,*clang;
    __nv_bfloat16 *Ph,*Pl,*Qh,*Ql,*Sh,*Sl,*Th,*Tl,*ADJh,*ADJl;
    __nv_bfloat16 *W1h,*W1l,*W2h,*W2l,*G0h,*G0l,*G1h,*G1l,*G2h,*G2l;
};
static Ptrs P;
static bool g_init = false;

extern "C" void kernel_launch(void* const* d_in, const int* in_sizes, int n_in,
                              void* d_out, int out_size)
{
    const float* xt   = (const float*)d_in[0];
    const float* fc   = (const float*)d_in[1];
    const float* ge   = (const float*)d_in[2];
    const float* sh   = (const float*)d_in[4];
    const float* sc   = (const float*)d_in[5];
    const float* mask = (const float*)d_in[6];
    const float* aWih = (const float*)d_in[7];
    const float* aWhh = (const float*)d_in[8];
    const float* abih = (const float*)d_in[9];
    const float* abhh = (const float*)d_in[10];
    const float* lWih = (const float*)d_in[11];
    const float* lWhh = (const float*)d_in[12];
    const float* lbih = (const float*)d_in[13];
    const float* lbhh = (const float*)d_in[14];
    const float* e1W  = (const float*)d_in[15];
    const float* e1b  = (const float*)d_in[16];
    const float* e2W  = (const float*)d_in[17];
    const float* e2b  = (const float*)d_in[18];
    const float* gW0  = (const float*)d_in[19];
    const float* gb0  = (const float*)d_in[20];
    const float* gW1  = (const float*)d_in[21];
    const float* gb1  = (const float*)d_in[22];
    const float* gW2  = (const float*)d_in[23];
    const float* gb2  = (const float*)d_in[24];
    (void)in_sizes; (void)n_in;
    float* out = (float*)d_out;

    if (!g_init){
        cudaGetSymbolAddress((void**)&P.adj,  g_adj);
        cudaGetSymbolAddress((void**)&P.xcat, g_xcat);
        cudaGetSymbolAddress((void**)&P.gates,g_gates);
        cudaGetSymbolAddress((void**)&P.gates2,g_gates2);
        cudaGetSymbolAddress((void**)&P.ht1,  g_ht1);
        cudaGetSymbolAddress((void**)&P.ht2,  g_ht2);
        cudaGetSymbolAddress((void**)&P.pvec, g_pvec);
        cudaGetSymbolAddress((void**)&P.srow, g_srow);
        cudaGetSymbolAddress((void**)&P.dvec, g_dvec);
        cudaGetSymbolAddress((void**)&P.minv, g_minv);
        cudaGetSymbolAddress((void**)&P.attv, g_attv);
        cudaGetSymbolAddress((void**)&P.xl,   g_xl);
        cudaGetSymbolAddress((void**)&P.hatt, g_hatt);
        cudaGetSymbolAddress((void**)&P.catt, g_catt);
        cudaGetSymbolAddress((void**)&P.hlang,g_hlang);
        cudaGetSymbolAddress((void**)&P.clang,g_clang);
        cudaGetSymbolAddress((void**)&P.Ph, g_Ph); cudaGetSymbolAddress((void**)&P.Pl, g_Pl);
        cudaGetSymbolAddress((void**)&P.Qh, g_Qh); cudaGetSymbolAddress((void**)&P.Ql, g_Ql);
        cudaGetSymbolAddress((void**)&P.Sh, g_Sh); cudaGetSymbolAddress((void**)&P.Sl, g_Sl);
        cudaGetSymbolAddress((void**)&P.Th, g_Th); cudaGetSymbolAddress((void**)&P.Tl, g_Tl);
        cudaGetSymbolAddress((void**)&P.ADJh, g_ADJh); cudaGetSymbolAddress((void**)&P.ADJl, g_ADJl);
        cudaGetSymbolAddress((void**)&P.W1h, g_W1h); cudaGetSymbolAddress((void**)&P.W1l, g_W1l);
        cudaGetSymbolAddress((void**)&P.W2h, g_W2h); cudaGetSymbolAddress((void**)&P.W2l, g_W2l);
        cudaGetSymbolAddress((void**)&P.G0h, g_G0h); cudaGetSymbolAddress((void**)&P.G0l, g_G0l);
        cudaGetSymbolAddress((void**)&P.G1h, g_G1h); cudaGetSymbolAddress((void**)&P.G1l, g_G1l);
        cudaGetSymbolAddress((void**)&P.G2h, g_G2h); cudaGetSymbolAddress((void**)&P.G2l, g_G2l);
        cudaFuncSetAttribute(hmma_gemm, cudaFuncAttributeMaxDynamicSharedMemorySize, MMA_SMEM);
        g_init = true;
    }

    const float* prev_h = sh + BR;
    const float* h0 = sh;
    const float* c0 = sc;
    const float* c1 = sc + BR;

    // ---- conversions (weights + GE) ----
    conv_mask_kernel<<<(int)((NGE/4+255)/256),256>>>(ge, mask, P.Ph, P.Pl, NGE/4);
    tconv_kernel<<<dim3(32,16,64),dim3(32,8)>>>(ge,(long)NN*RR, NN, RR, P.Th, P.Tl,(long)RR*NN, mask);
    conv_slice_kernel<<<(1048576/4+255)/256,256>>>(e1W, 2048, P.W1h, P.W1l, 1024, 1048576/4);
    conv_slice_kernel<<<(1048576/4+255)/256,256>>>(e2W, 2048, P.W2h, P.W2l, 1024, 1048576/4);
    tconv_kernel<<<dim3(32,32,1),dim3(32,8)>>>(gW0, 0, 1024, 1024, P.G0h, P.G0l, 0, nullptr);
    tconv_kernel<<<dim3(32,32,1),dim3(32,8)>>>(gW1, 0, 1024, 1024, P.G1h, P.G1l, 0, nullptr);
    tconv_kernel<<<dim3(32,32,1),dim3(32,8)>>>(gW2, 0, 1024, 1024, P.G2h, P.G2l, 0, nullptr);

    // ---- attention LSTM (FFMA fp32) ----
    concat3_kernel<<<(BB*3072+255)/256,256>>>(prev_h, fc, xt, P.xcat);
    small_gemm<true >(P.xcat,3072, aWih,3072, P.gates,4096, BB,4096,3072, abih);
    small_gemm<true >(h0,1024,     aWhh,1024, P.gates,4096, BB,4096,1024, abhh, 1);
    lstm_kernel<<<(BR+255)/256,256>>>(P.gates, c0, P.hatt, P.catt);

    // ---- h-terms ----
    small_gemm<true >(P.hatt,1024, e1W+1024,2048, P.ht1,1024, BB,1024,1024);
    small_gemm<true >(P.hatt,1024, e2W+1024,2048, P.ht2,1024, BB,1024,1024);
    small_gemm<false>(prev_h,1024, gW0+1024*1024,1024, P.pvec,1024, BB,1024,1024);

    // ---- E1/E2 (tensor core) ----
    hmma_gemm<<<dim3(8,256,1),256,MMA_SMEM>>>(P.Ph,P.Pl,1024,0, P.W1h,P.W1l,1024,0,
        1024, 0, 1, 0, nullptr,0, P.Qh,P.Ql,1024, e1b, P.ht1, mask, nullptr);
    hmma_gemm<<<dim3(8,256,1),256,MMA_SMEM>>>(P.Ph,P.Pl,1024,0, P.W2h,P.W2l,1024,0,
        1024, 0, 1, 0, nullptr,0, P.Sh,P.Sl,1024, e2b, P.ht2, mask, nullptr);

    // ---- Adj = E1 @ E2^T ----
    hmma_gemm<<<dim3(4,4,64),256,MMA_SMEM>>>(P.Qh,P.Ql,1024,(long)NN*RR, P.Sh,P.Sl,1024,(long)NN*RR,
        1024, 512, 0, 0, P.adj,512, nullptr,nullptr,0, nullptr,nullptr,nullptr,nullptr);

    // ---- Adj post-processing ----
    batchmin_kernel<<<BB,1024>>>(P.adj, P.minv);
    topk_kernel<<<BB*NN,512>>>(P.adj, P.minv, mask, P.dvec);
    dscale_conv_kernel<<<(int)(((long)BB*NN*NN+255)/256),256>>>(P.adj, P.dvec, P.ADJh, P.ADJl);
    srow_kernel<<<(BB*NN*32+255)/256,256>>>(P.adj, mask, P.srow);

    // ---- GCN layer 0 ----
    hmma_gemm<<<dim3(8,4,64),256,MMA_SMEM>>>(P.ADJh,P.ADJl,512,(long)NN*NN, P.Th,P.Tl,512,(long)RR*NN,
        512, 512, 1, 0, nullptr,0, P.Qh,P.Ql,1024, nullptr,nullptr,nullptr,nullptr);
    hmma_gemm<<<dim3(8,256,1),256,MMA_SMEM>>>(P.Qh,P.Ql,1024,0, P.G0h,P.G0l,1024,0,
        1024, 0, 2, 1, nullptr,0, P.Sh,P.Sl,0, gb0, P.pvec, P.srow, mask);

    // ---- GCN layer 1 ----
    hmma_gemm<<<dim3(8,4,64),256,MMA_SMEM>>>(P.ADJh,P.ADJl,512,(long)NN*NN, P.Sh,P.Sl,512,(long)RR*NN,
        512, 512, 1, 0, nullptr,0, P.Qh,P.Ql,1024, nullptr,nullptr,nullptr,nullptr);
    hmma_gemm<<<dim3(8,256,1),256,MMA_SMEM>>>(P.Qh,P.Ql,1024,0, P.G1h,P.G1l,1024,0,
        1024, 0, 2, 1, nullptr,0, P.Ph,P.Pl,0, gb1, nullptr, nullptr, mask);

    // ---- GCN layer 2 ----
    hmma_gemm<<<dim3(8,4,64),256,MMA_SMEM>>>(P.ADJh,P.ADJl,512,(long)NN*NN, P.Ph,P.Pl,512,(long)RR*NN,
        512, 512, 1, 0, nullptr,0, P.Qh,P.Ql,1024, nullptr,nullptr,nullptr,nullptr);
    hmma_gemm<<<dim3(8,256,1),256,MMA_SMEM>>>(P.Qh,P.Ql,1024,0, P.G2h,P.G2l,1024,0,
        1024, 0, 2, 1, nullptr,0, P.Sh,P.Sl,0, gb2, nullptr, nullptr, mask);

    // ---- att = max over nodes (XT contiguous) ----
    colmaxT_kernel<<<(BB*RR*32+255)/256,256>>>(P.Sh, P.Sl, P.attv);

    // ---- language LSTM ----
    concat2_kernel<<<(BB*2048+255)/256,256>>>(P.attv, P.hatt, P.xl);
    small_gemm<true >(P.xl,2048,   lWih,2048, P.gates2,4096, BB,4096,2048, lbih);
    small_gemm<true >(prev_h,1024, lWhh,1024, P.gates2,4096, BB,4096,1024, lbhh, 1);
    lstm_kernel<<<(BR+255)/256,256>>>(P.gates2, c1, P.hlang, P.clang);

    pack_kernel<<<(BR+255)/256,256>>>(P.hatt, P.catt, P.hlang, P.clang, out, out_size);
}

// round 6
// speedup vs baseline: 2.7032x; 1.1855x over previous
#include <cuda_runtime.h>
#include <cuda_bf16.h>
#include <math.h>
#include <stdint.h>

#define BB 64
#define NN 512
#define RR 1024
#define KTOP 256
#define BR (BB*RR)
#define NGE ((long)BB*NN*RR)

// ---------------- device scratch ----------------
__device__ float g_adj[(long)BB*NN*NN];
__device__ float g_xcat[BB*3072];
__device__ float g_gates[BB*4096];
__device__ float g_gates2[BB*4096];
__device__ float g_part[4*BB*4096];
__device__ float g_ht1[BB*RR];
__device__ float g_ht2[BB*RR];
__device__ float g_pvec[BB*RR];
__device__ float g_srow[BB*NN];
__device__ float g_dvec[BB*NN];
__device__ float g_minv[BB];
__device__ float g_attv[BB*RR];
__device__ float g_xl[BB*2048];
__device__ float g_hatt[BR];
__device__ float g_catt[BR];
__device__ float g_hlang[BR];
__device__ float g_clang[BR];

__device__ __nv_bfloat16 g_Ph[NGE], g_Pl[NGE];   // masked GE, later X2^T
__device__ __nv_bfloat16 g_Qh[NGE], g_Ql[NGE];   // E1, later Y
__device__ __nv_bfloat16 g_Sh[NGE], g_Sl[NGE];   // E2, later X1^T / X3^T
__device__ __nv_bfloat16 g_Th[NGE], g_Tl[NGE];   // GE^T (masked)
__device__ __nv_bfloat16 g_ADJh[(long)BB*NN*NN], g_ADJl[(long)BB*NN*NN];
__device__ __nv_bfloat16 g_W1h[1048576], g_W1l[1048576];
__device__ __nv_bfloat16 g_W2h[1048576], g_W2l[1048576];
__device__ __nv_bfloat16 g_G0h[1048576], g_G0l[1048576];
__device__ __nv_bfloat16 g_G1h[1048576], g_G1l[1048576];
__device__ __nv_bfloat16 g_G2h[1048576], g_G2l[1048576];

// ---------------- warp MMA helpers ----------------
__device__ __forceinline__ uint32_t smem_u32(const void* p){
    uint32_t a;
    asm("{ .reg .u64 t; cvta.to.shared.u64 t, %1; cvt.u32.u64 %0, t; }" : "=r"(a) : "l"(p));
    return a;
}
__device__ __forceinline__ uint32_t swz64(uint32_t x){ return x ^ ((x>>3)&0x30u); }
__device__ __forceinline__ void ldm4(uint32_t* r, uint32_t addr){
    asm volatile("ldmatrix.sync.aligned.m8n8.x4.shared.b16 {%0,%1,%2,%3}, [%4];"
        : "=r"(r[0]),"=r"(r[1]),"=r"(r[2]),"=r"(r[3]) : "r"(addr));
}
__device__ __forceinline__ void mma16816(float* d, const uint32_t* a, const uint32_t* b){
    asm volatile("mma.sync.aligned.m16n8k16.row.col.f32.bf16.bf16.f32 "
        "{%0,%1,%2,%3}, {%4,%5,%6,%7}, {%8,%9}, {%0,%1,%2,%3};"
        : "+f"(d[0]),"+f"(d[1]),"+f"(d[2]),"+f"(d[3])
        : "r"(a[0]),"r"(a[1]),"r"(a[2]),"r"(a[3]), "r"(b[0]),"r"(b[1]));
}
__device__ __forceinline__ void cpasync16(uint32_t dst, const void* src){
    asm volatile("cp.async.cg.shared.global [%0], [%1], 16;" :: "r"(dst), "l"(src));
}

// ---------------- bf16 hi/lo tensor-core GEMM, cp.async double-buffered ----------------
// C[128x128 tile] = (Ah+Al)[M,K] @ (Bh+Bl)[N,K]^T, K-major, fp32 accum.
// BK=32, 2 stages x 32KB, 8 warps (warp tile 32x64), 2 CTAs/SM.
#define MMA_SMEM (2*32768+1024)

__global__ void __launch_bounds__(256,2) hmma_gemm(
    const __nv_bfloat16* __restrict__ Ah, const __nv_bfloat16* __restrict__ Al, int lda, long sA,
    const __nv_bfloat16* __restrict__ Bh, const __nv_bfloat16* __restrict__ Bl, int ldb, long sB,
    int K, int rowsPerZ, int outMode, int relu,
    float* Cf, int ldc,
    __nv_bfloat16* Ch, __nv_bfloat16* Cl, int ldch,
    const float* __restrict__ bias, const float* __restrict__ addv,
    const float* __restrict__ rs, const float* __restrict__ ps)
{
    extern __shared__ char smraw[];
    uint32_t sb0 = smem_u32(smraw);
    uint32_t sb  = (sb0 + 1023u) & ~1023u;
    const int tid = threadIdx.x, wid = tid>>5, lane = tid&31;

    const __nv_bfloat16* A0 = Ah + blockIdx.z*sA;
    const __nv_bfloat16* A1 = Al + blockIdx.z*sA;
    const __nv_bfloat16* B0 = Bh + blockIdx.z*sB;
    const __nv_bfloat16* B1 = Bl + blockIdx.z*sB;
    const int rowBase = blockIdx.y*128, colBase = blockIdx.x*128;
    const int NC = K >> 5;

    const int wr = wid>>1, wc = wid&1;
    const int lr = lane&7, q = lane>>3;
    const int aRowOff = ((q&1)<<3) + lr;
    const int aKbOff  = (q>>1)<<4;
    const int bRowOff = ((q>>1)<<3) + lr;
    const int bKbOff  = (q&1)<<4;

    // per-thread cp.async assignment: 8 transfers (2 per buffer)
    const int cp_r[2] = { (tid&511)>>2, ((tid+256)&511)>>2 };
    const int cp_u    = tid&3;  // same unit for both (since +256 preserves low 2 bits)

    float acc[2][8][4];
    #pragma unroll
    for (int a=0;a<2;a++)
        #pragma unroll
        for (int b=0;b<8;b++)
            #pragma unroll
            for (int c=0;c<4;c++) acc[a][b][c]=0.f;

    auto load_chunk = [&](int ci, int s){
        const int k0 = ci<<5;
        const uint32_t st = sb + s*32768;
        #pragma unroll
        for (int j=0;j<2;j++){
            int r = cp_r[j];
            uint32_t doff = swz64((uint32_t)(r*64 + cp_u*16));
            long aoff = (long)(rowBase+r)*lda + k0 + cp_u*8;
            long boff = (long)(colBase+r)*ldb + k0 + cp_u*8;
            cpasync16(st +         doff, A0 + aoff);
            cpasync16(st +  8192 + doff, A1 + aoff);
            cpasync16(st + 16384 + doff, B0 + boff);
            cpasync16(st + 24576 + doff, B1 + boff);
        }
        asm volatile("cp.async.commit_group;" ::: "memory");
    };

    load_chunk(0, 0);
    for (int i=0;i<NC;i++){
        const int s = i&1;
        if (i+1 < NC){
            load_chunk(i+1, s^1);
            asm volatile("cp.async.wait_group 1;" ::: "memory");
        } else {
            asm volatile("cp.async.wait_group 0;" ::: "memory");
        }
        __syncthreads();
        const uint32_t st = sb + s*32768;
        #pragma unroll
        for (int ks=0;ks<2;ks++){
            const uint32_t kb = ks<<5;
            uint32_t ah[2][4], al[2][4], bbv[4][4];
            #pragma unroll
            for (int mi=0;mi<2;mi++){
                uint32_t ro = (uint32_t)((wr*32 + mi*16 + aRowOff)*64) + kb + aKbOff;
                ldm4(ah[mi], st + swz64(ro));
                ldm4(al[mi], st + 8192 + swz64(ro));
            }
            #pragma unroll
            for (int t=0;t<4;t++){
                uint32_t ro = (uint32_t)((wc*64 + t*16 + bRowOff)*64) + kb + bKbOff;
                ldm4(bbv[t], st + 16384 + swz64(ro));
            }
            #pragma unroll
            for (int mi=0;mi<2;mi++)
                #pragma unroll
                for (int t=0;t<4;t++){
                    mma16816(acc[mi][2*t],   ah[mi], &bbv[t][0]);
                    mma16816(acc[mi][2*t+1], ah[mi], &bbv[t][2]);
                }
            #pragma unroll
            for (int mi=0;mi<2;mi++)
                #pragma unroll
                for (int t=0;t<4;t++){
                    mma16816(acc[mi][2*t],   al[mi], &bbv[t][0]);
                    mma16816(acc[mi][2*t+1], al[mi], &bbv[t][2]);
                }
            #pragma unroll
            for (int t=0;t<4;t++){
                uint32_t ro = (uint32_t)((wc*64 + t*16 + bRowOff)*64) + kb + bKbOff;
                ldm4(bbv[t], st + 24576 + swz64(ro));
            }
            #pragma unroll
            for (int mi=0;mi<2;mi++)
                #pragma unroll
                for (int t=0;t<4;t++){
                    mma16816(acc[mi][2*t],   ah[mi], &bbv[t][0]);
                    mma16816(acc[mi][2*t+1], ah[mi], &bbv[t][2]);
                }
        }
        __syncthreads();
    }

    // ---- epilogue ----
    const int cpair = (lane&3)*2;
    #pragma unroll
    for (int mi=0;mi<2;mi++){
        #pragma unroll
        for (int rr=0;rr<2;rr++){
            const int r  = rowBase + wr*32 + mi*16 + (lane>>2) + rr*8;
            const int gr = blockIdx.z*rowsPerZ + r;
            const float rsv = rs ? rs[gr] : 1.f;
            const float psv = ps ? ps[gr] : 1.f;
            const float* avp = addv ? addv + (long)(gr>>9)*RR : nullptr;
            #pragma unroll
            for (int ni=0;ni<8;ni++){
                const int c = colBase + wc*64 + ni*8 + cpair;
                float x0 = acc[mi][ni][rr*2+0];
                float x1 = acc[mi][ni][rr*2+1];
                if (avp){ x0 += rsv*avp[c]; x1 += rsv*avp[c+1]; }
                if (bias){ x0 += bias[c]; x1 += bias[c+1]; }
                if (relu){ x0 = fmaxf(x0,0.f); x1 = fmaxf(x1,0.f); }
                x0 *= psv; x1 *= psv;
                if (outMode==0){
                    *(float2*)(Cf + (long)gr*ldc + c) = make_float2(x0,x1);
                } else {
                    __nv_bfloat16 h0 = __float2bfloat16(x0);
                    __nv_bfloat16 l0 = __float2bfloat16(x0-__bfloat162float(h0));
                    __nv_bfloat16 h1 = __float2bfloat16(x1);
                    __nv_bfloat16 l1 = __float2bfloat16(x1-__bfloat162float(h1));
                    if (outMode==1){
                        long o = (long)gr*ldch + c;
                        __nv_bfloat162 hp; hp.x=h0; hp.y=h1;
                        __nv_bfloat162 lp; lp.x=l0; lp.y=l1;
                        *(__nv_bfloat162*)(Ch+o) = hp;
                        *(__nv_bfloat162*)(Cl+o) = lp;
                    } else { // transposed: XT[b][feat][node]
                        long base = (long)(gr>>9)*((long)RR*NN) + (gr&511);
                        long o0 = base + (long)c*NN;
                        Ch[o0]=h0; Cl[o0]=l0;
                        Ch[o0+NN]=h1; Cl[o0+NN]=l1;
                    }
                }
            }
        }
    }
}

// ---------------- FFMA split-K GEMM for small (B=64) matmuls ----------------
// Partial z computes A[:,z*chunkK:(z+1)*chunkK] @ op(B) -> part + z*partStride.
template<bool BT>
__global__ void __launch_bounds__(256) gemm_part(
    const float* __restrict__ A,int lda,
    const float* __restrict__ B,int ldb,
    float* __restrict__ C,int ldc,long partStride,int chunkK)
{
    __shared__ float As[16][64];
    __shared__ float Bs[16][64];
    const int tid = threadIdx.x;
    const int rowBase = blockIdx.y*64, colBase = blockIdx.x*64;
    const int kbeg = blockIdx.z*chunkK, kend = kbeg + chunkK;
    const int tx = tid & 15, ty = tid >> 4;
    float acc[4][4];
#pragma unroll
    for (int i=0;i<4;i++)
#pragma unroll
        for (int j=0;j<4;j++) acc[i][j]=0.f;

    for (int k0=kbeg;k0<kend;k0+=16){
#pragma unroll
        for (int i=tid*4;i<64*16;i+=256*4){
            int r=i>>4, kk=i&15;
            float4 v = *(const float4*)(A + (long)(rowBase+r)*lda + k0 + kk);
            As[kk+0][r]=v.x; As[kk+1][r]=v.y; As[kk+2][r]=v.z; As[kk+3][r]=v.w;
        }
        if (BT){
#pragma unroll
            for (int i=tid*4;i<64*16;i+=256*4){
                int r=i>>4, kk=i&15;
                float4 v = *(const float4*)(B + (long)(colBase+r)*ldb + k0 + kk);
                Bs[kk+0][r]=v.x; Bs[kk+1][r]=v.y; Bs[kk+2][r]=v.z; Bs[kk+3][r]=v.w;
            }
        } else {
#pragma unroll
            for (int i=tid*4;i<16*64;i+=256*4){
                int r=i>>6, cc=i&63;
                *(float4*)&Bs[r][cc] = *(const float4*)(B + (long)(k0+r)*ldb + colBase + cc);
            }
        }
        __syncthreads();
#pragma unroll
        for (int k=0;k<16;k++){
            float a[4], b[4];
            *(float4*)a = *(const float4*)&As[k][ty*4];
            *(float4*)b = *(const float4*)&Bs[k][tx*4];
#pragma unroll
            for (int i=0;i<4;i++)
#pragma unroll
                for (int j=0;j<4;j++) acc[i][j] = fmaf(a[i], b[j], acc[i][j]);
        }
        __syncthreads();
    }
    float* Cp = C + (long)blockIdx.z*partStride;
#pragma unroll
    for (int i=0;i<4;i++){
        int r = rowBase + ty*4 + i;
#pragma unroll
        for (int j=0;j<4;j++)
            Cp[(long)r*ldc + colBase + tx*4 + j] = acc[i][j];
    }
}
static void sgemm(bool BT,const float* A,int lda,const float* B,int ldb,float* Cpart,int ldc,
                  int M,int N,int K,int splits){
    dim3 g(N/64, M/64, splits);
    int chunkK = K/splits;
    if (BT) gemm_part<true ><<<g,256>>>(A,lda,B,ldb,Cpart,ldc,(long)M*ldc,chunkK);
    else    gemm_part<false><<<g,256>>>(A,lda,B,ldb,Cpart,ldc,(long)M*ldc,chunkK);
}
// dst[i] = sum_z src[z*len+i] + b1[col] + b2[col]
__global__ void reduce_kernel(float* dst,const float* src,long len,int splits,int colmask,
                              const float* b1,const float* b2){
    long i = (long)blockIdx.x*blockDim.x+threadIdx.x;
    if (i >= len) return;
    float s = 0.f;
    for (int z=0;z<splits;z++) s += src[z*len+i];
    int col = (int)(i & colmask);
    if (b1) s += b1[col];
    if (b2) s += b2[col];
    dst[i] = s;
}

// ---------------- conversions ----------------
__device__ __forceinline__ void split1(float v, __nv_bfloat16& h, __nv_bfloat16& l){
    h = __float2bfloat16(v);
    l = __float2bfloat16(v - __bfloat162float(h));
}

__global__ void conv_mask_kernel(const float* __restrict__ src, const float* __restrict__ mask,
                                 __nv_bfloat16* __restrict__ dh, __nv_bfloat16* __restrict__ dl, long n4){
    long i = (long)blockIdx.x*blockDim.x + threadIdx.x;
    if (i >= n4) return;
    float4 v = ((const float4*)src)[i];
    float m = mask[i >> 8];
    v.x*=m; v.y*=m; v.z*=m; v.w*=m;
    __align__(8) __nv_bfloat16 h[4], l[4];
    split1(v.x,h[0],l[0]); split1(v.y,h[1],l[1]); split1(v.z,h[2],l[2]); split1(v.w,h[3],l[3]);
    ((uint2*)dh)[i] = *(uint2*)h;
    ((uint2*)dl)[i] = *(uint2*)l;
}

__global__ void conv_slice_kernel(const float* __restrict__ src, int ldsrc,
                                  __nv_bfloat16* __restrict__ dh, __nv_bfloat16* __restrict__ dl,
                                  int cols, int n4){
    int i = blockIdx.x*blockDim.x + threadIdx.x;
    if (i >= n4) return;
    int c4pr = cols/4;
    int r = i / c4pr, c4 = i % c4pr;
    float4 v = *(const float4*)(src + (long)r*ldsrc + c4*4);
    __align__(8) __nv_bfloat16 h[4], l[4];
    split1(v.x,h[0],l[0]); split1(v.y,h[1],l[1]); split1(v.z,h[2],l[2]); split1(v.w,h[3],l[3]);
    long o = (long)r*c4pr + c4;
    ((uint2*)dh)[o] = *(uint2*)h;
    ((uint2*)dl)[o] = *(uint2*)l;
}

// per-batch transpose+convert: src [rows,cols] fp32 -> dst [cols,rows] bf16 hi/lo
__global__ void tconv_kernel(const float* __restrict__ src, long sS, int rows, int cols,
                             __nv_bfloat16* __restrict__ dh, __nv_bfloat16* __restrict__ dl, long sD,
                             const float* __restrict__ mask){
    __shared__ float t[32][33];
    int b = blockIdx.z;
    const float* S = src + (long)b*sS;
    int r0 = blockIdx.y*32, c0 = blockIdx.x*32;
    int tx = threadIdx.x, ty = threadIdx.y;
    for (int i=ty;i<32;i+=8){
        float v = S[(long)(r0+i)*cols + c0+tx];
        if (mask) v *= mask[(long)b*rows + r0+i];
        t[i][tx] = v;
    }
    __syncthreads();
    __nv_bfloat16* DH = dh + (long)b*sD;
    __nv_bfloat16* DL = dl + (long)b*sD;
    for (int i=ty;i<32;i+=8){
        float v = t[tx][i];
        __nv_bfloat16 h, l; split1(v, h, l);
        long o = (long)(c0+i)*rows + r0+tx;
        DH[o] = h; DL[o] = l;
    }
}

// ---------------- pointwise / reductions ----------------
__device__ __forceinline__ float sigm(float x){ return 1.f/(1.f+__expf(-x)); }

__global__ void concat3_kernel(const float* a,const float* b,const float* c,float* out){
    int idx = blockIdx.x*blockDim.x+threadIdx.x;
    if (idx >= BB*3072) return;
    int bb = idx/3072, j = idx%3072;
    out[idx] = (j<1024) ? a[bb*1024+j] : (j<2048 ? b[bb*1024+j-1024] : c[bb*1024+j-2048]);
}
__global__ void concat2_kernel(const float* a,const float* b,float* out){
    int idx = blockIdx.x*blockDim.x+threadIdx.x;
    if (idx >= BB*2048) return;
    int bb = idx/2048, j = idx%2048;
    out[idx] = (j<1024) ? a[bb*1024+j] : b[bb*1024+j-1024];
}
__global__ void lstm_kernel(const float* gates,const float* c_prev,float* h_out,float* c_out){
    int idx = blockIdx.x*blockDim.x+threadIdx.x;
    if (idx >= BR) return;
    int bb = idx >> 10, r = idx & 1023;
    const float* g = gates + bb*4096;
    float c = sigm(g[1024+r])*c_prev[idx] + sigm(g[r])*tanhf(g[2048+r]);
    h_out[idx] = sigm(g[3072+r])*tanhf(c);
    c_out[idx] = c;
}
__global__ void batchmin_kernel(const float* Adj,float* minv){
    __shared__ float sm[1024];
    const float* a = Adj + (long)blockIdx.x*NN*NN;
    float mn = INFINITY;
    for (int i=threadIdx.x;i<NN*NN;i+=1024) mn = fminf(mn, a[i]);
    sm[threadIdx.x]=mn; __syncthreads();
    for (int s=512;s>0;s>>=1){ if (threadIdx.x<s) sm[threadIdx.x]=fminf(sm[threadIdx.x],sm[threadIdx.x+s]); __syncthreads(); }
    if (threadIdx.x==0) minv[blockIdx.x]=sm[0];
}
__global__ void __launch_bounds__(512) topk_kernel(float* Adj,const float* minv,
                                                   const float* mask,float* dvec){
    __shared__ unsigned long long keys[NN];
    __shared__ float red[NN];
    int row = blockIdx.x, t = threadIdx.x, bb = row >> 9;
    float mrow = mask[row];
    float* arow = Adj + (long)row*NN;
    float v = (arow[t] - minv[bb]) * mrow;
    keys[t] = ((unsigned long long)__float_as_uint(v) << 32) | (unsigned)(NN-1-t);
    __syncthreads();
    for (unsigned k2=2;k2<=NN;k2<<=1)
        for (unsigned j=k2>>1;j>0;j>>=1){
            unsigned ixj = t ^ j;
            if (ixj > (unsigned)t){
                unsigned long long x=keys[t], y=keys[ixj];
                bool desc = ((t & k2) == 0);
                if (desc ? (x<y) : (x>y)){ keys[t]=y; keys[ixj]=x; }
            }
            __syncthreads();
        }
    unsigned long long kk = keys[t];
    arow[t] = 0.f;
    __syncthreads();
    float s = 0.f;
    if (t < KTOP){
        int col = (NN-1) - (int)(unsigned)(kk & 0xffffffffu);
        float val = __uint_as_float((unsigned)(kk >> 32));
        arow[col] = val;
        s = val;
    }
    red[t]=s; __syncthreads();
    for (int st=NN/2;st>0;st>>=1){ if (t<st) red[t]+=red[t+st]; __syncthreads(); }
    if (t==0) dvec[row] = (red[0] > 0.f) ? rsqrtf(red[0]) : 0.f;
}
__global__ void dscale_conv_kernel(float* Adj,const float* d,
                                   __nv_bfloat16* Ah,__nv_bfloat16* Al){
    long idx = (long)blockIdx.x*blockDim.x+threadIdx.x;
    if (idx >= (long)BB*NN*NN) return;
    int row = (int)(idx >> 9), col = (int)(idx & (NN-1)), bb = row >> 9;
    float v = Adj[idx] * d[row] * d[(bb<<9)+col];
    Adj[idx] = v;
    __nv_bfloat16 h,l; split1(v,h,l);
    Ah[idx]=h; Al[idx]=l;
}
__global__ void srow_kernel(const float* Adj,const float* mask,float* srow){
    int warp = (blockIdx.x*blockDim.x+threadIdx.x) >> 5;
    int lane = threadIdx.x & 31;
    if (warp >= BB*NN) return;
    int bb = warp >> 9;
    const float* a = Adj + (long)warp*NN;
    const float* m = mask + bb*NN;
    float s = 0.f;
    for (int k=lane;k<NN;k+=32) s += a[k]*m[k];
    for (int o=16;o;o>>=1) s += __shfl_xor_sync(0xffffffffu, s, o);
    if (lane==0) srow[warp] = s;
}
__global__ void colmaxT_kernel(const __nv_bfloat16* Xh,const __nv_bfloat16* Xl,float* att){
    int warp = (blockIdx.x*blockDim.x+threadIdx.x) >> 5;
    int lane = threadIdx.x & 31;
    if (warp >= BB*RR) return;
    long base = (long)warp*NN;
    float mx = -INFINITY;
    for (int k=lane;k<NN;k+=32)
        mx = fmaxf(mx, __bfloat162float(Xh[base+k]) + __bfloat162float(Xl[base+k]));
    for (int o=16;o;o>>=1) mx = fmaxf(mx, __shfl_xor_sync(0xffffffffu, mx, o));
    if (lane==0) att[warp] = mx;
}
__global__ void pack_kernel(const float* hatt,const float* catt,
                            const float* hlang,const float* clang,float* out,int out_size){
    int i = blockIdx.x*blockDim.x+threadIdx.x;
    if (i >= BR) return;
    out[i] = hlang[i];
    if (out_size >= 5*BR){
        out[1*BR+i] = hatt[i];
        out[2*BR+i] = hlang[i];
        out[3*BR+i] = catt[i];
        out[4*BR+i] = clang[i];
    }
}

// ---------------- host driver ----------------
struct Ptrs {
    float *adj,*xcat,*gates,*gates2,*part,*ht1,*ht2,*pvec,*srow,*dvec,*minv,*attv,*xl,*hatt,*catt,*hlang,*clang;
    __nv_bfloat16 *Ph,*Pl,*Qh,*Ql,*Sh,*Sl,*Th,*Tl,*ADJh,*ADJl;
    __nv_bfloat16 *W1h,*W1l,*W2h,*W2l,*G0h,*G0l,*G1h,*G1l,*G2h,*G2l;
};
static Ptrs P;
static bool g_init = false;

extern "C" void kernel_launch(void* const* d_in, const int* in_sizes, int n_in,
                              void* d_out, int out_size)
{
    const float* xt   = (const float*)d_in[0];
    const float* fc   = (const float*)d_in[1];
    const float* ge   = (const float*)d_in[2];
    const float* sh   = (const float*)d_in[4];
    const float* sc   = (const float*)d_in[5];
    const float* mask = (const float*)d_in[6];
    const float* aWih = (const float*)d_in[7];
    const float* aWhh = (const float*)d_in[8];
    const float* abih = (const float*)d_in[9];
    const float* abhh = (const float*)d_in[10];
    const float* lWih = (const float*)d_in[11];
    const float* lWhh = (const float*)d_in[12];
    const float* lbih = (const float*)d_in[13];
    const float* lbhh = (const float*)d_in[14];
    const float* e1W  = (const float*)d_in[15];
    const float* e1b  = (const float*)d_in[16];
    const float* e2W  = (const float*)d_in[17];
    const float* e2b  = (const float*)d_in[18];
    const float* gW0  = (const float*)d_in[19];
    const float* gb0  = (const float*)d_in[20];
    const float* gW1  = (const float*)d_in[21];
    const float* gb1  = (const float*)d_in[22];
    const float* gW2  = (const float*)d_in[23];
    const float* gb2  = (const float*)d_in[24];
    (void)in_sizes; (void)n_in;
    float* out = (float*)d_out;

    if (!g_init){
        cudaGetSymbolAddress((void**)&P.adj,  g_adj);
        cudaGetSymbolAddress((void**)&P.xcat, g_xcat);
        cudaGetSymbolAddress((void**)&P.gates,g_gates);
        cudaGetSymbolAddress((void**)&P.gates2,g_gates2);
        cudaGetSymbolAddress((void**)&P.part, g_part);
        cudaGetSymbolAddress((void**)&P.ht1,  g_ht1);
        cudaGetSymbolAddress((void**)&P.ht2,  g_ht2);
        cudaGetSymbolAddress((void**)&P.pvec, g_pvec);
        cudaGetSymbolAddress((void**)&P.srow, g_srow);
        cudaGetSymbolAddress((void**)&P.dvec, g_dvec);
        cudaGetSymbolAddress((void**)&P.minv, g_minv);
        cudaGetSymbolAddress((void**)&P.attv, g_attv);
        cudaGetSymbolAddress((void**)&P.xl,   g_xl);
        cudaGetSymbolAddress((void**)&P.hatt, g_hatt);
        cudaGetSymbolAddress((void**)&P.catt, g_catt);
        cudaGetSymbolAddress((void**)&P.hlang,g_hlang);
        cudaGetSymbolAddress((void**)&P.clang,g_clang);
        cudaGetSymbolAddress((void**)&P.Ph, g_Ph); cudaGetSymbolAddress((void**)&P.Pl, g_Pl);
        cudaGetSymbolAddress((void**)&P.Qh, g_Qh); cudaGetSymbolAddress((void**)&P.Ql, g_Ql);
        cudaGetSymbolAddress((void**)&P.Sh, g_Sh); cudaGetSymbolAddress((void**)&P.Sl, g_Sl);
        cudaGetSymbolAddress((void**)&P.Th, g_Th); cudaGetSymbolAddress((void**)&P.Tl, g_Tl);
        cudaGetSymbolAddress((void**)&P.ADJh, g_ADJh); cudaGetSymbolAddress((void**)&P.ADJl, g_ADJl);
        cudaGetSymbolAddress((void**)&P.W1h, g_W1h); cudaGetSymbolAddress((void**)&P.W1l, g_W1l);
        cudaGetSymbolAddress((void**)&P.W2h, g_W2h); cudaGetSymbolAddress((void**)&P.W2l, g_W2l);
        cudaGetSymbolAddress((void**)&P.G0h, g_G0h); cudaGetSymbolAddress((void**)&P.G0l, g_G0l);
        cudaGetSymbolAddress((void**)&P.G1h, g_G1h); cudaGetSymbolAddress((void**)&P.G1l, g_G1l);
        cudaGetSymbolAddress((void**)&P.G2h, g_G2h); cudaGetSymbolAddress((void**)&P.G2l, g_G2l);
        cudaFuncSetAttribute(hmma_gemm, cudaFuncAttributeMaxDynamicSharedMemorySize, MMA_SMEM);
        g_init = true;
    }

    const float* prev_h = sh + BR;
    const float* h0 = sh;
    const float* c0 = sc;
    const float* c1 = sc + BR;

    // ---- conversions (weights + GE) ----
    conv_mask_kernel<<<(int)((NGE/4+255)/256),256>>>(ge, mask, P.Ph, P.Pl, NGE/4);
    tconv_kernel<<<dim3(32,16,64),dim3(32,8)>>>(ge,(long)NN*RR, NN, RR, P.Th, P.Tl,(long)RR*NN, mask);
    conv_slice_kernel<<<(1048576/4+255)/256,256>>>(e1W, 2048, P.W1h, P.W1l, 1024, 1048576/4);
    conv_slice_kernel<<<(1048576/4+255)/256,256>>>(e2W, 2048, P.W2h, P.W2l, 1024, 1048576/4);
    tconv_kernel<<<dim3(32,32,1),dim3(32,8)>>>(gW0, 0, 1024, 1024, P.G0h, P.G0l, 0, nullptr);
    tconv_kernel<<<dim3(32,32,1),dim3(32,8)>>>(gW1, 0, 1024, 1024, P.G1h, P.G1l, 0, nullptr);
    tconv_kernel<<<dim3(32,32,1),dim3(32,8)>>>(gW2, 0, 1024, 1024, P.G2h, P.G2l, 0, nullptr);

    // ---- attention LSTM (split-K FFMA) ----
    concat3_kernel<<<(BB*3072+255)/256,256>>>(prev_h, fc, xt, P.xcat);
    sgemm(true, P.xcat,3072, aWih,3072, P.part,            4096, BB,4096,3072, 3);
    sgemm(true, h0,1024,     aWhh,1024, P.part+3*BB*4096,  4096, BB,4096,1024, 1);
    reduce_kernel<<<(BB*4096+255)/256,256>>>(P.gates, P.part, BB*4096, 4, 4095, abih, abhh);
    lstm_kernel<<<(BR+255)/256,256>>>(P.gates, c0, P.hatt, P.catt);

    // ---- h-terms (split-K FFMA) ----
    sgemm(true, P.hatt,1024, e1W+1024,2048, P.part, 1024, BB,1024,1024, 4);
    reduce_kernel<<<(BB*1024+255)/256,256>>>(P.ht1, P.part, BB*1024, 4, 1023, nullptr, nullptr);
    sgemm(true, P.hatt,1024, e2W+1024,2048, P.part, 1024, BB,1024,1024, 4);
    reduce_kernel<<<(BB*1024+255)/256,256>>>(P.ht2, P.part, BB*1024, 4, 1023, nullptr, nullptr);
    sgemm(false, prev_h,1024, gW0+1024*1024,1024, P.part, 1024, BB,1024,1024, 4);
    reduce_kernel<<<(BB*1024+255)/256,256>>>(P.pvec, P.part, BB*1024, 4, 1023, nullptr, nullptr);

    // ---- E1/E2 (tensor core) ----
    hmma_gemm<<<dim3(8,256,1),256,MMA_SMEM>>>(P.Ph,P.Pl,1024,0, P.W1h,P.W1l,1024,0,
        1024, 0, 1, 0, nullptr,0, P.Qh,P.Ql,1024, e1b, P.ht1, mask, nullptr);
    hmma_gemm<<<dim3(8,256,1),256,MMA_SMEM>>>(P.Ph,P.Pl,1024,0, P.W2h,P.W2l,1024,0,
        1024, 0, 1, 0, nullptr,0, P.Sh,P.Sl,1024, e2b, P.ht2, mask, nullptr);

    // ---- Adj = E1 @ E2^T ----
    hmma_gemm<<<dim3(4,4,64),256,MMA_SMEM>>>(P.Qh,P.Ql,1024,(long)NN*RR, P.Sh,P.Sl,1024,(long)NN*RR,
        1024, 512, 0, 0, P.adj,512, nullptr,nullptr,0, nullptr,nullptr,nullptr,nullptr);

    // ---- Adj post-processing ----
    batchmin_kernel<<<BB,1024>>>(P.adj, P.minv);
    topk_kernel<<<BB*NN,512>>>(P.adj, P.minv, mask, P.dvec);
    dscale_conv_kernel<<<(int)(((long)BB*NN*NN+255)/256),256>>>(P.adj, P.dvec, P.ADJh, P.ADJl);
    srow_kernel<<<(BB*NN*32+255)/256,256>>>(P.adj, mask, P.srow);

    // ---- GCN layer 0 ----
    hmma_gemm<<<dim3(8,4,64),256,MMA_SMEM>>>(P.ADJh,P.ADJl,512,(long)NN*NN, P.Th,P.Tl,512,(long)RR*NN,
        512, 512, 1, 0, nullptr,0, P.Qh,P.Ql,1024, nullptr,nullptr,nullptr,nullptr);
    hmma_gemm<<<dim3(8,256,1),256,MMA_SMEM>>>(P.Qh,P.Ql,1024,0, P.G0h,P.G0l,1024,0,
        1024, 0, 2, 1, nullptr,0, P.Sh,P.Sl,0, gb0, P.pvec, P.srow, mask);

    // ---- GCN layer 1 ----
    hmma_gemm<<<dim3(8,4,64),256,MMA_SMEM>>>(P.ADJh,P.ADJl,512,(long)NN*NN, P.Sh,P.Sl,512,(long)RR*NN,
        512, 512, 1, 0, nullptr,0, P.Qh,P.Ql,1024, nullptr,nullptr,nullptr,nullptr);
    hmma_gemm<<<dim3(8,256,1),256,MMA_SMEM>>>(P.Qh,P.Ql,1024,0, P.G1h,P.G1l,1024,0,
        1024, 0, 2, 1, nullptr,0, P.Ph,P.Pl,0, gb1, nullptr, nullptr, mask);

    // ---- GCN layer 2 ----
    hmma_gemm<<<dim3(8,4,64),256,MMA_SMEM>>>(P.ADJh,P.ADJl,512,(long)NN*NN, P.Ph,P.Pl,512,(long)RR*NN,
        512, 512, 1, 0, nullptr,0, P.Qh,P.Ql,1024, nullptr,nullptr,nullptr,nullptr);
    hmma_gemm<<<dim3(8,256,1),256,MMA_SMEM>>>(P.Qh,P.Ql,1024,0, P.G2h,P.G2l,1024,0,
        1024, 0, 2, 1, nullptr,0, P.Sh,P.Sl,0, gb2, nullptr, nullptr, mask);

    // ---- att = max over nodes (XT contiguous) ----
    colmaxT_kernel<<<(BB*RR*32+255)/256,256>>>(P.Sh, P.Sl, P.attv);

    // ---- language LSTM (split-K FFMA) ----
    concat2_kernel<<<(BB*2048+255)/256,256>>>(P.attv, P.hatt, P.xl);
    sgemm(true, P.xl,2048,   lWih,2048, P.part,           4096, BB,4096,2048, 2);
    sgemm(true, prev_h,1024, lWhh,1024, P.part+2*BB*4096, 4096, BB,4096,1024, 1);
    reduce_kernel<<<(BB*4096+255)/256,256>>>(P.gates2, P.part, BB*4096, 3, 4095, lbih, lbhh);
    lstm_kernel<<<(BR+255)/256,256>>>(P.gates2, c1, P.hlang, P.clang);

    pack_kernel<<<(BR+255)/256,256>>>(P.hatt, P.catt, P.hlang, P.clang, out, out_size);
}

// round 7
// speedup vs baseline: 2.8242x; 1.0447x over previous
#include <cuda_runtime.h>
#include <cuda_bf16.h>
#include <math.h>
#include <stdint.h>

#define BB 64
#define NN 512
#define RR 1024
#define KTOP 256
#define BR (BB*RR)
#define NGE ((long)BB*NN*RR)

// ---------------- device scratch ----------------
__device__ float g_adj[(long)BB*NN*NN];
__device__ float g_xcat[BB*3072];
__device__ float g_gates[BB*4096];
__device__ float g_gates2[BB*4096];
__device__ float g_part[4*BB*4096];
__device__ float g_ht1[BB*RR];
__device__ float g_ht2[BB*RR];
__device__ float g_pvec[BB*RR];
__device__ float g_srow[BB*NN];
__device__ float g_dvec[BB*NN];
__device__ float g_minv[BB];
__device__ float g_attv[BB*RR];
__device__ float g_xl[BB*2048];
__device__ float g_hatt[BR];
__device__ float g_catt[BR];
__device__ float g_hlang[BR];
__device__ float g_clang[BR];

__device__ __nv_bfloat16 g_Ph[NGE], g_Pl[NGE];   // masked GE, later X2^T
__device__ __nv_bfloat16 g_Qh[NGE], g_Ql[NGE];   // E1, later Y
__device__ __nv_bfloat16 g_Sh[NGE], g_Sl[NGE];   // E2, later X1^T / X3^T
__device__ __nv_bfloat16 g_Th[NGE], g_Tl[NGE];   // GE^T (masked)
__device__ __nv_bfloat16 g_ADJh[(long)BB*NN*NN], g_ADJl[(long)BB*NN*NN];
__device__ __nv_bfloat16 g_W1h[1048576], g_W1l[1048576];
__device__ __nv_bfloat16 g_W2h[1048576], g_W2l[1048576];
__device__ __nv_bfloat16 g_G0h[1048576], g_G0l[1048576];
__device__ __nv_bfloat16 g_G1h[1048576], g_G1l[1048576];
__device__ __nv_bfloat16 g_G2h[1048576], g_G2l[1048576];

// ---------------- warp MMA helpers ----------------
__device__ __forceinline__ uint32_t smem_u32(const void* p){
    uint32_t a;
    asm("{ .reg .u64 t; cvta.to.shared.u64 t, %1; cvt.u32.u64 %0, t; }" : "=r"(a) : "l"(p));
    return a;
}
__device__ __forceinline__ uint32_t swz64(uint32_t x){ return x ^ ((x>>3)&0x30u); }
__device__ __forceinline__ void ldm4(uint32_t* r, uint32_t addr){
    asm volatile("ldmatrix.sync.aligned.m8n8.x4.shared.b16 {%0,%1,%2,%3}, [%4];"
        : "=r"(r[0]),"=r"(r[1]),"=r"(r[2]),"=r"(r[3]) : "r"(addr));
}
__device__ __forceinline__ void mma16816(float* d, const uint32_t* a, const uint32_t* b){
    asm volatile("mma.sync.aligned.m16n8k16.row.col.f32.bf16.bf16.f32 "
        "{%0,%1,%2,%3}, {%4,%5,%6,%7}, {%8,%9}, {%0,%1,%2,%3};"
        : "+f"(d[0]),"+f"(d[1]),"+f"(d[2]),"+f"(d[3])
        : "r"(a[0]),"r"(a[1]),"r"(a[2]),"r"(a[3]), "r"(b[0]),"r"(b[1]));
}
__device__ __forceinline__ void cpasync16(uint32_t dst, const void* src){
    asm volatile("cp.async.cg.shared.global [%0], [%1], 16;" :: "r"(dst), "l"(src));
}

// ---------------- bf16 hi/lo tensor-core GEMM, 3-stage cp.async ----------------
// C[128x128 tile] = (Ah+Al)[M,K] @ (Bh+Bl)[N,K]^T, K-major, fp32 accum.
// BK=32, 3 stages x 32KB, 8 warps (warp tile 32x64), 2 CTAs/SM, 1 sync/chunk.
#define MMA_SMEM (3*32768+1024)

__global__ void __launch_bounds__(256,2) hmma_gemm(
    const __nv_bfloat16* __restrict__ Ah, const __nv_bfloat16* __restrict__ Al, int lda, long sA,
    const __nv_bfloat16* __restrict__ Bh, const __nv_bfloat16* __restrict__ Bl, int ldb, long sB,
    int K, int rowsPerZ, int outMode, int relu,
    float* Cf, int ldc,
    __nv_bfloat16* Ch, __nv_bfloat16* Cl, int ldch,
    const float* __restrict__ bias, const float* __restrict__ addv,
    const float* __restrict__ rs, const float* __restrict__ ps)
{
    extern __shared__ char smraw[];
    uint32_t sb0 = smem_u32(smraw);
    uint32_t sb  = (sb0 + 1023u) & ~1023u;
    const int tid = threadIdx.x, wid = tid>>5, lane = tid&31;

    const __nv_bfloat16* A0 = Ah + blockIdx.z*sA;
    const __nv_bfloat16* A1 = Al + blockIdx.z*sA;
    const __nv_bfloat16* B0 = Bh + blockIdx.z*sB;
    const __nv_bfloat16* B1 = Bl + blockIdx.z*sB;
    const int rowBase = blockIdx.y*128, colBase = blockIdx.x*128;
    const int NC = K >> 5;

    const int wr = wid>>1, wc = wid&1;
    const int lr = lane&7, q = lane>>3;
    const int aRowOff = ((q&1)<<3) + lr;
    const int aKbOff  = (q>>1)<<4;
    const int bRowOff = ((q>>1)<<3) + lr;
    const int bKbOff  = (q&1)<<4;

    const int cp_r[2] = { (tid&511)>>2, ((tid+256)&511)>>2 };
    const int cp_u    = tid&3;

    float acc[2][8][4];
    #pragma unroll
    for (int a=0;a<2;a++)
        #pragma unroll
        for (int b=0;b<8;b++)
            #pragma unroll
            for (int c=0;c<4;c++) acc[a][b][c]=0.f;

    auto load_chunk = [&](int ci, int s){
        const int k0 = ci<<5;
        const uint32_t st = sb + s*32768;
        #pragma unroll
        for (int j=0;j<2;j++){
            int r = cp_r[j];
            uint32_t doff = swz64((uint32_t)(r*64 + cp_u*16));
            long aoff = (long)(rowBase+r)*lda + k0 + cp_u*8;
            long boff = (long)(colBase+r)*ldb + k0 + cp_u*8;
            cpasync16(st +         doff, A0 + aoff);
            cpasync16(st +  8192 + doff, A1 + aoff);
            cpasync16(st + 16384 + doff, B0 + boff);
            cpasync16(st + 24576 + doff, B1 + boff);
        }
        asm volatile("cp.async.commit_group;" ::: "memory");
    };

    load_chunk(0, 0);
    if (NC > 1) load_chunk(1, 1);

    int sidx = 0;                 // i % 3
    int nidx = (NC > 2) ? 2 : 0;  // (i+2) % 3 tracker
    for (int i=0;i<NC;i++){
        if (i+1 < NC) asm volatile("cp.async.wait_group 1;" ::: "memory");
        else          asm volatile("cp.async.wait_group 0;" ::: "memory");
        __syncthreads();
        if (i+2 < NC){
            load_chunk(i+2, nidx);
            nidx = (nidx==2)?0:nidx+1;
        }
        const uint32_t st = sb + sidx*32768;
        sidx = (sidx==2)?0:sidx+1;
        #pragma unroll
        for (int ks=0;ks<2;ks++){
            const uint32_t kb = ks<<5;
            uint32_t ah[2][4], al[2][4], bbv[4][4];
            #pragma unroll
            for (int mi=0;mi<2;mi++){
                uint32_t ro = (uint32_t)((wr*32 + mi*16 + aRowOff)*64) + kb + aKbOff;
                ldm4(ah[mi], st + swz64(ro));
                ldm4(al[mi], st + 8192 + swz64(ro));
            }
            #pragma unroll
            for (int t=0;t<4;t++){
                uint32_t ro = (uint32_t)((wc*64 + t*16 + bRowOff)*64) + kb + bKbOff;
                ldm4(bbv[t], st + 16384 + swz64(ro));
            }
            #pragma unroll
            for (int mi=0;mi<2;mi++)
                #pragma unroll
                for (int t=0;t<4;t++){
                    mma16816(acc[mi][2*t],   ah[mi], &bbv[t][0]);
                    mma16816(acc[mi][2*t+1], ah[mi], &bbv[t][2]);
                }
            #pragma unroll
            for (int mi=0;mi<2;mi++)
                #pragma unroll
                for (int t=0;t<4;t++){
                    mma16816(acc[mi][2*t],   al[mi], &bbv[t][0]);
                    mma16816(acc[mi][2*t+1], al[mi], &bbv[t][2]);
                }
            #pragma unroll
            for (int t=0;t<4;t++){
                uint32_t ro = (uint32_t)((wc*64 + t*16 + bRowOff)*64) + kb + bKbOff;
                ldm4(bbv[t], st + 24576 + swz64(ro));
            }
            #pragma unroll
            for (int mi=0;mi<2;mi++)
                #pragma unroll
                for (int t=0;t<4;t++){
                    mma16816(acc[mi][2*t],   ah[mi], &bbv[t][0]);
                    mma16816(acc[mi][2*t+1], ah[mi], &bbv[t][2]);
                }
        }
    }

    // ---- epilogue ----
    const int cpair = (lane&3)*2;
    #pragma unroll
    for (int mi=0;mi<2;mi++){
        #pragma unroll
        for (int rr=0;rr<2;rr++){
            const int r  = rowBase + wr*32 + mi*16 + (lane>>2) + rr*8;
            const int gr = blockIdx.z*rowsPerZ + r;
            const float rsv = rs ? rs[gr] : 1.f;
            const float psv = ps ? ps[gr] : 1.f;
            const float* avp = addv ? addv + (long)(gr>>9)*RR : nullptr;
            #pragma unroll
            for (int ni=0;ni<8;ni++){
                const int c = colBase + wc*64 + ni*8 + cpair;
                float x0 = acc[mi][ni][rr*2+0];
                float x1 = acc[mi][ni][rr*2+1];
                if (avp){ x0 += rsv*avp[c]; x1 += rsv*avp[c+1]; }
                if (bias){ x0 += bias[c]; x1 += bias[c+1]; }
                if (relu){ x0 = fmaxf(x0,0.f); x1 = fmaxf(x1,0.f); }
                x0 *= psv; x1 *= psv;
                if (outMode==0){
                    *(float2*)(Cf + (long)gr*ldc + c) = make_float2(x0,x1);
                } else {
                    __nv_bfloat16 h0 = __float2bfloat16(x0);
                    __nv_bfloat16 l0 = __float2bfloat16(x0-__bfloat162float(h0));
                    __nv_bfloat16 h1 = __float2bfloat16(x1);
                    __nv_bfloat16 l1 = __float2bfloat16(x1-__bfloat162float(h1));
                    if (outMode==1){
                        long o = (long)gr*ldch + c;
                        __nv_bfloat162 hp; hp.x=h0; hp.y=h1;
                        __nv_bfloat162 lp; lp.x=l0; lp.y=l1;
                        *(__nv_bfloat162*)(Ch+o) = hp;
                        *(__nv_bfloat162*)(Cl+o) = lp;
                    } else { // transposed: XT[b][feat][node]
                        long base = (long)(gr>>9)*((long)RR*NN) + (gr&511);
                        long o0 = base + (long)c*NN;
                        Ch[o0]=h0; Cl[o0]=l0;
                        Ch[o0+NN]=h1; Cl[o0+NN]=l1;
                    }
                }
            }
        }
    }
}

// ---------------- FFMA split-K GEMM for small (B=64) matmuls ----------------
template<bool BT>
__global__ void __launch_bounds__(256) gemm_part(
    const float* __restrict__ A,int lda,
    const float* __restrict__ B,int ldb,
    float* __restrict__ C,int ldc,long partStride,int chunkK)
{
    __shared__ float As[16][64];
    __shared__ float Bs[16][64];
    const int tid = threadIdx.x;
    const int rowBase = blockIdx.y*64, colBase = blockIdx.x*64;
    const int kbeg = blockIdx.z*chunkK, kend = kbeg + chunkK;
    const int tx = tid & 15, ty = tid >> 4;
    float acc[4][4];
#pragma unroll
    for (int i=0;i<4;i++)
#pragma unroll
        for (int j=0;j<4;j++) acc[i][j]=0.f;

    for (int k0=kbeg;k0<kend;k0+=16){
#pragma unroll
        for (int i=tid*4;i<64*16;i+=256*4){
            int r=i>>4, kk=i&15;
            float4 v = *(const float4*)(A + (long)(rowBase+r)*lda + k0 + kk);
            As[kk+0][r]=v.x; As[kk+1][r]=v.y; As[kk+2][r]=v.z; As[kk+3][r]=v.w;
        }
        if (BT){
#pragma unroll
            for (int i=tid*4;i<64*16;i+=256*4){
                int r=i>>4, kk=i&15;
                float4 v = *(const float4*)(B + (long)(colBase+r)*ldb + k0 + kk);
                Bs[kk+0][r]=v.x; Bs[kk+1][r]=v.y; Bs[kk+2][r]=v.z; Bs[kk+3][r]=v.w;
            }
        } else {
#pragma unroll
            for (int i=tid*4;i<16*64;i+=256*4){
                int r=i>>6, cc=i&63;
                *(float4*)&Bs[r][cc] = *(const float4*)(B + (long)(k0+r)*ldb + colBase + cc);
            }
        }
        __syncthreads();
#pragma unroll
        for (int k=0;k<16;k++){
            float a[4], b[4];
            *(float4*)a = *(const float4*)&As[k][ty*4];
            *(float4*)b = *(const float4*)&Bs[k][tx*4];
#pragma unroll
            for (int i=0;i<4;i++)
#pragma unroll
                for (int j=0;j<4;j++) acc[i][j] = fmaf(a[i], b[j], acc[i][j]);
        }
        __syncthreads();
    }
    float* Cp = C + (long)blockIdx.z*partStride;
#pragma unroll
    for (int i=0;i<4;i++){
        int r = rowBase + ty*4 + i;
#pragma unroll
        for (int j=0;j<4;j++)
            Cp[(long)r*ldc + colBase + tx*4 + j] = acc[i][j];
    }
}
static void sgemm(bool BT,const float* A,int lda,const float* B,int ldb,float* Cpart,int ldc,
                  int M,int N,int K,int splits){
    dim3 g(N/64, M/64, splits);
    int chunkK = K/splits;
    if (BT) gemm_part<true ><<<g,256>>>(A,lda,B,ldb,Cpart,ldc,(long)M*ldc,chunkK);
    else    gemm_part<false><<<g,256>>>(A,lda,B,ldb,Cpart,ldc,(long)M*ldc,chunkK);
}
__global__ void reduce_kernel(float* dst,const float* src,long len,int splits,int colmask,
                              const float* b1,const float* b2){
    long i = (long)blockIdx.x*blockDim.x+threadIdx.x;
    if (i >= len) return;
    float s = 0.f;
    for (int z=0;z<splits;z++) s += src[z*len+i];
    int col = (int)(i & colmask);
    if (b1) s += b1[col];
    if (b2) s += b2[col];
    dst[i] = s;
}

// ---------------- conversions ----------------
__device__ __forceinline__ void split1(float v, __nv_bfloat16& h, __nv_bfloat16& l){
    h = __float2bfloat16(v);
    l = __float2bfloat16(v - __bfloat162float(h));
}

// fused: masked GE -> Ph/Pl (row-major) AND Th/Tl (transposed), single GE read
__global__ void geconv_kernel(const float* __restrict__ ge, const float* __restrict__ mask,
                              __nv_bfloat16* __restrict__ Ph, __nv_bfloat16* __restrict__ Pl,
                              __nv_bfloat16* __restrict__ Th, __nv_bfloat16* __restrict__ Tl){
    __shared__ float t[32][33];
    int b = blockIdx.z;
    int r0 = blockIdx.x*32, n0 = blockIdx.y*32;
    int tx = threadIdx.x, ty = threadIdx.y;
    for (int i=ty;i<32;i+=8){
        long o = ((long)b*NN + n0+i)*RR + r0+tx;
        float v = ge[o] * mask[b*NN + n0+i];
        t[i][tx] = v;
        __nv_bfloat16 h,l; split1(v,h,l);
        Ph[o]=h; Pl[o]=l;
    }
    __syncthreads();
    for (int i=ty;i<32;i+=8){
        float v = t[tx][i];   // GE[b][n0+tx][r0+i] masked
        __nv_bfloat16 h,l; split1(v,h,l);
        long o = ((long)b*RR + r0+i)*NN + n0+tx;
        Th[o]=h; Tl[o]=l;
    }
}

__global__ void conv_slice_kernel(const float* __restrict__ src, int ldsrc,
                                  __nv_bfloat16* __restrict__ dh, __nv_bfloat16* __restrict__ dl,
                                  int cols, int n4){
    int i = blockIdx.x*blockDim.x + threadIdx.x;
    if (i >= n4) return;
    int c4pr = cols/4;
    int r = i / c4pr, c4 = i % c4pr;
    float4 v = *(const float4*)(src + (long)r*ldsrc + c4*4);
    __align__(8) __nv_bfloat16 h[4], l[4];
    split1(v.x,h[0],l[0]); split1(v.y,h[1],l[1]); split1(v.z,h[2],l[2]); split1(v.w,h[3],l[3]);
    long o = (long)r*c4pr + c4;
    ((uint2*)dh)[o] = *(uint2*)h;
    ((uint2*)dl)[o] = *(uint2*)l;
}

// transpose+convert (weights): src [rows,cols] fp32 -> dst [cols,rows] bf16 hi/lo
__global__ void tconv_kernel(const float* __restrict__ src, int rows, int cols,
                             __nv_bfloat16* __restrict__ dh, __nv_bfloat16* __restrict__ dl){
    __shared__ float t[32][33];
    int r0 = blockIdx.y*32, c0 = blockIdx.x*32;
    int tx = threadIdx.x, ty = threadIdx.y;
    for (int i=ty;i<32;i+=8)
        t[i][tx] = src[(long)(r0+i)*cols + c0+tx];
    __syncthreads();
    for (int i=ty;i<32;i+=8){
        float v = t[tx][i];
        __nv_bfloat16 h, l; split1(v, h, l);
        long o = (long)(c0+i)*rows + r0+tx;
        dh[o] = h; dl[o] = l;
    }
}

// ---------------- pointwise / reductions ----------------
__device__ __forceinline__ float sigm(float x){ return 1.f/(1.f+__expf(-x)); }

__global__ void concat3_kernel(const float* a,const float* b,const float* c,float* out){
    int idx = blockIdx.x*blockDim.x+threadIdx.x;
    if (idx >= BB*3072) return;
    int bb = idx/3072, j = idx%3072;
    out[idx] = (j<1024) ? a[bb*1024+j] : (j<2048 ? b[bb*1024+j-1024] : c[bb*1024+j-2048]);
}
__global__ void concat2_kernel(const float* a,const float* b,float* out){
    int idx = blockIdx.x*blockDim.x+threadIdx.x;
    if (idx >= BB*2048) return;
    int bb = idx/2048, j = idx%2048;
    out[idx] = (j<1024) ? a[bb*1024+j] : b[bb*1024+j-1024];
}
__global__ void lstm_kernel(const float* gates,const float* c_prev,float* h_out,float* c_out){
    int idx = blockIdx.x*blockDim.x+threadIdx.x;
    if (idx >= BR) return;
    int bb = idx >> 10, r = idx & 1023;
    const float* g = gates + bb*4096;
    float c = sigm(g[1024+r])*c_prev[idx] + sigm(g[r])*tanhf(g[2048+r]);
    h_out[idx] = sigm(g[3072+r])*tanhf(c);
    c_out[idx] = c;
}
__global__ void batchmin_kernel(const float* Adj,float* minv){
    __shared__ float sm[1024];
    const float* a = Adj + (long)blockIdx.x*NN*NN;
    float mn = INFINITY;
    for (int i=threadIdx.x;i<NN*NN;i+=1024) mn = fminf(mn, a[i]);
    sm[threadIdx.x]=mn; __syncthreads();
    for (int s=512;s>0;s>>=1){ if (threadIdx.x<s) sm[threadIdx.x]=fminf(sm[threadIdx.x],sm[threadIdx.x+s]); __syncthreads(); }
    if (threadIdx.x==0) minv[blockIdx.x]=sm[0];
}
__global__ void __launch_bounds__(512) topk_kernel(float* Adj,const float* minv,
                                                   const float* mask,float* dvec){
    __shared__ unsigned long long keys[NN];
    __shared__ float red[NN];
    int row = blockIdx.x, t = threadIdx.x, bb = row >> 9;
    float mrow = mask[row];
    float* arow = Adj + (long)row*NN;
    float v = (arow[t] - minv[bb]) * mrow;
    keys[t] = ((unsigned long long)__float_as_uint(v) << 32) | (unsigned)(NN-1-t);
    __syncthreads();
    for (unsigned k2=2;k2<=NN;k2<<=1)
        for (unsigned j=k2>>1;j>0;j>>=1){
            unsigned ixj = t ^ j;
            if (ixj > (unsigned)t){
                unsigned long long x=keys[t], y=keys[ixj];
                bool desc = ((t & k2) == 0);
                if (desc ? (x<y) : (x>y)){ keys[t]=y; keys[ixj]=x; }
            }
            __syncthreads();
        }
    unsigned long long kk = keys[t];
    arow[t] = 0.f;
    __syncthreads();
    float s = 0.f;
    if (t < KTOP){
        int col = (NN-1) - (int)(unsigned)(kk & 0xffffffffu);
        float val = __uint_as_float((unsigned)(kk >> 32));
        arow[col] = val;
        s = val;
    }
    red[t]=s; __syncthreads();
    for (int st=NN/2;st>0;st>>=1){ if (t<st) red[t]+=red[t+st]; __syncthreads(); }
    if (t==0) dvec[row] = (red[0] > 0.f) ? rsqrtf(red[0]) : 0.f;
}
// fused: Adj *= d_r*d_c, split to bf16 hi/lo, and srow[r] = sum_c Adj_norm*mask_c
__global__ void rowfinal_kernel(const float* __restrict__ adj, const float* __restrict__ dvec,
                                const float* __restrict__ mask,
                                __nv_bfloat16* __restrict__ Ah, __nv_bfloat16* __restrict__ Al,
                                float* __restrict__ srow){
    int row = blockIdx.x*8 + (threadIdx.x>>5);
    int lane = threadIdx.x & 31;
    int bb = row >> 9;
    const float* a = adj + (long)row*NN;
    const float dr = dvec[row];
    const float* dc = dvec + (bb<<9);
    const float* m  = mask + (bb<<9);
    float s = 0.f;
    for (int k=lane*4; k<NN; k+=128){
        float4 v  = *(const float4*)(a+k);
        float4 d4 = *(const float4*)(dc+k);
        float4 m4 = *(const float4*)(m+k);
        float x0=v.x*dr*d4.x, x1=v.y*dr*d4.y, x2=v.z*dr*d4.z, x3=v.w*dr*d4.w;
        s += x0*m4.x + x1*m4.y + x2*m4.z + x3*m4.w;
        __align__(8) __nv_bfloat16 h[4], l[4];
        split1(x0,h[0],l[0]); split1(x1,h[1],l[1]); split1(x2,h[2],l[2]); split1(x3,h[3],l[3]);
        long o = ((long)row*NN + k) >> 2;
        ((uint2*)Ah)[o] = *(uint2*)h;
        ((uint2*)Al)[o] = *(uint2*)l;
    }
    for (int o=16;o;o>>=1) s += __shfl_xor_sync(0xffffffffu, s, o);
    if (lane==0) srow[row] = s;
}
__global__ void colmaxT_kernel(const __nv_bfloat16* Xh,const __nv_bfloat16* Xl,float* att){
    int warp = (blockIdx.x*blockDim.x+threadIdx.x) >> 5;
    int lane = threadIdx.x & 31;
    if (warp >= BB*RR) return;
    long base = (long)warp*NN;
    float mx = -INFINITY;
    for (int k=lane;k<NN;k+=32)
        mx = fmaxf(mx, __bfloat162float(Xh[base+k]) + __bfloat162float(Xl[base+k]));
    for (int o=16;o;o>>=1) mx = fmaxf(mx, __shfl_xor_sync(0xffffffffu, mx, o));
    if (lane==0) att[warp] = mx;
}
__global__ void pack_kernel(const float* hatt,const float* catt,
                            const float* hlang,const float* clang,float* out,int out_size){
    int i = blockIdx.x*blockDim.x+threadIdx.x;
    if (i >= BR) return;
    out[i] = hlang[i];
    if (out_size >= 5*BR){
        out[1*BR+i] = hatt[i];
        out[2*BR+i] = hlang[i];
        out[3*BR+i] = catt[i];
        out[4*BR+i] = clang[i];
    }
}

// ---------------- host driver ----------------
struct Ptrs {
    float *adj,*xcat,*gates,*gates2,*part,*ht1,*ht2,*pvec,*srow,*dvec,*minv,*attv,*xl,*hatt,*catt,*hlang,*clang;
    __nv_bfloat16 *Ph,*Pl,*Qh,*Ql,*Sh,*Sl,*Th,*Tl,*ADJh,*ADJl;
    __nv_bfloat16 *W1h,*W1l,*W2h,*W2l,*G0h,*G0l,*G1h,*G1l,*G2h,*G2l;
};
static Ptrs P;
static bool g_init = false;

extern "C" void kernel_launch(void* const* d_in, const int* in_sizes, int n_in,
                              void* d_out, int out_size)
{
    const float* xt   = (const float*)d_in[0];
    const float* fc   = (const float*)d_in[1];
    const float* ge   = (const float*)d_in[2];
    const float* sh   = (const float*)d_in[4];
    const float* sc   = (const float*)d_in[5];
    const float* mask = (const float*)d_in[6];
    const float* aWih = (const float*)d_in[7];
    const float* aWhh = (const float*)d_in[8];
    const float* abih = (const float*)d_in[9];
    const float* abhh = (const float*)d_in[10];
    const float* lWih = (const float*)d_in[11];
    const float* lWhh = (const float*)d_in[12];
    const float* lbih = (const float*)d_in[13];
    const float* lbhh = (const float*)d_in[14];
    const float* e1W  = (const float*)d_in[15];
    const float* e1b  = (const float*)d_in[16];
    const float* e2W  = (const float*)d_in[17];
    const float* e2b  = (const float*)d_in[18];
    const float* gW0  = (const float*)d_in[19];
    const float* gb0  = (const float*)d_in[20];
    const float* gW1  = (const float*)d_in[21];
    const float* gb1  = (const float*)d_in[22];
    const float* gW2  = (const float*)d_in[23];
    const float* gb2  = (const float*)d_in[24];
    (void)in_sizes; (void)n_in;
    float* out = (float*)d_out;

    if (!g_init){
        cudaGetSymbolAddress((void**)&P.adj,  g_adj);
        cudaGetSymbolAddress((void**)&P.xcat, g_xcat);
        cudaGetSymbolAddress((void**)&P.gates,g_gates);
        cudaGetSymbolAddress((void**)&P.gates2,g_gates2);
        cudaGetSymbolAddress((void**)&P.part, g_part);
        cudaGetSymbolAddress((void**)&P.ht1,  g_ht1);
        cudaGetSymbolAddress((void**)&P.ht2,  g_ht2);
        cudaGetSymbolAddress((void**)&P.pvec, g_pvec);
        cudaGetSymbolAddress((void**)&P.srow, g_srow);
        cudaGetSymbolAddress((void**)&P.dvec, g_dvec);
        cudaGetSymbolAddress((void**)&P.minv, g_minv);
        cudaGetSymbolAddress((void**)&P.attv, g_attv);
        cudaGetSymbolAddress((void**)&P.xl,   g_xl);
        cudaGetSymbolAddress((void**)&P.hatt, g_hatt);
        cudaGetSymbolAddress((void**)&P.catt, g_catt);
        cudaGetSymbolAddress((void**)&P.hlang,g_hlang);
        cudaGetSymbolAddress((void**)&P.clang,g_clang);
        cudaGetSymbolAddress((void**)&P.Ph, g_Ph); cudaGetSymbolAddress((void**)&P.Pl, g_Pl);
        cudaGetSymbolAddress((void**)&P.Qh, g_Qh); cudaGetSymbolAddress((void**)&P.Ql, g_Ql);
        cudaGetSymbolAddress((void**)&P.Sh, g_Sh); cudaGetSymbolAddress((void**)&P.Sl, g_Sl);
        cudaGetSymbolAddress((void**)&P.Th, g_Th); cudaGetSymbolAddress((void**)&P.Tl, g_Tl);
        cudaGetSymbolAddress((void**)&P.ADJh, g_ADJh); cudaGetSymbolAddress((void**)&P.ADJl, g_ADJl);
        cudaGetSymbolAddress((void**)&P.W1h, g_W1h); cudaGetSymbolAddress((void**)&P.W1l, g_W1l);
        cudaGetSymbolAddress((void**)&P.W2h, g_W2h); cudaGetSymbolAddress((void**)&P.W2l, g_W2l);
        cudaGetSymbolAddress((void**)&P.G0h, g_G0h); cudaGetSymbolAddress((void**)&P.G0l, g_G0l);
        cudaGetSymbolAddress((void**)&P.G1h, g_G1h); cudaGetSymbolAddress((void**)&P.G1l, g_G1l);
        cudaGetSymbolAddress((void**)&P.G2h, g_G2h); cudaGetSymbolAddress((void**)&P.G2l, g_G2l);
        cudaFuncSetAttribute(hmma_gemm, cudaFuncAttributeMaxDynamicSharedMemorySize, MMA_SMEM);
        g_init = true;
    }

    const float* prev_h = sh + BR;
    const float* h0 = sh;
    const float* c0 = sc;
    const float* c1 = sc + BR;

    // ---- conversions (GE fused normal+transpose, weights) ----
    geconv_kernel<<<dim3(RR/32, NN/32, BB), dim3(32,8)>>>(ge, mask, P.Ph, P.Pl, P.Th, P.Tl);
    conv_slice_kernel<<<(1048576/4+255)/256,256>>>(e1W, 2048, P.W1h, P.W1l, 1024, 1048576/4);
    conv_slice_kernel<<<(1048576/4+255)/256,256>>>(e2W, 2048, P.W2h, P.W2l, 1024, 1048576/4);
    tconv_kernel<<<dim3(32,32),dim3(32,8)>>>(gW0, 1024, 1024, P.G0h, P.G0l);
    tconv_kernel<<<dim3(32,32),dim3(32,8)>>>(gW1, 1024, 1024, P.G1h, P.G1l);
    tconv_kernel<<<dim3(32,32),dim3(32,8)>>>(gW2, 1024, 1024, P.G2h, P.G2l);

    // ---- attention LSTM (split-K FFMA) ----
    concat3_kernel<<<(BB*3072+255)/256,256>>>(prev_h, fc, xt, P.xcat);
    sgemm(true, P.xcat,3072, aWih,3072, P.part,            4096, BB,4096,3072, 3);
    sgemm(true, h0,1024,     aWhh,1024, P.part+3*BB*4096,  4096, BB,4096,1024, 1);
    reduce_kernel<<<(BB*4096+255)/256,256>>>(P.gates, P.part, BB*4096, 4, 4095, abih, abhh);
    lstm_kernel<<<(BR+255)/256,256>>>(P.gates, c0, P.hatt, P.catt);

    // ---- h-terms (split-K FFMA) ----
    sgemm(true, P.hatt,1024, e1W+1024,2048, P.part, 1024, BB,1024,1024, 4);
    reduce_kernel<<<(BB*1024+255)/256,256>>>(P.ht1, P.part, BB*1024, 4, 1023, nullptr, nullptr);
    sgemm(true, P.hatt,1024, e2W+1024,2048, P.part, 1024, BB,1024,1024, 4);
    reduce_kernel<<<(BB*1024+255)/256,256>>>(P.ht2, P.part, BB*1024, 4, 1023, nullptr, nullptr);
    sgemm(false, prev_h,1024, gW0+1024*1024,1024, P.part, 1024, BB,1024,1024, 4);
    reduce_kernel<<<(BB*1024+255)/256,256>>>(P.pvec, P.part, BB*1024, 4, 1023, nullptr, nullptr);

    // ---- E1/E2 (tensor core) ----
    hmma_gemm<<<dim3(8,256,1),256,MMA_SMEM>>>(P.Ph,P.Pl,1024,0, P.W1h,P.W1l,1024,0,
        1024, 0, 1, 0, nullptr,0, P.Qh,P.Ql,1024, e1b, P.ht1, mask, nullptr);
    hmma_gemm<<<dim3(8,256,1),256,MMA_SMEM>>>(P.Ph,P.Pl,1024,0, P.W2h,P.W2l,1024,0,
        1024, 0, 1, 0, nullptr,0, P.Sh,P.Sl,1024, e2b, P.ht2, mask, nullptr);

    // ---- Adj = E1 @ E2^T ----
    hmma_gemm<<<dim3(4,4,64),256,MMA_SMEM>>>(P.Qh,P.Ql,1024,(long)NN*RR, P.Sh,P.Sl,1024,(long)NN*RR,
        1024, 512, 0, 0, P.adj,512, nullptr,nullptr,0, nullptr,nullptr,nullptr,nullptr);

    // ---- Adj post-processing ----
    batchmin_kernel<<<BB,1024>>>(P.adj, P.minv);
    topk_kernel<<<BB*NN,512>>>(P.adj, P.minv, mask, P.dvec);
    rowfinal_kernel<<<BB*NN/8,256>>>(P.adj, P.dvec, mask, P.ADJh, P.ADJl, P.srow);

    // ---- GCN layer 0 ----
    hmma_gemm<<<dim3(8,4,64),256,MMA_SMEM>>>(P.ADJh,P.ADJl,512,(long)NN*NN, P.Th,P.Tl,512,(long)RR*NN,
        512, 512, 1, 0, nullptr,0, P.Qh,P.Ql,1024, nullptr,nullptr,nullptr,nullptr);
    hmma_gemm<<<dim3(8,256,1),256,MMA_SMEM>>>(P.Qh,P.Ql,1024,0, P.G0h,P.G0l,1024,0,
        1024, 0, 2, 1, nullptr,0, P.Sh,P.Sl,0, gb0, P.pvec, P.srow, mask);

    // ---- GCN layer 1 ----
    hmma_gemm<<<dim3(8,4,64),256,MMA_SMEM>>>(P.ADJh,P.ADJl,512,(long)NN*NN, P.Sh,P.Sl,512,(long)RR*NN,
        512, 512, 1, 0, nullptr,0, P.Qh,P.Ql,1024, nullptr,nullptr,nullptr,nullptr);
    hmma_gemm<<<dim3(8,256,1),256,MMA_SMEM>>>(P.Qh,P.Ql,1024,0, P.G1h,P.G1l,1024,0,
        1024, 0, 2, 1, nullptr,0, P.Ph,P.Pl,0, gb1, nullptr, nullptr, mask);

    // ---- GCN layer 2 ----
    hmma_gemm<<<dim3(8,4,64),256,MMA_SMEM>>>(P.ADJh,P.ADJl,512,(long)NN*NN, P.Ph,P.Pl,512,(long)RR*NN,
        512, 512, 1, 0, nullptr,0, P.Qh,P.Ql,1024, nullptr,nullptr,nullptr,nullptr);
    hmma_gemm<<<dim3(8,256,1),256,MMA_SMEM>>>(P.Qh,P.Ql,1024,0, P.G2h,P.G2l,1024,0,
        1024, 0, 2, 1, nullptr,0, P.Sh,P.Sl,0, gb2, nullptr, nullptr, mask);

    // ---- att = max over nodes (XT contiguous) ----
    colmaxT_kernel<<<(BB*RR*32+255)/256,256>>>(P.Sh, P.Sl, P.attv);

    // ---- language LSTM (split-K FFMA) ----
    concat2_kernel<<<(BB*2048+255)/256,256>>>(P.attv, P.hatt, P.xl);
    sgemm(true, P.xl,2048,   lWih,2048, P.part,           4096, BB,4096,2048, 2);
    sgemm(true, prev_h,1024, lWhh,1024, P.part+2*BB*4096, 4096, BB,4096,1024, 1);
    reduce_kernel<<<(BB*4096+255)/256,256>>>(P.gates2, P.part, BB*4096, 3, 4095, lbih, lbhh);
    lstm_kernel<<<(BR+255)/256,256>>>(P.gates2, c1, P.hlang, P.clang);

    pack_kernel<<<(BR+255)/256,256>>>(P.hatt, P.catt, P.hlang, P.clang, out, out_size);
}

// round 8
// speedup vs baseline: 2.9204x; 1.0341x over previous
#include <cuda_runtime.h>
#include <cuda_bf16.h>
#include <math.h>
#include <stdint.h>

#define BB 64
#define NN 512
#define RR 1024
#define KTOP 256
#define BR (BB*RR)
#define NGE ((long)BB*NN*RR)

// ---------------- device scratch ----------------
__device__ float g_adj[(long)BB*NN*NN];
__device__ float g_xcat[BB*3072];
__device__ float g_gates[BB*4096];
__device__ float g_gates2[BB*4096];
__device__ float g_part[4*BB*4096];
__device__ float g_ht1[BB*RR];
__device__ float g_ht2[BB*RR];
__device__ float g_pvec[BB*RR];
__device__ float g_srow[BB*NN];
__device__ float g_dvec[BB*NN];
__device__ float g_minv[BB];
__device__ float g_attv[BB*RR];
__device__ float g_xl[BB*2048];
__device__ float g_hatt[BR];
__device__ float g_catt[BR];
__device__ float g_hlang[BR];
__device__ float g_clang[BR];

__device__ __nv_bfloat16 g_Ph[NGE], g_Pl[NGE];   // masked GE, later X2^T
__device__ __nv_bfloat16 g_Qh[NGE], g_Ql[NGE];   // E1, later Y
__device__ __nv_bfloat16 g_Sh[NGE], g_Sl[NGE];   // E2, later X1^T / X3^T
__device__ __nv_bfloat16 g_Th[NGE], g_Tl[NGE];   // GE^T (masked)
__device__ __nv_bfloat16 g_ADJh[(long)BB*NN*NN], g_ADJl[(long)BB*NN*NN];
__device__ __nv_bfloat16 g_W1h[1048576], g_W1l[1048576];
__device__ __nv_bfloat16 g_W2h[1048576], g_W2l[1048576];
__device__ __nv_bfloat16 g_G0h[1048576], g_G0l[1048576];
__device__ __nv_bfloat16 g_G1h[1048576], g_G1l[1048576];
__device__ __nv_bfloat16 g_G2h[1048576], g_G2l[1048576];

// ---------------- warp MMA helpers ----------------
__device__ __forceinline__ uint32_t smem_u32(const void* p){
    uint32_t a;
    asm("{ .reg .u64 t; cvta.to.shared.u64 t, %1; cvt.u32.u64 %0, t; }" : "=r"(a) : "l"(p));
    return a;
}
__device__ __forceinline__ uint32_t swz64(uint32_t x){ return x ^ ((x>>3)&0x30u); }
__device__ __forceinline__ void ldm4(uint32_t* r, uint32_t addr){
    asm volatile("ldmatrix.sync.aligned.m8n8.x4.shared.b16 {%0,%1,%2,%3}, [%4];"
        : "=r"(r[0]),"=r"(r[1]),"=r"(r[2]),"=r"(r[3]) : "r"(addr));
}
__device__ __forceinline__ void mma16816(float* d, const uint32_t* a, const uint32_t* b){
    asm volatile("mma.sync.aligned.m16n8k16.row.col.f32.bf16.bf16.f32 "
        "{%0,%1,%2,%3}, {%4,%5,%6,%7}, {%8,%9}, {%0,%1,%2,%3};"
        : "+f"(d[0]),"+f"(d[1]),"+f"(d[2]),"+f"(d[3])
        : "r"(a[0]),"r"(a[1]),"r"(a[2]),"r"(a[3]), "r"(b[0]),"r"(b[1]));
}
__device__ __forceinline__ void cpasync16(uint32_t dst, const void* src){
    asm volatile("cp.async.cg.shared.global [%0], [%1], 16;" :: "r"(dst), "l"(src));
}

// ---------------- bf16 hi/lo tensor-core GEMM, 3-stage cp.async ----------------
// C[128x128 tile] = (Ah+Al)[M,K] @ (Bh+Bl)[N,K]^T, K-major, fp32 accum.
// 128 threads = 4 warps (2x2), warp tile 64x64. BK=32, 3 stages x 32KB, 2 CTA/SM.
#define MMA_SMEM (3*32768+1024)

__global__ void __launch_bounds__(128,2) hmma_gemm(
    const __nv_bfloat16* __restrict__ Ah, const __nv_bfloat16* __restrict__ Al, int lda, long sA,
    const __nv_bfloat16* __restrict__ Bh, const __nv_bfloat16* __restrict__ Bl, int ldb, long sB,
    int K, int rowsPerZ, int outMode, int relu,
    float* Cf, int ldc,
    __nv_bfloat16* Ch, __nv_bfloat16* Cl, int ldch,
    const float* __restrict__ bias, const float* __restrict__ addv,
    const float* __restrict__ rs, const float* __restrict__ ps)
{
    extern __shared__ char smraw[];
    uint32_t sb0 = smem_u32(smraw);
    uint32_t sb  = (sb0 + 1023u) & ~1023u;
    const int tid = threadIdx.x, wid = tid>>5, lane = tid&31;

    const __nv_bfloat16* A0 = Ah + blockIdx.z*sA;
    const __nv_bfloat16* A1 = Al + blockIdx.z*sA;
    const __nv_bfloat16* B0 = Bh + blockIdx.z*sB;
    const __nv_bfloat16* B1 = Bl + blockIdx.z*sB;
    const int rowBase = blockIdx.y*128, colBase = blockIdx.x*128;
    const int NC = K >> 5;

    const int wr = wid>>1, wc = wid&1;     // warp tile 64x64
    const int lr = lane&7, q = lane>>3;
    const int aRowOff = ((q&1)<<3) + lr;
    const int aKbOff  = (q>>1)<<4;
    const int bRowOff = ((q>>1)<<3) + lr;
    const int bKbOff  = (q&1)<<4;

    const int cp_row = tid>>2;   // 0..31
    const int cp_u   = tid&3;

    float acc[4][8][4];
    #pragma unroll
    for (int a=0;a<4;a++)
        #pragma unroll
        for (int b=0;b<8;b++)
            #pragma unroll
            for (int c=0;c<4;c++) acc[a][b][c]=0.f;

    auto load_chunk = [&](int ci, int s){
        const int k0 = ci<<5;
        const uint32_t st = sb + s*32768;
        #pragma unroll
        for (int j=0;j<4;j++){
            int r = cp_row + j*32;
            uint32_t doff = swz64((uint32_t)(r*64 + cp_u*16));
            long aoff = (long)(rowBase+r)*lda + k0 + cp_u*8;
            long boff = (long)(colBase+r)*ldb + k0 + cp_u*8;
            cpasync16(st +         doff, A0 + aoff);
            cpasync16(st +  8192 + doff, A1 + aoff);
            cpasync16(st + 16384 + doff, B0 + boff);
            cpasync16(st + 24576 + doff, B1 + boff);
        }
        asm volatile("cp.async.commit_group;" ::: "memory");
    };

    load_chunk(0, 0);
    if (NC > 1) load_chunk(1, 1);

    int sidx = 0;
    int nidx = (NC > 2) ? 2 : 0;
    for (int i=0;i<NC;i++){
        if (i+1 < NC) asm volatile("cp.async.wait_group 1;" ::: "memory");
        else          asm volatile("cp.async.wait_group 0;" ::: "memory");
        __syncthreads();
        if (i+2 < NC){
            load_chunk(i+2, nidx);
            nidx = (nidx==2)?0:nidx+1;
        }
        const uint32_t st = sb + sidx*32768;
        sidx = (sidx==2)?0:sidx+1;
        #pragma unroll
        for (int ks=0;ks<2;ks++){
            const uint32_t kb = ks<<5;
            uint32_t bh[4][4], bl[4][4], af[4][4];
            #pragma unroll
            for (int t=0;t<4;t++){
                uint32_t ro = (uint32_t)((wc*64 + t*16 + bRowOff)*64) + kb + bKbOff;
                ldm4(bh[t], st + 16384 + swz64(ro));
                ldm4(bl[t], st + 24576 + swz64(ro));
            }
            #pragma unroll
            for (int mi=0;mi<4;mi++){
                uint32_t ro = (uint32_t)((wr*64 + mi*16 + aRowOff)*64) + kb + aKbOff;
                ldm4(af[mi], st + swz64(ro));
            }
            // pass 1: Ah * Bh
            #pragma unroll
            for (int mi=0;mi<4;mi++)
                #pragma unroll
                for (int t=0;t<4;t++){
                    mma16816(acc[mi][2*t],   af[mi], &bh[t][0]);
                    mma16816(acc[mi][2*t+1], af[mi], &bh[t][2]);
                }
            // pass 2: Ah * Bl
            #pragma unroll
            for (int mi=0;mi<4;mi++)
                #pragma unroll
                for (int t=0;t<4;t++){
                    mma16816(acc[mi][2*t],   af[mi], &bl[t][0]);
                    mma16816(acc[mi][2*t+1], af[mi], &bl[t][2]);
                }
            // reload A-lo over af, pass 3: Al * Bh
            #pragma unroll
            for (int mi=0;mi<4;mi++){
                uint32_t ro = (uint32_t)((wr*64 + mi*16 + aRowOff)*64) + kb + aKbOff;
                ldm4(af[mi], st + 8192 + swz64(ro));
            }
            #pragma unroll
            for (int mi=0;mi<4;mi++)
                #pragma unroll
                for (int t=0;t<4;t++){
                    mma16816(acc[mi][2*t],   af[mi], &bh[t][0]);
                    mma16816(acc[mi][2*t+1], af[mi], &bh[t][2]);
                }
        }
    }

    // ---- epilogue ----
    const int cpair = (lane&3)*2;
    #pragma unroll
    for (int mi=0;mi<4;mi++){
        #pragma unroll
        for (int rr=0;rr<2;rr++){
            const int r  = rowBase + wr*64 + mi*16 + (lane>>2) + rr*8;
            const int gr = blockIdx.z*rowsPerZ + r;
            const float rsv = rs ? rs[gr] : 1.f;
            const float psv = ps ? ps[gr] : 1.f;
            const float* avp = addv ? addv + (long)(gr>>9)*RR : nullptr;
            #pragma unroll
            for (int ni=0;ni<8;ni++){
                const int c = colBase + wc*64 + ni*8 + cpair;
                float x0 = acc[mi][ni][rr*2+0];
                float x1 = acc[mi][ni][rr*2+1];
                if (avp){ x0 += rsv*avp[c]; x1 += rsv*avp[c+1]; }
                if (bias){ x0 += bias[c]; x1 += bias[c+1]; }
                if (relu){ x0 = fmaxf(x0,0.f); x1 = fmaxf(x1,0.f); }
                x0 *= psv; x1 *= psv;
                if (outMode==0){
                    *(float2*)(Cf + (long)gr*ldc + c) = make_float2(x0,x1);
                } else {
                    __nv_bfloat16 h0 = __float2bfloat16(x0);
                    __nv_bfloat16 l0 = __float2bfloat16(x0-__bfloat162float(h0));
                    __nv_bfloat16 h1 = __float2bfloat16(x1);
                    __nv_bfloat16 l1 = __float2bfloat16(x1-__bfloat162float(h1));
                    if (outMode==1){
                        long o = (long)gr*ldch + c;
                        __nv_bfloat162 hp; hp.x=h0; hp.y=h1;
                        __nv_bfloat162 lp; lp.x=l0; lp.y=l1;
                        *(__nv_bfloat162*)(Ch+o) = hp;
                        *(__nv_bfloat162*)(Cl+o) = lp;
                    } else { // transposed: XT[b][feat][node]
                        long base = (long)(gr>>9)*((long)RR*NN) + (gr&511);
                        long o0 = base + (long)c*NN;
                        Ch[o0]=h0; Cl[o0]=l0;
                        Ch[o0+NN]=h1; Cl[o0+NN]=l1;
                    }
                }
            }
        }
    }
}

// ---------------- FFMA split-K GEMM for small (B=64) matmuls ----------------
template<bool BT>
__global__ void __launch_bounds__(256) gemm_part(
    const float* __restrict__ A,int lda,
    const float* __restrict__ B,int ldb,
    float* __restrict__ C,int ldc,long partStride,int chunkK)
{
    __shared__ float As[16][64];
    __shared__ float Bs[16][64];
    const int tid = threadIdx.x;
    const int rowBase = blockIdx.y*64, colBase = blockIdx.x*64;
    const int kbeg = blockIdx.z*chunkK, kend = kbeg + chunkK;
    const int tx = tid & 15, ty = tid >> 4;
    float acc[4][4];
#pragma unroll
    for (int i=0;i<4;i++)
#pragma unroll
        for (int j=0;j<4;j++) acc[i][j]=0.f;

    for (int k0=kbeg;k0<kend;k0+=16){
#pragma unroll
        for (int i=tid*4;i<64*16;i+=256*4){
            int r=i>>4, kk=i&15;
            float4 v = *(const float4*)(A + (long)(rowBase+r)*lda + k0 + kk);
            As[kk+0][r]=v.x; As[kk+1][r]=v.y; As[kk+2][r]=v.z; As[kk+3][r]=v.w;
        }
        if (BT){
#pragma unroll
            for (int i=tid*4;i<64*16;i+=256*4){
                int r=i>>4, kk=i&15;
                float4 v = *(const float4*)(B + (long)(colBase+r)*ldb + k0 + kk);
                Bs[kk+0][r]=v.x; Bs[kk+1][r]=v.y; Bs[kk+2][r]=v.z; Bs[kk+3][r]=v.w;
            }
        } else {
#pragma unroll
            for (int i=tid*4;i<16*64;i+=256*4){
                int r=i>>6, cc=i&63;
                *(float4*)&Bs[r][cc] = *(const float4*)(B + (long)(k0+r)*ldb + colBase + cc);
            }
        }
        __syncthreads();
#pragma unroll
        for (int k=0;k<16;k++){
            float a[4], b[4];
            *(float4*)a = *(const float4*)&As[k][ty*4];
            *(float4*)b = *(const float4*)&Bs[k][tx*4];
#pragma unroll
            for (int i=0;i<4;i++)
#pragma unroll
                for (int j=0;j<4;j++) acc[i][j] = fmaf(a[i], b[j], acc[i][j]);
        }
        __syncthreads();
    }
    float* Cp = C + (long)blockIdx.z*partStride;
#pragma unroll
    for (int i=0;i<4;i++){
        int r = rowBase + ty*4 + i;
#pragma unroll
        for (int j=0;j<4;j++)
            Cp[(long)r*ldc + colBase + tx*4 + j] = acc[i][j];
    }
}
static void sgemm(bool BT,const float* A,int lda,const float* B,int ldb,float* Cpart,int ldc,
                  int M,int N,int K,int splits){
    dim3 g(N/64, M/64, splits);
    int chunkK = K/splits;
    if (BT) gemm_part<true ><<<g,256>>>(A,lda,B,ldb,Cpart,ldc,(long)M*ldc,chunkK);
    else    gemm_part<false><<<g,256>>>(A,lda,B,ldb,Cpart,ldc,(long)M*ldc,chunkK);
}
__global__ void reduce_kernel(float* dst,const float* src,long len,int splits,int colmask,
                              const float* b1,const float* b2){
    long i = (long)blockIdx.x*blockDim.x+threadIdx.x;
    if (i >= len) return;
    float s = 0.f;
    for (int z=0;z<splits;z++) s += src[z*len+i];
    int col = (int)(i & colmask);
    if (b1) s += b1[col];
    if (b2) s += b2[col];
    dst[i] = s;
}

// ---------------- conversions ----------------
__device__ __forceinline__ void split1(float v, __nv_bfloat16& h, __nv_bfloat16& l){
    h = __float2bfloat16(v);
    l = __float2bfloat16(v - __bfloat162float(h));
}

// fused: masked GE -> Ph/Pl (row-major) AND Th/Tl (transposed), single GE read
__global__ void geconv_kernel(const float* __restrict__ ge, const float* __restrict__ mask,
                              __nv_bfloat16* __restrict__ Ph, __nv_bfloat16* __restrict__ Pl,
                              __nv_bfloat16* __restrict__ Th, __nv_bfloat16* __restrict__ Tl){
    __shared__ float t[32][33];
    int b = blockIdx.z;
    int r0 = blockIdx.x*32, n0 = blockIdx.y*32;
    int tx = threadIdx.x, ty = threadIdx.y;
    for (int i=ty;i<32;i+=8){
        long o = ((long)b*NN + n0+i)*RR + r0+tx;
        float v = ge[o] * mask[b*NN + n0+i];
        t[i][tx] = v;
        __nv_bfloat16 h,l; split1(v,h,l);
        Ph[o]=h; Pl[o]=l;
    }
    __syncthreads();
    for (int i=ty;i<32;i+=8){
        float v = t[tx][i];
        __nv_bfloat16 h,l; split1(v,h,l);
        long o = ((long)b*RR + r0+i)*NN + n0+tx;
        Th[o]=h; Tl[o]=l;
    }
}

__global__ void conv_slice_kernel(const float* __restrict__ src, int ldsrc,
                                  __nv_bfloat16* __restrict__ dh, __nv_bfloat16* __restrict__ dl,
                                  int cols, int n4){
    int i = blockIdx.x*blockDim.x + threadIdx.x;
    if (i >= n4) return;
    int c4pr = cols/4;
    int r = i / c4pr, c4 = i % c4pr;
    float4 v = *(const float4*)(src + (long)r*ldsrc + c4*4);
    __align__(8) __nv_bfloat16 h[4], l[4];
    split1(v.x,h[0],l[0]); split1(v.y,h[1],l[1]); split1(v.z,h[2],l[2]); split1(v.w,h[3],l[3]);
    long o = (long)r*c4pr + c4;
    ((uint2*)dh)[o] = *(uint2*)h;
    ((uint2*)dl)[o] = *(uint2*)l;
}

// transpose+convert (weights): src [rows,cols] fp32 -> dst [cols,rows] bf16 hi/lo
__global__ void tconv_kernel(const float* __restrict__ src, int rows, int cols,
                             __nv_bfloat16* __restrict__ dh, __nv_bfloat16* __restrict__ dl){
    __shared__ float t[32][33];
    int r0 = blockIdx.y*32, c0 = blockIdx.x*32;
    int tx = threadIdx.x, ty = threadIdx.y;
    for (int i=ty;i<32;i+=8)
        t[i][tx] = src[(long)(r0+i)*cols + c0+tx];
    __syncthreads();
    for (int i=ty;i<32;i+=8){
        float v = t[tx][i];
        __nv_bfloat16 h, l; split1(v, h, l);
        long o = (long)(c0+i)*rows + r0+tx;
        dh[o] = h; dl[o] = l;
    }
}

// ---------------- pointwise / reductions ----------------
__device__ __forceinline__ float sigm(float x){ return 1.f/(1.f+__expf(-x)); }

__global__ void concat3_kernel(const float* a,const float* b,const float* c,float* out){
    int idx = blockIdx.x*blockDim.x+threadIdx.x;
    if (idx >= BB*3072) return;
    int bb = idx/3072, j = idx%3072;
    out[idx] = (j<1024) ? a[bb*1024+j] : (j<2048 ? b[bb*1024+j-1024] : c[bb*1024+j-2048]);
}
__global__ void concat2_kernel(const float* a,const float* b,float* out){
    int idx = blockIdx.x*blockDim.x+threadIdx.x;
    if (idx >= BB*2048) return;
    int bb = idx/2048, j = idx%2048;
    out[idx] = (j<1024) ? a[bb*1024+j] : b[bb*1024+j-1024];
}
__global__ void lstm_kernel(const float* gates,const float* c_prev,float* h_out,float* c_out){
    int idx = blockIdx.x*blockDim.x+threadIdx.x;
    if (idx >= BR) return;
    int bb = idx >> 10, r = idx & 1023;
    const float* g = gates + bb*4096;
    float c = sigm(g[1024+r])*c_prev[idx] + sigm(g[r])*tanhf(g[2048+r]);
    h_out[idx] = sigm(g[3072+r])*tanhf(c);
    c_out[idx] = c;
}
__global__ void batchmin_kernel(const float* Adj,float* minv){
    __shared__ float sm[1024];
    const float* a = Adj + (long)blockIdx.x*NN*NN;
    float mn = INFINITY;
    for (int i=threadIdx.x;i<NN*NN;i+=1024) mn = fminf(mn, a[i]);
    sm[threadIdx.x]=mn; __syncthreads();
    for (int s=512;s>0;s>>=1){ if (threadIdx.x<s) sm[threadIdx.x]=fminf(sm[threadIdx.x],sm[threadIdx.x+s]); __syncthreads(); }
    if (threadIdx.x==0) minv[blockIdx.x]=sm[0];
}
__global__ void __launch_bounds__(512) topk_kernel(float* Adj,const float* minv,
                                                   const float* mask,float* dvec){
    __shared__ unsigned long long keys[NN];
    __shared__ float red[NN];
    int row = blockIdx.x, t = threadIdx.x, bb = row >> 9;
    float mrow = mask[row];
    float* arow = Adj + (long)row*NN;
    float v = (arow[t] - minv[bb]) * mrow;
    keys[t] = ((unsigned long long)__float_as_uint(v) << 32) | (unsigned)(NN-1-t);
    __syncthreads();
    for (unsigned k2=2;k2<=NN;k2<<=1)
        for (unsigned j=k2>>1;j>0;j>>=1){
            unsigned ixj = t ^ j;
            if (ixj > (unsigned)t){
                unsigned long long x=keys[t], y=keys[ixj];
                bool desc = ((t & k2) == 0);
                if (desc ? (x<y) : (x>y)){ keys[t]=y; keys[ixj]=x; }
            }
            __syncthreads();
        }
    unsigned long long kk = keys[t];
    arow[t] = 0.f;
    __syncthreads();
    float s = 0.f;
    if (t < KTOP){
        int col = (NN-1) - (int)(unsigned)(kk & 0xffffffffu);
        float val = __uint_as_float((unsigned)(kk >> 32));
        arow[col] = val;
        s = val;
    }
    red[t]=s; __syncthreads();
    for (int st=NN/2;st>0;st>>=1){ if (t<st) red[t]+=red[t+st]; __syncthreads(); }
    if (t==0) dvec[row] = (red[0] > 0.f) ? rsqrtf(red[0]) : 0.f;
}
// fused: Adj *= d_r*d_c, split to bf16 hi/lo, and srow[r] = sum_c Adj_norm*mask_c
__global__ void rowfinal_kernel(const float* __restrict__ adj, const float* __restrict__ dvec,
                                const float* __restrict__ mask,
                                __nv_bfloat16* __restrict__ Ah, __nv_bfloat16* __restrict__ Al,
                                float* __restrict__ srow){
    int row = blockIdx.x*8 + (threadIdx.x>>5);
    int lane = threadIdx.x & 31;
    int bb = row >> 9;
    const float* a = adj + (long)row*NN;
    const float dr = dvec[row];
    const float* dc = dvec + (bb<<9);
    const float* m  = mask + (bb<<9);
    float s = 0.f;
    for (int k=lane*4; k<NN; k+=128){
        float4 v  = *(const float4*)(a+k);
        float4 d4 = *(const float4*)(dc+k);
        float4 m4 = *(const float4*)(m+k);
        float x0=v.x*dr*d4.x, x1=v.y*dr*d4.y, x2=v.z*dr*d4.z, x3=v.w*dr*d4.w;
        s += x0*m4.x + x1*m4.y + x2*m4.z + x3*m4.w;
        __align__(8) __nv_bfloat16 h[4], l[4];
        split1(x0,h[0],l[0]); split1(x1,h[1],l[1]); split1(x2,h[2],l[2]); split1(x3,h[3],l[3]);
        long o = ((long)row*NN + k) >> 2;
        ((uint2*)Ah)[o] = *(uint2*)h;
        ((uint2*)Al)[o] = *(uint2*)l;
    }
    for (int o=16;o;o>>=1) s += __shfl_xor_sync(0xffffffffu, s, o);
    if (lane==0) srow[row] = s;
}
__global__ void colmaxT_kernel(const __nv_bfloat16* Xh,const __nv_bfloat16* Xl,float* att){
    int warp = (blockIdx.x*blockDim.x+threadIdx.x) >> 5;
    int lane = threadIdx.x & 31;
    if (warp >= BB*RR) return;
    long base = (long)warp*NN;
    float mx = -INFINITY;
    for (int k=lane;k<NN;k+=32)
        mx = fmaxf(mx, __bfloat162float(Xh[base+k]) + __bfloat162float(Xl[base+k]));
    for (int o=16;o;o>>=1) mx = fmaxf(mx, __shfl_xor_sync(0xffffffffu, mx, o));
    if (lane==0) att[warp] = mx;
}
__global__ void pack_kernel(const float* hatt,const float* catt,
                            const float* hlang,const float* clang,float* out,int out_size){
    int i = blockIdx.x*blockDim.x+threadIdx.x;
    if (i >= BR) return;
    out[i] = hlang[i];
    if (out_size >= 5*BR){
        out[1*BR+i] = hatt[i];
        out[2*BR+i] = hlang[i];
        out[3*BR+i] = catt[i];
        out[4*BR+i] = clang[i];
    }
}

// ---------------- host driver ----------------
struct Ptrs {
    float *adj,*xcat,*gates,*gates2,*part,*ht1,*ht2,*pvec,*srow,*dvec,*minv,*attv,*xl,*hatt,*catt,*hlang,*clang;
    __nv_bfloat16 *Ph,*Pl,*Qh,*Ql,*Sh,*Sl,*Th,*Tl,*ADJh,*ADJl;
    __nv_bfloat16 *W1h,*W1l,*W2h,*W2l,*G0h,*G0l,*G1h,*G1l,*G2h,*G2l;
};
static Ptrs P;
static bool g_init = false;

extern "C" void kernel_launch(void* const* d_in, const int* in_sizes, int n_in,
                              void* d_out, int out_size)
{
    const float* xt   = (const float*)d_in[0];
    const float* fc   = (const float*)d_in[1];
    const float* ge   = (const float*)d_in[2];
    const float* sh   = (const float*)d_in[4];
    const float* sc   = (const float*)d_in[5];
    const float* mask = (const float*)d_in[6];
    const float* aWih = (const float*)d_in[7];
    const float* aWhh = (const float*)d_in[8];
    const float* abih = (const float*)d_in[9];
    const float* abhh = (const float*)d_in[10];
    const float* lWih = (const float*)d_in[11];
    const float* lWhh = (const float*)d_in[12];
    const float* lbih = (const float*)d_in[13];
    const float* lbhh = (const float*)d_in[14];
    const float* e1W  = (const float*)d_in[15];
    const float* e1b  = (const float*)d_in[16];
    const float* e2W  = (const float*)d_in[17];
    const float* e2b  = (const float*)d_in[18];
    const float* gW0  = (const float*)d_in[19];
    const float* gb0  = (const float*)d_in[20];
    const float* gW1  = (const float*)d_in[21];
    const float* gb1  = (const float*)d_in[22];
    const float* gW2  = (const float*)d_in[23];
    const float* gb2  = (const float*)d_in[24];
    (void)in_sizes; (void)n_in;
    float* out = (float*)d_out;

    if (!g_init){
        cudaGetSymbolAddress((void**)&P.adj,  g_adj);
        cudaGetSymbolAddress((void**)&P.xcat, g_xcat);
        cudaGetSymbolAddress((void**)&P.gates,g_gates);
        cudaGetSymbolAddress((void**)&P.gates2,g_gates2);
        cudaGetSymbolAddress((void**)&P.part, g_part);
        cudaGetSymbolAddress((void**)&P.ht1,  g_ht1);
        cudaGetSymbolAddress((void**)&P.ht2,  g_ht2);
        cudaGetSymbolAddress((void**)&P.pvec, g_pvec);
        cudaGetSymbolAddress((void**)&P.srow, g_srow);
        cudaGetSymbolAddress((void**)&P.dvec, g_dvec);
        cudaGetSymbolAddress((void**)&P.minv, g_minv);
        cudaGetSymbolAddress((void**)&P.attv, g_attv);
        cudaGetSymbolAddress((void**)&P.xl,   g_xl);
        cudaGetSymbolAddress((void**)&P.hatt, g_hatt);
        cudaGetSymbolAddress((void**)&P.catt, g_catt);
        cudaGetSymbolAddress((void**)&P.hlang,g_hlang);
        cudaGetSymbolAddress((void**)&P.clang,g_clang);
        cudaGetSymbolAddress((void**)&P.Ph, g_Ph); cudaGetSymbolAddress((void**)&P.Pl, g_Pl);
        cudaGetSymbolAddress((void**)&P.Qh, g_Qh); cudaGetSymbolAddress((void**)&P.Ql, g_Ql);
        cudaGetSymbolAddress((void**)&P.Sh, g_Sh); cudaGetSymbolAddress((void**)&P.Sl, g_Sl);
        cudaGetSymbolAddress((void**)&P.Th, g_Th); cudaGetSymbolAddress((void**)&P.Tl, g_Tl);
        cudaGetSymbolAddress((void**)&P.ADJh, g_ADJh); cudaGetSymbolAddress((void**)&P.ADJl, g_ADJl);
        cudaGetSymbolAddress((void**)&P.W1h, g_W1h); cudaGetSymbolAddress((void**)&P.W1l, g_W1l);
        cudaGetSymbolAddress((void**)&P.W2h, g_W2h); cudaGetSymbolAddress((void**)&P.W2l, g_W2l);
        cudaGetSymbolAddress((void**)&P.G0h, g_G0h); cudaGetSymbolAddress((void**)&P.G0l, g_G0l);
        cudaGetSymbolAddress((void**)&P.G1h, g_G1h); cudaGetSymbolAddress((void**)&P.G1l, g_G1l);
        cudaGetSymbolAddress((void**)&P.G2h, g_G2h); cudaGetSymbolAddress((void**)&P.G2l, g_G2l);
        cudaFuncSetAttribute(hmma_gemm, cudaFuncAttributeMaxDynamicSharedMemorySize, MMA_SMEM);
        g_init = true;
    }

    const float* prev_h = sh + BR;
    const float* h0 = sh;
    const float* c0 = sc;
    const float* c1 = sc + BR;

    // ---- conversions (GE fused normal+transpose, weights) ----
    geconv_kernel<<<dim3(RR/32, NN/32, BB), dim3(32,8)>>>(ge, mask, P.Ph, P.Pl, P.Th, P.Tl);
    conv_slice_kernel<<<(1048576/4+255)/256,256>>>(e1W, 2048, P.W1h, P.W1l, 1024, 1048576/4);
    conv_slice_kernel<<<(1048576/4+255)/256,256>>>(e2W, 2048, P.W2h, P.W2l, 1024, 1048576/4);
    tconv_kernel<<<dim3(32,32),dim3(32,8)>>>(gW0, 1024, 1024, P.G0h, P.G0l);
    tconv_kernel<<<dim3(32,32),dim3(32,8)>>>(gW1, 1024, 1024, P.G1h, P.G1l);
    tconv_kernel<<<dim3(32,32),dim3(32,8)>>>(gW2, 1024, 1024, P.G2h, P.G2l);

    // ---- attention LSTM (split-K FFMA) ----
    concat3_kernel<<<(BB*3072+255)/256,256>>>(prev_h, fc, xt, P.xcat);
    sgemm(true, P.xcat,3072, aWih,3072, P.part,            4096, BB,4096,3072, 3);
    sgemm(true, h0,1024,     aWhh,1024, P.part+3*BB*4096,  4096, BB,4096,1024, 1);
    reduce_kernel<<<(BB*4096+255)/256,256>>>(P.gates, P.part, BB*4096, 4, 4095, abih, abhh);
    lstm_kernel<<<(BR+255)/256,256>>>(P.gates, c0, P.hatt, P.catt);

    // ---- h-terms (split-K FFMA) ----
    sgemm(true, P.hatt,1024, e1W+1024,2048, P.part, 1024, BB,1024,1024, 4);
    reduce_kernel<<<(BB*1024+255)/256,256>>>(P.ht1, P.part, BB*1024, 4, 1023, nullptr, nullptr);
    sgemm(true, P.hatt,1024, e2W+1024,2048, P.part, 1024, BB,1024,1024, 4);
    reduce_kernel<<<(BB*1024+255)/256,256>>>(P.ht2, P.part, BB*1024, 4, 1023, nullptr, nullptr);
    sgemm(false, prev_h,1024, gW0+1024*1024,1024, P.part, 1024, BB,1024,1024, 4);
    reduce_kernel<<<(BB*1024+255)/256,256>>>(P.pvec, P.part, BB*1024, 4, 1023, nullptr, nullptr);

    // ---- E1/E2 (tensor core) ----
    hmma_gemm<<<dim3(8,256,1),128,MMA_SMEM>>>(P.Ph,P.Pl,1024,0, P.W1h,P.W1l,1024,0,
        1024, 0, 1, 0, nullptr,0, P.Qh,P.Ql,1024, e1b, P.ht1, mask, nullptr);
    hmma_gemm<<<dim3(8,256,1),128,MMA_SMEM>>>(P.Ph,P.Pl,1024,0, P.W2h,P.W2l,1024,0,
        1024, 0, 1, 0, nullptr,0, P.Sh,P.Sl,1024, e2b, P.ht2, mask, nullptr);

    // ---- Adj = E1 @ E2^T ----
    hmma_gemm<<<dim3(4,4,64),128,MMA_SMEM>>>(P.Qh,P.Ql,1024,(long)NN*RR, P.Sh,P.Sl,1024,(long)NN*RR,
        1024, 512, 0, 0, P.adj,512, nullptr,nullptr,0, nullptr,nullptr,nullptr,nullptr);

    // ---- Adj post-processing ----
    batchmin_kernel<<<BB,1024>>>(P.adj, P.minv);
    topk_kernel<<<BB*NN,512>>>(P.adj, P.minv, mask, P.dvec);
    rowfinal_kernel<<<BB*NN/8,256>>>(P.adj, P.dvec, mask, P.ADJh, P.ADJl, P.srow);

    // ---- GCN layer 0 ----
    hmma_gemm<<<dim3(8,4,64),128,MMA_SMEM>>>(P.ADJh,P.ADJl,512,(long)NN*NN, P.Th,P.Tl,512,(long)RR*NN,
        512, 512, 1, 0, nullptr,0, P.Qh,P.Ql,1024, nullptr,nullptr,nullptr,nullptr);
    hmma_gemm<<<dim3(8,256,1),128,MMA_SMEM>>>(P.Qh,P.Ql,1024,0, P.G0h,P.G0l,1024,0,
        1024, 0, 2, 1, nullptr,0, P.Sh,P.Sl,0, gb0, P.pvec, P.srow, mask);

    // ---- GCN layer 1 ----
    hmma_gemm<<<dim3(8,4,64),128,MMA_SMEM>>>(P.ADJh,P.ADJl,512,(long)NN*NN, P.Sh,P.Sl,512,(long)RR*NN,
        512, 512, 1, 0, nullptr,0, P.Qh,P.Ql,1024, nullptr,nullptr,nullptr,nullptr);
    hmma_gemm<<<dim3(8,256,1),128,MMA_SMEM>>>(P.Qh,P.Ql,1024,0, P.G1h,P.G1l,1024,0,
        1024, 0, 2, 1, nullptr,0, P.Ph,P.Pl,0, gb1, nullptr, nullptr, mask);

    // ---- GCN layer 2 ----
    hmma_gemm<<<dim3(8,4,64),128,MMA_SMEM>>>(P.ADJh,P.ADJl,512,(long)NN*NN, P.Ph,P.Pl,512,(long)RR*NN,
        512, 512, 1, 0, nullptr,0, P.Qh,P.Ql,1024, nullptr,nullptr,nullptr,nullptr);
    hmma_gemm<<<dim3(8,256,1),128,MMA_SMEM>>>(P.Qh,P.Ql,1024,0, P.G2h,P.G2l,1024,0,
        1024, 0, 2, 1, nullptr,0, P.Sh,P.Sl,0, gb2, nullptr, nullptr, mask);

    // ---- att = max over nodes (XT contiguous) ----
    colmaxT_kernel<<<(BB*RR*32+255)/256,256>>>(P.Sh, P.Sl, P.attv);

    // ---- language LSTM (split-K FFMA) ----
    concat2_kernel<<<(BB*2048+255)/256,256>>>(P.attv, P.hatt, P.xl);
    sgemm(true, P.xl,2048,   lWih,2048, P.part,           4096, BB,4096,2048, 2);
    sgemm(true, prev_h,1024, lWhh,1024, P.part+2*BB*4096, 4096, BB,4096,1024, 1);
    reduce_kernel<<<(BB*4096+255)/256,256>>>(P.gates2, P.part, BB*4096, 3, 4095, lbih, lbhh);
    lstm_kernel<<<(BR+255)/256,256>>>(P.gates2, c1, P.hlang, P.clang);

    pack_kernel<<<(BR+255)/256,256>>>(P.hatt, P.catt, P.hlang, P.clang, out, out_size);
}

// round 9
// speedup vs baseline: 2.9612x; 1.0140x over previous
#include <cuda_runtime.h>
#include <cuda_bf16.h>
#include <math.h>
#include <stdint.h>

#define BB 64
#define NN 512
#define RR 1024
#define KTOP 256
#define BR (BB*RR)
#define NGE ((long)BB*NN*RR)

// ---------------- device scratch ----------------
__device__ float g_adj[(long)BB*NN*NN];
__device__ float g_xcat[BB*3072];
__device__ float g_gates[BB*4096];
__device__ float g_gates2[BB*4096];
__device__ float g_part[4*BB*4096];
__device__ float g_ht1[BB*RR];
__device__ float g_ht2[BB*RR];
__device__ float g_pvec[BB*RR];
__device__ float g_srow[BB*NN];
__device__ float g_dvec[BB*NN];
__device__ float g_minv[BB];
__device__ float g_attv[BB*RR];
__device__ float g_xl[BB*2048];
__device__ float g_hatt[BR];
__device__ float g_catt[BR];
__device__ float g_hlang[BR];
__device__ float g_clang[BR];

__device__ __nv_bfloat16 g_Ph[NGE], g_Pl[NGE];   // GEM -> Z1^T -> X3^T
__device__ __nv_bfloat16 g_Qh[NGE], g_Ql[NGE];   // E1 -> Z0^T -> X2
__device__ __nv_bfloat16 g_Sh[NGE], g_Sl[NGE];   // E2 -> X1 -> Z2^T
__device__ __nv_bfloat16 g_ADJh[(long)BB*NN*NN], g_ADJl[(long)BB*NN*NN];
__device__ __nv_bfloat16 g_W1h[1048576], g_W1l[1048576];
__device__ __nv_bfloat16 g_W2h[1048576], g_W2l[1048576];
__device__ __nv_bfloat16 g_G0h[1048576], g_G0l[1048576];
__device__ __nv_bfloat16 g_G1h[1048576], g_G1l[1048576];
__device__ __nv_bfloat16 g_G2h[1048576], g_G2l[1048576];

// ---------------- warp MMA helpers ----------------
__device__ __forceinline__ uint32_t smem_u32(const void* p){
    uint32_t a;
    asm("{ .reg .u64 t; cvta.to.shared.u64 t, %1; cvt.u32.u64 %0, t; }" : "=r"(a) : "l"(p));
    return a;
}
__device__ __forceinline__ uint32_t swz64(uint32_t x){ return x ^ ((x>>3)&0x30u); }
__device__ __forceinline__ void ldm4(uint32_t* r, uint32_t addr){
    asm volatile("ldmatrix.sync.aligned.m8n8.x4.shared.b16 {%0,%1,%2,%3}, [%4];"
        : "=r"(r[0]),"=r"(r[1]),"=r"(r[2]),"=r"(r[3]) : "r"(addr));
}
__device__ __forceinline__ void mma16816(float* d, const uint32_t* a, const uint32_t* b){
    asm volatile("mma.sync.aligned.m16n8k16.row.col.f32.bf16.bf16.f32 "
        "{%0,%1,%2,%3}, {%4,%5,%6,%7}, {%8,%9}, {%0,%1,%2,%3};"
        : "+f"(d[0]),"+f"(d[1]),"+f"(d[2]),"+f"(d[3])
        : "r"(a[0]),"r"(a[1]),"r"(a[2]),"r"(a[3]), "r"(b[0]),"r"(b[1]));
}
__device__ __forceinline__ void cpasync16(uint32_t dst, const void* src){
    asm volatile("cp.async.cg.shared.global [%0], [%1], 16;" :: "r"(dst), "l"(src));
}

// ---------------- bf16 hi/lo tensor-core GEMM, 3-stage cp.async ----------------
// C[128x128 tile] = (Ah+Al)[M,K] @ (Bh+Bl)[N,K]^T, K-major, fp32 accum.
// 128 threads = 4 warps (2x2), warp tile 64x64. BK=32, 3 stages x 32KB, 2 CTA/SM.
#define MMA_SMEM (3*32768+1024)

__global__ void __launch_bounds__(128,2) hmma_gemm(
    const __nv_bfloat16* __restrict__ Ah, const __nv_bfloat16* __restrict__ Al, int lda, long sA,
    const __nv_bfloat16* __restrict__ Bh, const __nv_bfloat16* __restrict__ Bl, int ldb, long sB,
    int K, int rowsPerZ, int outMode, int relu,
    float* Cf, int ldc,
    __nv_bfloat16* Ch, __nv_bfloat16* Cl, int ldch,
    const float* __restrict__ bias, const float* __restrict__ addv,
    const float* __restrict__ rs, const float* __restrict__ ps)
{
    extern __shared__ char smraw[];
    uint32_t sb0 = smem_u32(smraw);
    uint32_t sb  = (sb0 + 1023u) & ~1023u;
    const int tid = threadIdx.x, wid = tid>>5, lane = tid&31;

    const __nv_bfloat16* A0 = Ah + blockIdx.z*sA;
    const __nv_bfloat16* A1 = Al + blockIdx.z*sA;
    const __nv_bfloat16* B0 = Bh + blockIdx.z*sB;
    const __nv_bfloat16* B1 = Bl + blockIdx.z*sB;
    const int rowBase = blockIdx.y*128, colBase = blockIdx.x*128;
    const int NC = K >> 5;

    const int wr = wid>>1, wc = wid&1;     // warp tile 64x64
    const int lr = lane&7, q = lane>>3;
    const int aRowOff = ((q&1)<<3) + lr;
    const int aKbOff  = (q>>1)<<4;
    const int bRowOff = ((q>>1)<<3) + lr;
    const int bKbOff  = (q&1)<<4;

    const int cp_row = tid>>2;
    const int cp_u   = tid&3;

    float acc[4][8][4];
    #pragma unroll
    for (int a=0;a<4;a++)
        #pragma unroll
        for (int b=0;b<8;b++)
            #pragma unroll
            for (int c=0;c<4;c++) acc[a][b][c]=0.f;

    auto load_chunk = [&](int ci, int s){
        const int k0 = ci<<5;
        const uint32_t st = sb + s*32768;
        #pragma unroll
        for (int j=0;j<4;j++){
            int r = cp_row + j*32;
            uint32_t doff = swz64((uint32_t)(r*64 + cp_u*16));
            long aoff = (long)(rowBase+r)*lda + k0 + cp_u*8;
            long boff = (long)(colBase+r)*ldb + k0 + cp_u*8;
            cpasync16(st +         doff, A0 + aoff);
            cpasync16(st +  8192 + doff, A1 + aoff);
            cpasync16(st + 16384 + doff, B0 + boff);
            cpasync16(st + 24576 + doff, B1 + boff);
        }
        asm volatile("cp.async.commit_group;" ::: "memory");
    };

    load_chunk(0, 0);
    if (NC > 1) load_chunk(1, 1);

    int sidx = 0;
    int nidx = (NC > 2) ? 2 : 0;
    for (int i=0;i<NC;i++){
        if (i+1 < NC) asm volatile("cp.async.wait_group 1;" ::: "memory");
        else          asm volatile("cp.async.wait_group 0;" ::: "memory");
        __syncthreads();
        if (i+2 < NC){
            load_chunk(i+2, nidx);
            nidx = (nidx==2)?0:nidx+1;
        }
        const uint32_t st = sb + sidx*32768;
        sidx = (sidx==2)?0:sidx+1;
        #pragma unroll
        for (int ks=0;ks<2;ks++){
            const uint32_t kb = ks<<5;
            uint32_t bh[4][4], bl[4][4], af[4][4];
            #pragma unroll
            for (int t=0;t<4;t++){
                uint32_t ro = (uint32_t)((wc*64 + t*16 + bRowOff)*64) + kb + bKbOff;
                ldm4(bh[t], st + 16384 + swz64(ro));
                ldm4(bl[t], st + 24576 + swz64(ro));
            }
            #pragma unroll
            for (int mi=0;mi<4;mi++){
                uint32_t ro = (uint32_t)((wr*64 + mi*16 + aRowOff)*64) + kb + aKbOff;
                ldm4(af[mi], st + swz64(ro));
            }
            #pragma unroll
            for (int mi=0;mi<4;mi++)
                #pragma unroll
                for (int t=0;t<4;t++){
                    mma16816(acc[mi][2*t],   af[mi], &bh[t][0]);
                    mma16816(acc[mi][2*t+1], af[mi], &bh[t][2]);
                }
            #pragma unroll
            for (int mi=0;mi<4;mi++)
                #pragma unroll
                for (int t=0;t<4;t++){
                    mma16816(acc[mi][2*t],   af[mi], &bl[t][0]);
                    mma16816(acc[mi][2*t+1], af[mi], &bl[t][2]);
                }
            #pragma unroll
            for (int mi=0;mi<4;mi++){
                uint32_t ro = (uint32_t)((wr*64 + mi*16 + aRowOff)*64) + kb + aKbOff;
                ldm4(af[mi], st + 8192 + swz64(ro));
            }
            #pragma unroll
            for (int mi=0;mi<4;mi++)
                #pragma unroll
                for (int t=0;t<4;t++){
                    mma16816(acc[mi][2*t],   af[mi], &bh[t][0]);
                    mma16816(acc[mi][2*t+1], af[mi], &bh[t][2]);
                }
        }
    }

    // ---- epilogue ----
    const int cpair = (lane&3)*2;
    #pragma unroll
    for (int mi=0;mi<4;mi++){
        #pragma unroll
        for (int rr=0;rr<2;rr++){
            const int r  = rowBase + wr*64 + mi*16 + (lane>>2) + rr*8;
            const int gr = blockIdx.z*rowsPerZ + r;
            const float rsv = rs ? rs[gr] : 1.f;
            const float psv = ps ? ps[gr] : 1.f;
            const float* avp = addv ? addv + (long)(gr>>9)*RR : nullptr;
            #pragma unroll
            for (int ni=0;ni<8;ni++){
                const int c = colBase + wc*64 + ni*8 + cpair;
                float x0 = acc[mi][ni][rr*2+0];
                float x1 = acc[mi][ni][rr*2+1];
                if (avp){ x0 += rsv*avp[c]; x1 += rsv*avp[c+1]; }
                if (bias){ x0 += bias[c]; x1 += bias[c+1]; }
                if (relu){ x0 = fmaxf(x0,0.f); x1 = fmaxf(x1,0.f); }
                x0 *= psv; x1 *= psv;
                if (outMode==0){
                    *(float2*)(Cf + (long)gr*ldc + c) = make_float2(x0,x1);
                } else {
                    __nv_bfloat16 h0 = __float2bfloat16(x0);
                    __nv_bfloat16 l0 = __float2bfloat16(x0-__bfloat162float(h0));
                    __nv_bfloat16 h1 = __float2bfloat16(x1);
                    __nv_bfloat16 l1 = __float2bfloat16(x1-__bfloat162float(h1));
                    if (outMode==1){
                        long o = (long)gr*ldch + c;
                        __nv_bfloat162 hp; hp.x=h0; hp.y=h1;
                        __nv_bfloat162 lp; lp.x=l0; lp.y=l1;
                        *(__nv_bfloat162*)(Ch+o) = hp;
                        *(__nv_bfloat162*)(Cl+o) = lp;
                    } else { // transposed: out[b][feat][node]
                        long base = (long)(gr>>9)*((long)RR*NN) + (gr&511);
                        long o0 = base + (long)c*NN;
                        Ch[o0]=h0; Cl[o0]=l0;
                        Ch[o0+NN]=h1; Cl[o0+NN]=l1;
                    }
                }
            }
        }
    }
}

// ---------------- FFMA split-K GEMM for small (B=64) matmuls ----------------
template<bool BT>
__global__ void __launch_bounds__(256) gemm_part(
    const float* __restrict__ A,int lda,
    const float* __restrict__ B,int ldb,
    float* __restrict__ C,int ldc,long partStride,int chunkK)
{
    __shared__ float As[16][64];
    __shared__ float Bs[16][64];
    const int tid = threadIdx.x;
    const int rowBase = blockIdx.y*64, colBase = blockIdx.x*64;
    const int kbeg = blockIdx.z*chunkK, kend = kbeg + chunkK;
    const int tx = tid & 15, ty = tid >> 4;
    float acc[4][4];
#pragma unroll
    for (int i=0;i<4;i++)
#pragma unroll
        for (int j=0;j<4;j++) acc[i][j]=0.f;

    for (int k0=kbeg;k0<kend;k0+=16){
#pragma unroll
        for (int i=tid*4;i<64*16;i+=256*4){
            int r=i>>4, kk=i&15;
            float4 v = *(const float4*)(A + (long)(rowBase+r)*lda + k0 + kk);
            As[kk+0][r]=v.x; As[kk+1][r]=v.y; As[kk+2][r]=v.z; As[kk+3][r]=v.w;
        }
        if (BT){
#pragma unroll
            for (int i=tid*4;i<64*16;i+=256*4){
                int r=i>>4, kk=i&15;
                float4 v = *(const float4*)(B + (long)(colBase+r)*ldb + k0 + kk);
                Bs[kk+0][r]=v.x; Bs[kk+1][r]=v.y; Bs[kk+2][r]=v.z; Bs[kk+3][r]=v.w;
            }
        } else {
#pragma unroll
            for (int i=tid*4;i<16*64;i+=256*4){
                int r=i>>6, cc=i&63;
                *(float4*)&Bs[r][cc] = *(const float4*)(B + (long)(k0+r)*ldb + colBase + cc);
            }
        }
        __syncthreads();
#pragma unroll
        for (int k=0;k<16;k++){
            float a[4], b[4];
            *(float4*)a = *(const float4*)&As[k][ty*4];
            *(float4*)b = *(const float4*)&Bs[k][tx*4];
#pragma unroll
            for (int i=0;i<4;i++)
#pragma unroll
                for (int j=0;j<4;j++) acc[i][j] = fmaf(a[i], b[j], acc[i][j]);
        }
        __syncthreads();
    }
    float* Cp = C + (long)blockIdx.z*partStride;
#pragma unroll
    for (int i=0;i<4;i++){
        int r = rowBase + ty*4 + i;
#pragma unroll
        for (int j=0;j<4;j++)
            Cp[(long)r*ldc + colBase + tx*4 + j] = acc[i][j];
    }
}
static void sgemm(bool BT,const float* A,int lda,const float* B,int ldb,float* Cpart,int ldc,
                  int M,int N,int K,int splits){
    dim3 g(N/64, M/64, splits);
    int chunkK = K/splits;
    if (BT) gemm_part<true ><<<g,256>>>(A,lda,B,ldb,Cpart,ldc,(long)M*ldc,chunkK);
    else    gemm_part<false><<<g,256>>>(A,lda,B,ldb,Cpart,ldc,(long)M*ldc,chunkK);
}
__global__ void reduce_kernel(float* dst,const float* src,long len,int splits,int colmask,
                              const float* b1,const float* b2){
    long i = (long)blockIdx.x*blockDim.x+threadIdx.x;
    if (i >= len) return;
    float s = 0.f;
    for (int z=0;z<splits;z++) s += src[z*len+i];
    int col = (int)(i & colmask);
    if (b1) s += b1[col];
    if (b2) s += b2[col];
    dst[i] = s;
}

// ---------------- conversions ----------------
__device__ __forceinline__ void split1(float v, __nv_bfloat16& h, __nv_bfloat16& l){
    h = __float2bfloat16(v);
    l = __float2bfloat16(v - __bfloat162float(h));
}

__global__ void conv_mask_kernel(const float* __restrict__ src, const float* __restrict__ mask,
                                 __nv_bfloat16* __restrict__ dh, __nv_bfloat16* __restrict__ dl, long n4){
    long i = (long)blockIdx.x*blockDim.x + threadIdx.x;
    if (i >= n4) return;
    float4 v = ((const float4*)src)[i];
    float m = mask[i >> 8];
    v.x*=m; v.y*=m; v.z*=m; v.w*=m;
    __align__(8) __nv_bfloat16 h[4], l[4];
    split1(v.x,h[0],l[0]); split1(v.y,h[1],l[1]); split1(v.z,h[2],l[2]); split1(v.w,h[3],l[3]);
    ((uint2*)dh)[i] = *(uint2*)h;
    ((uint2*)dl)[i] = *(uint2*)l;
}

__global__ void conv_slice_kernel(const float* __restrict__ src, int ldsrc,
                                  __nv_bfloat16* __restrict__ dh, __nv_bfloat16* __restrict__ dl,
                                  int cols, int n4){
    int i = blockIdx.x*blockDim.x + threadIdx.x;
    if (i >= n4) return;
    int c4pr = cols/4;
    int r = i / c4pr, c4 = i % c4pr;
    float4 v = *(const float4*)(src + (long)r*ldsrc + c4*4);
    __align__(8) __nv_bfloat16 h[4], l[4];
    split1(v.x,h[0],l[0]); split1(v.y,h[1],l[1]); split1(v.z,h[2],l[2]); split1(v.w,h[3],l[3]);
    long o = (long)r*c4pr + c4;
    ((uint2*)dh)[o] = *(uint2*)h;
    ((uint2*)dl)[o] = *(uint2*)l;
}

// transpose+convert (weights): src [rows,cols] fp32 -> dst [cols,rows] bf16 hi/lo
__global__ void tconv_kernel(const float* __restrict__ src, int rows, int cols,
                             __nv_bfloat16* __restrict__ dh, __nv_bfloat16* __restrict__ dl){
    __shared__ float t[32][33];
    int r0 = blockIdx.y*32, c0 = blockIdx.x*32;
    int tx = threadIdx.x, ty = threadIdx.y;
    for (int i=ty;i<32;i+=8)
        t[i][tx] = src[(long)(r0+i)*cols + c0+tx];
    __syncthreads();
    for (int i=ty;i<32;i+=8){
        float v = t[tx][i];
        __nv_bfloat16 h, l; split1(v, h, l);
        long o = (long)(c0+i)*rows + r0+tx;
        dh[o] = h; dl[o] = l;
    }
}

// ---------------- pointwise / reductions ----------------
__device__ __forceinline__ float sigm(float x){ return 1.f/(1.f+__expf(-x)); }

__global__ void concat3_kernel(const float* a,const float* b,const float* c,float* out){
    int idx = blockIdx.x*blockDim.x+threadIdx.x;
    if (idx >= BB*3072) return;
    int bb = idx/3072, j = idx%3072;
    out[idx] = (j<1024) ? a[bb*1024+j] : (j<2048 ? b[bb*1024+j-1024] : c[bb*1024+j-2048]);
}
__global__ void concat2_kernel(const float* a,const float* b,float* out){
    int idx = blockIdx.x*blockDim.x+threadIdx.x;
    if (idx >= BB*2048) return;
    int bb = idx/2048, j = idx%2048;
    out[idx] = (j<1024) ? a[bb*1024+j] : b[bb*1024+j-1024];
}
__global__ void lstm_kernel(const float* gates,const float* c_prev,float* h_out,float* c_out){
    int idx = blockIdx.x*blockDim.x+threadIdx.x;
    if (idx >= BR) return;
    int bb = idx >> 10, r = idx & 1023;
    const float* g = gates + bb*4096;
    float c = sigm(g[1024+r])*c_prev[idx] + sigm(g[r])*tanhf(g[2048+r]);
    h_out[idx] = sigm(g[3072+r])*tanhf(c);
    c_out[idx] = c;
}
__global__ void batchmin_kernel(const float* Adj,float* minv){
    __shared__ float sm[1024];
    const float* a = Adj + (long)blockIdx.x*NN*NN;
    float mn = INFINITY;
    for (int i=threadIdx.x;i<NN*NN;i+=1024) mn = fminf(mn, a[i]);
    sm[threadIdx.x]=mn; __syncthreads();
    for (int s=512;s>0;s>>=1){ if (threadIdx.x<s) sm[threadIdx.x]=fminf(sm[threadIdx.x],sm[threadIdx.x+s]); __syncthreads(); }
    if (threadIdx.x==0) minv[blockIdx.x]=sm[0];
}
__global__ void __launch_bounds__(512) topk_kernel(float* Adj,const float* minv,
                                                   const float* mask,float* dvec){
    __shared__ unsigned long long keys[NN];
    __shared__ float red[NN];
    int row = blockIdx.x, t = threadIdx.x, bb = row >> 9;
    float mrow = mask[row];
    float* arow = Adj + (long)row*NN;
    float v = (arow[t] - minv[bb]) * mrow;
    keys[t] = ((unsigned long long)__float_as_uint(v) << 32) | (unsigned)(NN-1-t);
    __syncthreads();
    for (unsigned k2=2;k2<=NN;k2<<=1)
        for (unsigned j=k2>>1;j>0;j>>=1){
            unsigned ixj = t ^ j;
            if (ixj > (unsigned)t){
                unsigned long long x=keys[t], y=keys[ixj];
                bool desc = ((t & k2) == 0);
                if (desc ? (x<y) : (x>y)){ keys[t]=y; keys[ixj]=x; }
            }
            __syncthreads();
        }
    unsigned long long kk = keys[t];
    arow[t] = 0.f;
    __syncthreads();
    float s = 0.f;
    if (t < KTOP){
        int col = (NN-1) - (int)(unsigned)(kk & 0xffffffffu);
        float val = __uint_as_float((unsigned)(kk >> 32));
        arow[col] = val;
        s = val;
    }
    red[t]=s; __syncthreads();
    for (int st=NN/2;st>0;st>>=1){ if (t<st) red[t]+=red[t+st]; __syncthreads(); }
    if (t==0) dvec[row] = (red[0] > 0.f) ? rsqrtf(red[0]) : 0.f;
}
// fused: Adj *= d_r*d_c, split to bf16 hi/lo, and srow[r] = sum_c Adj_norm*mask_c
__global__ void rowfinal_kernel(const float* __restrict__ adj, const float* __restrict__ dvec,
                                const float* __restrict__ mask,
                                __nv_bfloat16* __restrict__ Ah, __nv_bfloat16* __restrict__ Al,
                                float* __restrict__ srow){
    int row = blockIdx.x*8 + (threadIdx.x>>5);
    int lane = threadIdx.x & 31;
    int bb = row >> 9;
    const float* a = adj + (long)row*NN;
    const float dr = dvec[row];
    const float* dc = dvec + (bb<<9);
    const float* m  = mask + (bb<<9);
    float s = 0.f;
    for (int k=lane*4; k<NN; k+=128){
        float4 v  = *(const float4*)(a+k);
        float4 d4 = *(const float4*)(dc+k);
        float4 m4 = *(const float4*)(m+k);
        float x0=v.x*dr*d4.x, x1=v.y*dr*d4.y, x2=v.z*dr*d4.z, x3=v.w*dr*d4.w;
        s += x0*m4.x + x1*m4.y + x2*m4.z + x3*m4.w;
        __align__(8) __nv_bfloat16 h[4], l[4];
        split1(x0,h[0],l[0]); split1(x1,h[1],l[1]); split1(x2,h[2],l[2]); split1(x3,h[3],l[3]);
        long o = ((long)row*NN + k) >> 2;
        ((uint2*)Ah)[o] = *(uint2*)h;
        ((uint2*)Al)[o] = *(uint2*)l;
    }
    for (int o=16;o;o>>=1) s += __shfl_xor_sync(0xffffffffu, s, o);
    if (lane==0) srow[row] = s;
}
__global__ void colmaxT_kernel(const __nv_bfloat16* Xh,const __nv_bfloat16* Xl,float* att){
    int warp = (blockIdx.x*blockDim.x+threadIdx.x) >> 5;
    int lane = threadIdx.x & 31;
    if (warp >= BB*RR) return;
    long base = (long)warp*NN;
    float mx = -INFINITY;
    for (int k=lane;k<NN;k+=32)
        mx = fmaxf(mx, __bfloat162float(Xh[base+k]) + __bfloat162float(Xl[base+k]));
    for (int o=16;o;o>>=1) mx = fmaxf(mx, __shfl_xor_sync(0xffffffffu, mx, o));
    if (lane==0) att[warp] = mx;
}
__global__ void pack_kernel(const float* hatt,const float* catt,
                            const float* hlang,const float* clang,float* out,int out_size){
    int i = blockIdx.x*blockDim.x+threadIdx.x;
    if (i >= BR) return;
    out[i] = hlang[i];
    if (out_size >= 5*BR){
        out[1*BR+i] = hatt[i];
        out[2*BR+i] = hlang[i];
        out[3*BR+i] = catt[i];
        out[4*BR+i] = clang[i];
    }
}

// ---------------- host driver ----------------
struct Ptrs {
    float *adj,*xcat,*gates,*gates2,*part,*ht1,*ht2,*pvec,*srow,*dvec,*minv,*attv,*xl,*hatt,*catt,*hlang,*clang;
    __nv_bfloat16 *Ph,*Pl,*Qh,*Ql,*Sh,*Sl,*ADJh,*ADJl;
    __nv_bfloat16 *W1h,*W1l,*W2h,*W2l,*G0h,*G0l,*G1h,*G1l,*G2h,*G2l;
};
static Ptrs P;
static bool g_init = false;

extern "C" void kernel_launch(void* const* d_in, const int* in_sizes, int n_in,
                              void* d_out, int out_size)
{
    const float* xt   = (const float*)d_in[0];
    const float* fc   = (const float*)d_in[1];
    const float* ge   = (const float*)d_in[2];
    const float* sh   = (const float*)d_in[4];
    const float* sc   = (const float*)d_in[5];
    const float* mask = (const float*)d_in[6];
    const float* aWih = (const float*)d_in[7];
    const float* aWhh = (const float*)d_in[8];
    const float* abih = (const float*)d_in[9];
    const float* abhh = (const float*)d_in[10];
    const float* lWih = (const float*)d_in[11];
    const float* lWhh = (const float*)d_in[12];
    const float* lbih = (const float*)d_in[13];
    const float* lbhh = (const float*)d_in[14];
    const float* e1W  = (const float*)d_in[15];
    const float* e1b  = (const float*)d_in[16];
    const float* e2W  = (const float*)d_in[17];
    const float* e2b  = (const float*)d_in[18];
    const float* gW0  = (const float*)d_in[19];
    const float* gb0  = (const float*)d_in[20];
    const float* gW1  = (const float*)d_in[21];
    const float* gb1  = (const float*)d_in[22];
    const float* gW2  = (const float*)d_in[23];
    const float* gb2  = (const float*)d_in[24];
    (void)in_sizes; (void)n_in;
    float* out = (float*)d_out;

    if (!g_init){
        cudaGetSymbolAddress((void**)&P.adj,  g_adj);
        cudaGetSymbolAddress((void**)&P.xcat, g_xcat);
        cudaGetSymbolAddress((void**)&P.gates,g_gates);
        cudaGetSymbolAddress((void**)&P.gates2,g_gates2);
        cudaGetSymbolAddress((void**)&P.part, g_part);
        cudaGetSymbolAddress((void**)&P.ht1,  g_ht1);
        cudaGetSymbolAddress((void**)&P.ht2,  g_ht2);
        cudaGetSymbolAddress((void**)&P.pvec, g_pvec);
        cudaGetSymbolAddress((void**)&P.srow, g_srow);
        cudaGetSymbolAddress((void**)&P.dvec, g_dvec);
        cudaGetSymbolAddress((void**)&P.minv, g_minv);
        cudaGetSymbolAddress((void**)&P.attv, g_attv);
        cudaGetSymbolAddress((void**)&P.xl,   g_xl);
        cudaGetSymbolAddress((void**)&P.hatt, g_hatt);
        cudaGetSymbolAddress((void**)&P.catt, g_catt);
        cudaGetSymbolAddress((void**)&P.hlang,g_hlang);
        cudaGetSymbolAddress((void**)&P.clang,g_clang);
        cudaGetSymbolAddress((void**)&P.Ph, g_Ph); cudaGetSymbolAddress((void**)&P.Pl, g_Pl);
        cudaGetSymbolAddress((void**)&P.Qh, g_Qh); cudaGetSymbolAddress((void**)&P.Ql, g_Ql);
        cudaGetSymbolAddress((void**)&P.Sh, g_Sh); cudaGetSymbolAddress((void**)&P.Sl, g_Sl);
        cudaGetSymbolAddress((void**)&P.ADJh, g_ADJh); cudaGetSymbolAddress((void**)&P.ADJl, g_ADJl);
        cudaGetSymbolAddress((void**)&P.W1h, g_W1h); cudaGetSymbolAddress((void**)&P.W1l, g_W1l);
        cudaGetSymbolAddress((void**)&P.W2h, g_W2h); cudaGetSymbolAddress((void**)&P.W2l, g_W2l);
        cudaGetSymbolAddress((void**)&P.G0h, g_G0h); cudaGetSymbolAddress((void**)&P.G0l, g_G0l);
        cudaGetSymbolAddress((void**)&P.G1h, g_G1h); cudaGetSymbolAddress((void**)&P.G1l, g_G1l);
        cudaGetSymbolAddress((void**)&P.G2h, g_G2h); cudaGetSymbolAddress((void**)&P.G2l, g_G2l);
        cudaFuncSetAttribute(hmma_gemm, cudaFuncAttributeMaxDynamicSharedMemorySize, MMA_SMEM);
        g_init = true;
    }

    const float* prev_h = sh + BR;
    const float* h0 = sh;
    const float* c0 = sc;
    const float* c1 = sc + BR;

    // ---- conversions ----
    conv_mask_kernel<<<(int)((NGE/4+255)/256),256>>>(ge, mask, P.Ph, P.Pl, NGE/4);
    conv_slice_kernel<<<(1048576/4+255)/256,256>>>(e1W, 2048, P.W1h, P.W1l, 1024, 1048576/4);
    conv_slice_kernel<<<(1048576/4+255)/256,256>>>(e2W, 2048, P.W2h, P.W2l, 1024, 1048576/4);
    tconv_kernel<<<dim3(32,32),dim3(32,8)>>>(gW0, 1024, 1024, P.G0h, P.G0l);
    tconv_kernel<<<dim3(32,32),dim3(32,8)>>>(gW1, 1024, 1024, P.G1h, P.G1l);
    tconv_kernel<<<dim3(32,32),dim3(32,8)>>>(gW2, 1024, 1024, P.G2h, P.G2l);

    // ---- attention LSTM (split-K FFMA) ----
    concat3_kernel<<<(BB*3072+255)/256,256>>>(prev_h, fc, xt, P.xcat);
    sgemm(true, P.xcat,3072, aWih,3072, P.part,            4096, BB,4096,3072, 3);
    sgemm(true, h0,1024,     aWhh,1024, P.part+3*BB*4096,  4096, BB,4096,1024, 1);
    reduce_kernel<<<(BB*4096+255)/256,256>>>(P.gates, P.part, BB*4096, 4, 4095, abih, abhh);
    lstm_kernel<<<(BR+255)/256,256>>>(P.gates, c0, P.hatt, P.catt);

    // ---- h-terms (split-K FFMA) ----
    sgemm(true, P.hatt,1024, e1W+1024,2048, P.part, 1024, BB,1024,1024, 4);
    reduce_kernel<<<(BB*1024+255)/256,256>>>(P.ht1, P.part, BB*1024, 4, 1023, nullptr, nullptr);
    sgemm(true, P.hatt,1024, e2W+1024,2048, P.part, 1024, BB,1024,1024, 4);
    reduce_kernel<<<(BB*1024+255)/256,256>>>(P.ht2, P.part, BB*1024, 4, 1023, nullptr, nullptr);
    sgemm(false, prev_h,1024, gW0+1024*1024,1024, P.part, 1024, BB,1024,1024, 4);
    reduce_kernel<<<(BB*1024+255)/256,256>>>(P.pvec, P.part, BB*1024, 4, 1023, nullptr, nullptr);

    // ---- E1/E2 ----
    hmma_gemm<<<dim3(8,256,1),128,MMA_SMEM>>>(P.Ph,P.Pl,1024,0, P.W1h,P.W1l,1024,0,
        1024, 0, 1, 0, nullptr,0, P.Qh,P.Ql,1024, e1b, P.ht1, mask, nullptr);
    hmma_gemm<<<dim3(8,256,1),128,MMA_SMEM>>>(P.Ph,P.Pl,1024,0, P.W2h,P.W2l,1024,0,
        1024, 0, 1, 0, nullptr,0, P.Sh,P.Sl,1024, e2b, P.ht2, mask, nullptr);

    // ---- Adj = E1 @ E2^T ----
    hmma_gemm<<<dim3(4,4,64),128,MMA_SMEM>>>(P.Qh,P.Ql,1024,(long)NN*RR, P.Sh,P.Sl,1024,(long)NN*RR,
        1024, 512, 0, 0, P.adj,512, nullptr,nullptr,0, nullptr,nullptr,nullptr,nullptr);

    // ---- Adj post-processing ----
    batchmin_kernel<<<BB,1024>>>(P.adj, P.minv);
    topk_kernel<<<BB*NN,512>>>(P.adj, P.minv, mask, P.dvec);
    rowfinal_kernel<<<BB*NN/8,256>>>(P.adj, P.dvec, mask, P.ADJh, P.ADJl, P.srow);

    // ---- GCN layer 0: Z0 = GEM@G0 (->Q, transposed), X1 = relu(Adj@Z0 + srow*pvec + b0)*m (->S)
    hmma_gemm<<<dim3(8,256,1),128,MMA_SMEM>>>(P.Ph,P.Pl,1024,0, P.G0h,P.G0l,1024,0,
        1024, 0, 2, 0, nullptr,0, P.Qh,P.Ql,0, nullptr, nullptr, nullptr, nullptr);
    hmma_gemm<<<dim3(8,4,64),128,MMA_SMEM>>>(P.ADJh,P.ADJl,512,(long)NN*NN, P.Qh,P.Ql,512,(long)RR*NN,
        512, 512, 1, 1, nullptr,0, P.Sh,P.Sl,1024, gb0, P.pvec, P.srow, mask);

    // ---- GCN layer 1: Z1 = X1@G1 (->P, transposed), X2 = relu(Adj@Z1 + b1)*m (->Q)
    hmma_gemm<<<dim3(8,256,1),128,MMA_SMEM>>>(P.Sh,P.Sl,1024,0, P.G1h,P.G1l,1024,0,
        1024, 0, 2, 0, nullptr,0, P.Ph,P.Pl,0, nullptr, nullptr, nullptr, nullptr);
    hmma_gemm<<<dim3(8,4,64),128,MMA_SMEM>>>(P.ADJh,P.ADJl,512,(long)NN*NN, P.Ph,P.Pl,512,(long)RR*NN,
        512, 512, 1, 1, nullptr,0, P.Qh,P.Ql,1024, gb1, nullptr, nullptr, mask);

    // ---- GCN layer 2: Z2 = X2@G2 (->S, transposed), X3^T = relu(Adj@Z2 + b2)*m (->P, transposed)
    hmma_gemm<<<dim3(8,256,1),128,MMA_SMEM>>>(P.Qh,P.Ql,1024,0, P.G2h,P.G2l,1024,0,
        1024, 0, 2, 0, nullptr,0, P.Sh,P.Sl,0, nullptr, nullptr, nullptr, nullptr);
    hmma_gemm<<<dim3(8,4,64),128,MMA_SMEM>>>(P.ADJh,P.ADJl,512,(long)NN*NN, P.Sh,P.Sl,512,(long)RR*NN,
        512, 512, 2, 1, nullptr,0, P.Ph,P.Pl,0, gb2, nullptr, nullptr, mask);

    // ---- att = max over nodes (X3^T contiguous) ----
    colmaxT_kernel<<<(BB*RR*32+255)/256,256>>>(P.Ph, P.Pl, P.attv);

    // ---- language LSTM (split-K FFMA) ----
    concat2_kernel<<<(BB*2048+255)/256,256>>>(P.attv, P.hatt, P.xl);
    sgemm(true, P.xl,2048,   lWih,2048, P.part,           4096, BB,4096,2048, 2);
    sgemm(true, prev_h,1024, lWhh,1024, P.part+2*BB*4096, 4096, BB,4096,1024, 1);
    reduce_kernel<<<(BB*4096+255)/256,256>>>(P.gates2, P.part, BB*4096, 3, 4095, lbih, lbhh);
    lstm_kernel<<<(BR+255)/256,256>>>(P.gates2, c1, P.hlang, P.clang);

    pack_kernel<<<(BR+255)/256,256>>>(P.hatt, P.catt, P.hlang, P.clang, out, out_size);
}

// round 10
// speedup vs baseline: 3.4392x; 1.1614x over previous
#include <cuda_runtime.h>
#include <cuda_fp16.h>
#include <math.h>
#include <stdint.h>

#define BB 64
#define NN 512
#define RR 1024
#define KTOP 256
#define BR (BB*RR)
#define NGE ((long)BB*NN*RR)

// ---------------- device scratch ----------------
__device__ float g_adj[(long)BB*NN*NN];
__device__ float g_xcat[BB*3072];
__device__ float g_gates[BB*4096];
__device__ float g_gates2[BB*4096];
__device__ float g_part[4*BB*4096];
__device__ float g_ht1[BB*RR];
__device__ float g_ht2[BB*RR];
__device__ float g_pvec[BB*RR];
__device__ float g_srow[BB*NN];
__device__ float g_dvec[BB*NN];
__device__ float g_minv[BB];
__device__ float g_attv[BB*RR];
__device__ float g_xl[BB*2048];
__device__ float g_hatt[BR];
__device__ float g_catt[BR];
__device__ float g_hlang[BR];
__device__ float g_clang[BR];

__device__ __half g_Ph[NGE], g_Pl[NGE];   // GEM -> Z1^T -> X3^T
__device__ __half g_Qh[NGE], g_Ql[NGE];   // E1 -> Z0^T -> X2
__device__ __half g_Sh[NGE], g_Sl[NGE];   // E2 -> X1 -> Z2^T
__device__ __half g_ADJh[(long)BB*NN*NN];  // hi only (A-side of 2-pass)
__device__ __half g_W1h[1048576], g_W1l[1048576];
__device__ __half g_W2h[1048576], g_W2l[1048576];
__device__ __half g_G0h[1048576], g_G0l[1048576];
__device__ __half g_G1h[1048576], g_G1l[1048576];
__device__ __half g_G2h[1048576], g_G2l[1048576];

// ---------------- warp MMA helpers ----------------
__device__ __forceinline__ uint32_t smem_u32(const void* p){
    uint32_t a;
    asm("{ .reg .u64 t; cvta.to.shared.u64 t, %1; cvt.u32.u64 %0, t; }" : "=r"(a) : "l"(p));
    return a;
}
__device__ __forceinline__ uint32_t swz64(uint32_t x){ return x ^ ((x>>3)&0x30u); }
__device__ __forceinline__ void ldm4(uint32_t* r, uint32_t addr){
    asm volatile("ldmatrix.sync.aligned.m8n8.x4.shared.b16 {%0,%1,%2,%3}, [%4];"
        : "=r"(r[0]),"=r"(r[1]),"=r"(r[2]),"=r"(r[3]) : "r"(addr));
}
__device__ __forceinline__ void mma16816(float* d, const uint32_t* a, const uint32_t* b){
    asm volatile("mma.sync.aligned.m16n8k16.row.col.f32.f16.f16.f32 "
        "{%0,%1,%2,%3}, {%4,%5,%6,%7}, {%8,%9}, {%0,%1,%2,%3};"
        : "+f"(d[0]),"+f"(d[1]),"+f"(d[2]),"+f"(d[3])
        : "r"(a[0]),"r"(a[1]),"r"(a[2]),"r"(a[3]), "r"(b[0]),"r"(b[1]));
}
__device__ __forceinline__ void cpasync16(uint32_t dst, const void* src){
    asm volatile("cp.async.cg.shared.global [%0], [%1], 16;" :: "r"(dst), "l"(src));
}

// ---------------- fp16 hi/lo tensor-core GEMM, 3-stage cp.async ----------------
// PASSES=3: C=(Ah+Al)@(Bh+Bl)^T approx (err 2^-22). PASSES=2: C=Ah@(Bh+Bl)^T (err 2^-12).
// K-major, fp32 accum. 128 threads = 4 warps (2x2), warp tile 64x64. BK=32, 3 stages.
#define MMA_SMEM (3*32768+1024)

template<int PASSES>
__global__ void __launch_bounds__(128,2) hmma_gemm(
    const __half* __restrict__ Ah, const __half* __restrict__ Al, int lda, long sA,
    const __half* __restrict__ Bh, const __half* __restrict__ Bl, int ldb, long sB,
    int K, int rowsPerZ, int outMode, int relu,
    float* Cf, int ldc,
    __half* Ch, __half* Cl, int ldch,
    const float* __restrict__ bias, const float* __restrict__ addv,
    const float* __restrict__ rs, const float* __restrict__ ps)
{
    extern __shared__ char smraw[];
    uint32_t sb0 = smem_u32(smraw);
    uint32_t sb  = (sb0 + 1023u) & ~1023u;
    const int tid = threadIdx.x, wid = tid>>5, lane = tid&31;

    const __half* A0 = Ah + blockIdx.z*sA;
    const __half* A1 = (PASSES==3) ? (Al + blockIdx.z*sA) : nullptr;
    const __half* B0 = Bh + blockIdx.z*sB;
    const __half* B1 = Bl + blockIdx.z*sB;
    const int rowBase = blockIdx.y*128, colBase = blockIdx.x*128;
    const int NC = K >> 5;

    const int wr = wid>>1, wc = wid&1;
    const int lr = lane&7, q = lane>>3;
    const int aRowOff = ((q&1)<<3) + lr;
    const int aKbOff  = (q>>1)<<4;
    const int bRowOff = ((q>>1)<<3) + lr;
    const int bKbOff  = (q&1)<<4;

    const int cp_row = tid>>2;
    const int cp_u   = tid&3;

    float acc[4][8][4];
    #pragma unroll
    for (int a=0;a<4;a++)
        #pragma unroll
        for (int b=0;b<8;b++)
            #pragma unroll
            for (int c=0;c<4;c++) acc[a][b][c]=0.f;

    auto load_chunk = [&](int ci, int s){
        const int k0 = ci<<5;
        const uint32_t st = sb + s*32768;
        #pragma unroll
        for (int j=0;j<4;j++){
            int r = cp_row + j*32;
            uint32_t doff = swz64((uint32_t)(r*64 + cp_u*16));
            long aoff = (long)(rowBase+r)*lda + k0 + cp_u*8;
            long boff = (long)(colBase+r)*ldb + k0 + cp_u*8;
            cpasync16(st +         doff, A0 + aoff);
            if (PASSES==3) cpasync16(st + 8192 + doff, A1 + aoff);
            cpasync16(st + 16384 + doff, B0 + boff);
            cpasync16(st + 24576 + doff, B1 + boff);
        }
        asm volatile("cp.async.commit_group;" ::: "memory");
    };

    load_chunk(0, 0);
    if (NC > 1) load_chunk(1, 1);

    int sidx = 0;
    int nidx = (NC > 2) ? 2 : 0;
    for (int i=0;i<NC;i++){
        if (i+1 < NC) asm volatile("cp.async.wait_group 1;" ::: "memory");
        else          asm volatile("cp.async.wait_group 0;" ::: "memory");
        __syncthreads();
        if (i+2 < NC){
            load_chunk(i+2, nidx);
            nidx = (nidx==2)?0:nidx+1;
        }
        const uint32_t st = sb + sidx*32768;
        sidx = (sidx==2)?0:sidx+1;
        #pragma unroll
        for (int ks=0;ks<2;ks++){
            const uint32_t kb = ks<<5;
            uint32_t bh[4][4], bl[4][4], af[4][4];
            #pragma unroll
            for (int t=0;t<4;t++){
                uint32_t ro = (uint32_t)((wc*64 + t*16 + bRowOff)*64) + kb + bKbOff;
                ldm4(bh[t], st + 16384 + swz64(ro));
                ldm4(bl[t], st + 24576 + swz64(ro));
            }
            #pragma unroll
            for (int mi=0;mi<4;mi++){
                uint32_t ro = (uint32_t)((wr*64 + mi*16 + aRowOff)*64) + kb + aKbOff;
                ldm4(af[mi], st + swz64(ro));
            }
            // pass 1: Ah*Bh
            #pragma unroll
            for (int mi=0;mi<4;mi++)
                #pragma unroll
                for (int t=0;t<4;t++){
                    mma16816(acc[mi][2*t],   af[mi], &bh[t][0]);
                    mma16816(acc[mi][2*t+1], af[mi], &bh[t][2]);
                }
            // pass 2: Ah*Bl
            #pragma unroll
            for (int mi=0;mi<4;mi++)
                #pragma unroll
                for (int t=0;t<4;t++){
                    mma16816(acc[mi][2*t],   af[mi], &bl[t][0]);
                    mma16816(acc[mi][2*t+1], af[mi], &bl[t][2]);
                }
            if (PASSES==3){
                #pragma unroll
                for (int mi=0;mi<4;mi++){
                    uint32_t ro = (uint32_t)((wr*64 + mi*16 + aRowOff)*64) + kb + aKbOff;
                    ldm4(af[mi], st + 8192 + swz64(ro));
                }
                #pragma unroll
                for (int mi=0;mi<4;mi++)
                    #pragma unroll
                    for (int t=0;t<4;t++){
                        mma16816(acc[mi][2*t],   af[mi], &bh[t][0]);
                        mma16816(acc[mi][2*t+1], af[mi], &bh[t][2]);
                    }
            }
        }
    }

    // ---- epilogue ----
    const int cpair = (lane&3)*2;
    #pragma unroll
    for (int mi=0;mi<4;mi++){
        #pragma unroll
        for (int rr=0;rr<2;rr++){
            const int r  = rowBase + wr*64 + mi*16 + (lane>>2) + rr*8;
            const int gr = blockIdx.z*rowsPerZ + r;
            const float rsv = rs ? rs[gr] : 1.f;
            const float psv = ps ? ps[gr] : 1.f;
            const float* avp = addv ? addv + (long)(gr>>9)*RR : nullptr;
            #pragma unroll
            for (int ni=0;ni<8;ni++){
                const int c = colBase + wc*64 + ni*8 + cpair;
                float x0 = acc[mi][ni][rr*2+0];
                float x1 = acc[mi][ni][rr*2+1];
                if (avp){ x0 += rsv*avp[c]; x1 += rsv*avp[c+1]; }
                if (bias){ x0 += bias[c]; x1 += bias[c+1]; }
                if (relu){ x0 = fmaxf(x0,0.f); x1 = fmaxf(x1,0.f); }
                x0 *= psv; x1 *= psv;
                if (outMode==0){
                    *(float2*)(Cf + (long)gr*ldc + c) = make_float2(x0,x1);
                } else {
                    __half h0 = __float2half_rn(x0);
                    __half l0 = __float2half_rn(x0-__half2float(h0));
                    __half h1 = __float2half_rn(x1);
                    __half l1 = __float2half_rn(x1-__half2float(h1));
                    if (outMode==1){
                        long o = (long)gr*ldch + c;
                        *(__half2*)(Ch+o) = __halves2half2(h0,h1);
                        *(__half2*)(Cl+o) = __halves2half2(l0,l1);
                    } else { // transposed: out[b][feat][node]
                        long base = (long)(gr>>9)*((long)RR*NN) + (gr&511);
                        long o0 = base + (long)c*NN;
                        Ch[o0]=h0; Cl[o0]=l0;
                        Ch[o0+NN]=h1; Cl[o0+NN]=l1;
                    }
                }
            }
        }
    }
}

// ---------------- FFMA split-K GEMM for small (B=64) matmuls ----------------
template<bool BT>
__global__ void __launch_bounds__(256) gemm_part(
    const float* __restrict__ A,int lda,
    const float* __restrict__ B,int ldb,
    float* __restrict__ C,int ldc,long partStride,int chunkK)
{
    __shared__ float As[16][64];
    __shared__ float Bs[16][64];
    const int tid = threadIdx.x;
    const int rowBase = blockIdx.y*64, colBase = blockIdx.x*64;
    const int kbeg = blockIdx.z*chunkK, kend = kbeg + chunkK;
    const int tx = tid & 15, ty = tid >> 4;
    float acc[4][4];
#pragma unroll
    for (int i=0;i<4;i++)
#pragma unroll
        for (int j=0;j<4;j++) acc[i][j]=0.f;

    for (int k0=kbeg;k0<kend;k0+=16){
#pragma unroll
        for (int i=tid*4;i<64*16;i+=256*4){
            int r=i>>4, kk=i&15;
            float4 v = *(const float4*)(A + (long)(rowBase+r)*lda + k0 + kk);
            As[kk+0][r]=v.x; As[kk+1][r]=v.y; As[kk+2][r]=v.z; As[kk+3][r]=v.w;
        }
        if (BT){
#pragma unroll
            for (int i=tid*4;i<64*16;i+=256*4){
                int r=i>>4, kk=i&15;
                float4 v = *(const float4*)(B + (long)(colBase+r)*ldb + k0 + kk);
                Bs[kk+0][r]=v.x; Bs[kk+1][r]=v.y; Bs[kk+2][r]=v.z; Bs[kk+3][r]=v.w;
            }
        } else {
#pragma unroll
            for (int i=tid*4;i<16*64;i+=256*4){
                int r=i>>6, cc=i&63;
                *(float4*)&Bs[r][cc] = *(const float4*)(B + (long)(k0+r)*ldb + colBase + cc);
            }
        }
        __syncthreads();
#pragma unroll
        for (int k=0;k<16;k++){
            float a[4], b[4];
            *(float4*)a = *(const float4*)&As[k][ty*4];
            *(float4*)b = *(const float4*)&Bs[k][tx*4];
#pragma unroll
            for (int i=0;i<4;i++)
#pragma unroll
                for (int j=0;j<4;j++) acc[i][j] = fmaf(a[i], b[j], acc[i][j]);
        }
        __syncthreads();
    }
    float* Cp = C + (long)blockIdx.z*partStride;
#pragma unroll
    for (int i=0;i<4;i++){
        int r = rowBase + ty*4 + i;
#pragma unroll
        for (int j=0;j<4;j++)
            Cp[(long)r*ldc + colBase + tx*4 + j] = acc[i][j];
    }
}
static void sgemm(bool BT,const float* A,int lda,const float* B,int ldb,float* Cpart,int ldc,
                  int M,int N,int K,int splits){
    dim3 g(N/64, M/64, splits);
    int chunkK = K/splits;
    if (BT) gemm_part<true ><<<g,256>>>(A,lda,B,ldb,Cpart,ldc,(long)M*ldc,chunkK);
    else    gemm_part<false><<<g,256>>>(A,lda,B,ldb,Cpart,ldc,(long)M*ldc,chunkK);
}
__global__ void reduce_kernel(float* dst,const float* src,long len,int splits,int colmask,
                              const float* b1,const float* b2){
    long i = (long)blockIdx.x*blockDim.x+threadIdx.x;
    if (i >= len) return;
    float s = 0.f;
    for (int z=0;z<splits;z++) s += src[z*len+i];
    int col = (int)(i & colmask);
    if (b1) s += b1[col];
    if (b2) s += b2[col];
    dst[i] = s;
}

// ---------------- conversions ----------------
__device__ __forceinline__ void split1(float v, __half& h, __half& l){
    h = __float2half_rn(v);
    l = __float2half_rn(v - __half2float(h));
}

__global__ void conv_mask_kernel(const float* __restrict__ src, const float* __restrict__ mask,
                                 __half* __restrict__ dh, __half* __restrict__ dl, long n4){
    long i = (long)blockIdx.x*blockDim.x + threadIdx.x;
    if (i >= n4) return;
    float4 v = ((const float4*)src)[i];
    float m = mask[i >> 8];
    v.x*=m; v.y*=m; v.z*=m; v.w*=m;
    __align__(8) __half h[4], l[4];
    split1(v.x,h[0],l[0]); split1(v.y,h[1],l[1]); split1(v.z,h[2],l[2]); split1(v.w,h[3],l[3]);
    ((uint2*)dh)[i] = *(uint2*)h;
    ((uint2*)dl)[i] = *(uint2*)l;
}

__global__ void conv_slice_kernel(const float* __restrict__ src, int ldsrc,
                                  __half* __restrict__ dh, __half* __restrict__ dl,
                                  int cols, int n4){
    int i = blockIdx.x*blockDim.x + threadIdx.x;
    if (i >= n4) return;
    int c4pr = cols/4;
    int r = i / c4pr, c4 = i % c4pr;
    float4 v = *(const float4*)(src + (long)r*ldsrc + c4*4);
    __align__(8) __half h[4], l[4];
    split1(v.x,h[0],l[0]); split1(v.y,h[1],l[1]); split1(v.z,h[2],l[2]); split1(v.w,h[3],l[3]);
    long o = (long)r*c4pr + c4;
    ((uint2*)dh)[o] = *(uint2*)h;
    ((uint2*)dl)[o] = *(uint2*)l;
}

// transpose+convert (weights): src [rows,cols] fp32 -> dst [cols,rows] half hi/lo
__global__ void tconv_kernel(const float* __restrict__ src, int rows, int cols,
                             __half* __restrict__ dh, __half* __restrict__ dl){
    __shared__ float t[32][33];
    int r0 = blockIdx.y*32, c0 = blockIdx.x*32;
    int tx = threadIdx.x, ty = threadIdx.y;
    for (int i=ty;i<32;i+=8)
        t[i][tx] = src[(long)(r0+i)*cols + c0+tx];
    __syncthreads();
    for (int i=ty;i<32;i+=8){
        float v = t[tx][i];
        __half h, l; split1(v, h, l);
        long o = (long)(c0+i)*rows + r0+tx;
        dh[o] = h; dl[o] = l;
    }
}

// ---------------- pointwise / reductions ----------------
__device__ __forceinline__ float sigm(float x){ return 1.f/(1.f+__expf(-x)); }

__global__ void concat3_kernel(const float* a,const float* b,const float* c,float* out){
    int idx = blockIdx.x*blockDim.x+threadIdx.x;
    if (idx >= BB*3072) return;
    int bb = idx/3072, j = idx%3072;
    out[idx] = (j<1024) ? a[bb*1024+j] : (j<2048 ? b[bb*1024+j-1024] : c[bb*1024+j-2048]);
}
__global__ void concat2_kernel(const float* a,const float* b,float* out){
    int idx = blockIdx.x*blockDim.x+threadIdx.x;
    if (idx >= BB*2048) return;
    int bb = idx/2048, j = idx%2048;
    out[idx] = (j<1024) ? a[bb*1024+j] : b[bb*1024+j-1024];
}
__global__ void lstm_kernel(const float* gates,const float* c_prev,float* h_out,float* c_out){
    int idx = blockIdx.x*blockDim.x+threadIdx.x;
    if (idx >= BR) return;
    int bb = idx >> 10, r = idx & 1023;
    const float* g = gates + bb*4096;
    float c = sigm(g[1024+r])*c_prev[idx] + sigm(g[r])*tanhf(g[2048+r]);
    h_out[idx] = sigm(g[3072+r])*tanhf(c);
    c_out[idx] = c;
}
__global__ void batchmin_kernel(const float* Adj,float* minv){
    __shared__ float sm[1024];
    const float* a = Adj + (long)blockIdx.x*NN*NN;
    float mn = INFINITY;
    for (int i=threadIdx.x;i<NN*NN;i+=1024) mn = fminf(mn, a[i]);
    sm[threadIdx.x]=mn; __syncthreads();
    for (int s=512;s>0;s>>=1){ if (threadIdx.x<s) sm[threadIdx.x]=fminf(sm[threadIdx.x],sm[threadIdx.x+s]); __syncthreads(); }
    if (threadIdx.x==0) minv[blockIdx.x]=sm[0];
}
__global__ void __launch_bounds__(512) topk_kernel(float* Adj,const float* minv,
                                                   const float* mask,float* dvec){
    __shared__ unsigned long long keys[NN];
    __shared__ float red[NN];
    int row = blockIdx.x, t = threadIdx.x, bb = row >> 9;
    float mrow = mask[row];
    float* arow = Adj + (long)row*NN;
    float v = (arow[t] - minv[bb]) * mrow;
    keys[t] = ((unsigned long long)__float_as_uint(v) << 32) | (unsigned)(NN-1-t);
    __syncthreads();
    for (unsigned k2=2;k2<=NN;k2<<=1)
        for (unsigned j=k2>>1;j>0;j>>=1){
            unsigned ixj = t ^ j;
            if (ixj > (unsigned)t){
                unsigned long long x=keys[t], y=keys[ixj];
                bool desc = ((t & k2) == 0);
                if (desc ? (x<y) : (x>y)){ keys[t]=y; keys[ixj]=x; }
            }
            __syncthreads();
        }
    unsigned long long kk = keys[t];
    arow[t] = 0.f;
    __syncthreads();
    float s = 0.f;
    if (t < KTOP){
        int col = (NN-1) - (int)(unsigned)(kk & 0xffffffffu);
        float val = __uint_as_float((unsigned)(kk >> 32));
        arow[col] = val;
        s = val;
    }
    red[t]=s; __syncthreads();
    for (int st=NN/2;st>0;st>>=1){ if (t<st) red[t]+=red[t+st]; __syncthreads(); }
    if (t==0) dvec[row] = (red[0] > 0.f) ? rsqrtf(red[0]) : 0.f;
}
// fused: Adj *= d_r*d_c, write fp16 hi (A-side of 2-pass), srow[r] = sum_c Adj_norm*mask_c
__global__ void rowfinal_kernel(const float* __restrict__ adj, const float* __restrict__ dvec,
                                const float* __restrict__ mask,
                                __half* __restrict__ Ah, float* __restrict__ srow){
    int row = blockIdx.x*8 + (threadIdx.x>>5);
    int lane = threadIdx.x & 31;
    int bb = row >> 9;
    const float* a = adj + (long)row*NN;
    const float dr = dvec[row];
    const float* dc = dvec + (bb<<9);
    const float* m  = mask + (bb<<9);
    float s = 0.f;
    for (int k=lane*4; k<NN; k+=128){
        float4 v  = *(const float4*)(a+k);
        float4 d4 = *(const float4*)(dc+k);
        float4 m4 = *(const float4*)(m+k);
        float x0=v.x*dr*d4.x, x1=v.y*dr*d4.y, x2=v.z*dr*d4.z, x3=v.w*dr*d4.w;
        s += x0*m4.x + x1*m4.y + x2*m4.z + x3*m4.w;
        __align__(8) __half h[4];
        h[0]=__float2half_rn(x0); h[1]=__float2half_rn(x1);
        h[2]=__float2half_rn(x2); h[3]=__float2half_rn(x3);
        long o = ((long)row*NN + k) >> 2;
        ((uint2*)Ah)[o] = *(uint2*)h;
    }
    for (int o=16;o;o>>=1) s += __shfl_xor_sync(0xffffffffu, s, o);
    if (lane==0) srow[row] = s;
}
__global__ void colmaxT_kernel(const __half* Xh,const __half* Xl,float* att){
    int warp = (blockIdx.x*blockDim.x+threadIdx.x) >> 5;
    int lane = threadIdx.x & 31;
    if (warp >= BB*RR) return;
    long base = (long)warp*NN;
    float mx = -INFINITY;
    for (int k=lane;k<NN;k+=32)
        mx = fmaxf(mx, __half2float(Xh[base+k]) + __half2float(Xl[base+k]));
    for (int o=16;o;o>>=1) mx = fmaxf(mx, __shfl_xor_sync(0xffffffffu, mx, o));
    if (lane==0) att[warp] = mx;
}
__global__ void pack_kernel(const float* hatt,const float* catt,
                            const float* hlang,const float* clang,float* out,int out_size){
    int i = blockIdx.x*blockDim.x+threadIdx.x;
    if (i >= BR) return;
    out[i] = hlang[i];
    if (out_size >= 5*BR){
        out[1*BR+i] = hatt[i];
        out[2*BR+i] = hlang[i];
        out[3*BR+i] = catt[i];
        out[4*BR+i] = clang[i];
    }
}

// ---------------- host driver ----------------
struct Ptrs {
    float *adj,*xcat,*gates,*gates2,*part,*ht1,*ht2,*pvec,*srow,*dvec,*minv,*attv,*xl,*hatt,*catt,*hlang,*clang;
    __half *Ph,*Pl,*Qh,*Ql,*Sh,*Sl,*ADJh;
    __half *W1h,*W1l,*W2h,*W2l,*G0h,*G0l,*G1h,*G1l,*G2h,*G2l;
};
static Ptrs P;
static bool g_init = false;

extern "C" void kernel_launch(void* const* d_in, const int* in_sizes, int n_in,
                              void* d_out, int out_size)
{
    const float* xt   = (const float*)d_in[0];
    const float* fc   = (const float*)d_in[1];
    const float* ge   = (const float*)d_in[2];
    const float* sh   = (const float*)d_in[4];
    const float* sc   = (const float*)d_in[5];
    const float* mask = (const float*)d_in[6];
    const float* aWih = (const float*)d_in[7];
    const float* aWhh = (const float*)d_in[8];
    const float* abih = (const float*)d_in[9];
    const float* abhh = (const float*)d_in[10];
    const float* lWih = (const float*)d_in[11];
    const float* lWhh = (const float*)d_in[12];
    const float* lbih = (const float*)d_in[13];
    const float* lbhh = (const float*)d_in[14];
    const float* e1W  = (const float*)d_in[15];
    const float* e1b  = (const float*)d_in[16];
    const float* e2W  = (const float*)d_in[17];
    const float* e2b  = (const float*)d_in[18];
    const float* gW0  = (const float*)d_in[19];
    const float* gb0  = (const float*)d_in[20];
    const float* gW1  = (const float*)d_in[21];
    const float* gb1  = (const float*)d_in[22];
    const float* gW2  = (const float*)d_in[23];
    const float* gb2  = (const float*)d_in[24];
    (void)in_sizes; (void)n_in;
    float* out = (float*)d_out;

    if (!g_init){
        cudaGetSymbolAddress((void**)&P.adj,  g_adj);
        cudaGetSymbolAddress((void**)&P.xcat, g_xcat);
        cudaGetSymbolAddress((void**)&P.gates,g_gates);
        cudaGetSymbolAddress((void**)&P.gates2,g_gates2);
        cudaGetSymbolAddress((void**)&P.part, g_part);
        cudaGetSymbolAddress((void**)&P.ht1,  g_ht1);
        cudaGetSymbolAddress((void**)&P.ht2,  g_ht2);
        cudaGetSymbolAddress((void**)&P.pvec, g_pvec);
        cudaGetSymbolAddress((void**)&P.srow, g_srow);
        cudaGetSymbolAddress((void**)&P.dvec, g_dvec);
        cudaGetSymbolAddress((void**)&P.minv, g_minv);
        cudaGetSymbolAddress((void**)&P.attv, g_attv);
        cudaGetSymbolAddress((void**)&P.xl,   g_xl);
        cudaGetSymbolAddress((void**)&P.hatt, g_hatt);
        cudaGetSymbolAddress((void**)&P.catt, g_catt);
        cudaGetSymbolAddress((void**)&P.hlang,g_hlang);
        cudaGetSymbolAddress((void**)&P.clang,g_clang);
        cudaGetSymbolAddress((void**)&P.Ph, g_Ph); cudaGetSymbolAddress((void**)&P.Pl, g_Pl);
        cudaGetSymbolAddress((void**)&P.Qh, g_Qh); cudaGetSymbolAddress((void**)&P.Ql, g_Ql);
        cudaGetSymbolAddress((void**)&P.Sh, g_Sh); cudaGetSymbolAddress((void**)&P.Sl, g_Sl);
        cudaGetSymbolAddress((void**)&P.ADJh, g_ADJh);
        cudaGetSymbolAddress((void**)&P.W1h, g_W1h); cudaGetSymbolAddress((void**)&P.W1l, g_W1l);
        cudaGetSymbolAddress((void**)&P.W2h, g_W2h); cudaGetSymbolAddress((void**)&P.W2l, g_W2l);
        cudaGetSymbolAddress((void**)&P.G0h, g_G0h); cudaGetSymbolAddress((void**)&P.G0l, g_G0l);
        cudaGetSymbolAddress((void**)&P.G1h, g_G1h); cudaGetSymbolAddress((void**)&P.G1l, g_G1l);
        cudaGetSymbolAddress((void**)&P.G2h, g_G2h); cudaGetSymbolAddress((void**)&P.G2l, g_G2l);
        cudaFuncSetAttribute(hmma_gemm<3>, cudaFuncAttributeMaxDynamicSharedMemorySize, MMA_SMEM);
        cudaFuncSetAttribute(hmma_gemm<2>, cudaFuncAttributeMaxDynamicSharedMemorySize, MMA_SMEM);
        g_init = true;
    }

    const float* prev_h = sh + BR;
    const float* h0 = sh;
    const float* c0 = sc;
    const float* c1 = sc + BR;

    // ---- conversions ----
    conv_mask_kernel<<<(int)((NGE/4+255)/256),256>>>(ge, mask, P.Ph, P.Pl, NGE/4);
    conv_slice_kernel<<<(1048576/4+255)/256,256>>>(e1W, 2048, P.W1h, P.W1l, 1024, 1048576/4);
    conv_slice_kernel<<<(1048576/4+255)/256,256>>>(e2W, 2048, P.W2h, P.W2l, 1024, 1048576/4);
    tconv_kernel<<<dim3(32,32),dim3(32,8)>>>(gW0, 1024, 1024, P.G0h, P.G0l);
    tconv_kernel<<<dim3(32,32),dim3(32,8)>>>(gW1, 1024, 1024, P.G1h, P.G1l);
    tconv_kernel<<<dim3(32,32),dim3(32,8)>>>(gW2, 1024, 1024, P.G2h, P.G2l);

    // ---- attention LSTM (split-K FFMA) ----
    concat3_kernel<<<(BB*3072+255)/256,256>>>(prev_h, fc, xt, P.xcat);
    sgemm(true, P.xcat,3072, aWih,3072, P.part,            4096, BB,4096,3072, 3);
    sgemm(true, h0,1024,     aWhh,1024, P.part+3*BB*4096,  4096, BB,4096,1024, 1);
    reduce_kernel<<<(BB*4096+255)/256,256>>>(P.gates, P.part, BB*4096, 4, 4095, abih, abhh);
    lstm_kernel<<<(BR+255)/256,256>>>(P.gates, c0, P.hatt, P.catt);

    // ---- h-terms (split-K FFMA) ----
    sgemm(true, P.hatt,1024, e1W+1024,2048, P.part, 1024, BB,1024,1024, 4);
    reduce_kernel<<<(BB*1024+255)/256,256>>>(P.ht1, P.part, BB*1024, 4, 1023, nullptr, nullptr);
    sgemm(true, P.hatt,1024, e2W+1024,2048, P.part, 1024, BB,1024,1024, 4);
    reduce_kernel<<<(BB*1024+255)/256,256>>>(P.ht2, P.part, BB*1024, 4, 1023, nullptr, nullptr);
    sgemm(false, prev_h,1024, gW0+1024*1024,1024, P.part, 1024, BB,1024,1024, 4);
    reduce_kernel<<<(BB*1024+255)/256,256>>>(P.pvec, P.part, BB*1024, 4, 1023, nullptr, nullptr);

    // ---- E1/E2 (3-pass: protects topk ranking) ----
    hmma_gemm<3><<<dim3(8,256,1),128,MMA_SMEM>>>(P.Ph,P.Pl,1024,0, P.W1h,P.W1l,1024,0,
        1024, 0, 1, 0, nullptr,0, P.Qh,P.Ql,1024, e1b, P.ht1, mask, nullptr);
    hmma_gemm<3><<<dim3(8,256,1),128,MMA_SMEM>>>(P.Ph,P.Pl,1024,0, P.W2h,P.W2l,1024,0,
        1024, 0, 1, 0, nullptr,0, P.Sh,P.Sl,1024, e2b, P.ht2, mask, nullptr);

    // ---- Adj = E1 @ E2^T (3-pass) ----
    hmma_gemm<3><<<dim3(4,4,64),128,MMA_SMEM>>>(P.Qh,P.Ql,1024,(long)NN*RR, P.Sh,P.Sl,1024,(long)NN*RR,
        1024, 512, 0, 0, P.adj,512, nullptr,nullptr,0, nullptr,nullptr,nullptr,nullptr);

    // ---- Adj post-processing ----
    batchmin_kernel<<<BB,1024>>>(P.adj, P.minv);
    topk_kernel<<<BB*NN,512>>>(P.adj, P.minv, mask, P.dvec);
    rowfinal_kernel<<<BB*NN/8,256>>>(P.adj, P.dvec, mask, P.ADJh, P.srow);

    // ---- GCN layer 0 (2-pass): Z0 = GEM@G0 (->Q^T), X1 = relu(Adj@Z0 + srow*pvec + b0)*m (->S)
    hmma_gemm<2><<<dim3(8,256,1),128,MMA_SMEM>>>(P.Ph,P.Ph,1024,0, P.G0h,P.G0l,1024,0,
        1024, 0, 2, 0, nullptr,0, P.Qh,P.Ql,0, nullptr, nullptr, nullptr, nullptr);
    hmma_gemm<2><<<dim3(8,4,64),128,MMA_SMEM>>>(P.ADJh,P.ADJh,512,(long)NN*NN, P.Qh,P.Ql,512,(long)RR*NN,
        512, 512, 1, 1, nullptr,0, P.Sh,P.Sl,1024, gb0, P.pvec, P.srow, mask);

    // ---- GCN layer 1 (2-pass): Z1 = X1@G1 (->P^T), X2 = relu(Adj@Z1 + b1)*m (->Q)
    hmma_gemm<2><<<dim3(8,256,1),128,MMA_SMEM>>>(P.Sh,P.Sh,1024,0, P.G1h,P.G1l,1024,0,
        1024, 0, 2, 0, nullptr,0, P.Ph,P.Pl,0, nullptr, nullptr, nullptr, nullptr);
    hmma_gemm<2><<<dim3(8,4,64),128,MMA_SMEM>>>(P.ADJh,P.ADJh,512,(long)NN*NN, P.Ph,P.Pl,512,(long)RR*NN,
        512, 512, 1, 1, nullptr,0, P.Qh,P.Ql,1024, gb1, nullptr, nullptr, mask);

    // ---- GCN layer 2 (2-pass): Z2 = X2@G2 (->S^T), X3^T = relu(Adj@Z2 + b2)*m (->P^T)
    hmma_gemm<2><<<dim3(8,256,1),128,MMA_SMEM>>>(P.Qh,P.Qh,1024,0, P.G2h,P.G2l,1024,0,
        1024, 0, 2, 0, nullptr,0, P.Sh,P.Sl,0, nullptr, nullptr, nullptr, nullptr);
    hmma_gemm<2><<<dim3(8,4,64),128,MMA_SMEM>>>(P.ADJh,P.ADJh,512,(long)NN*NN, P.Sh,P.Sl,512,(long)RR*NN,
        512, 512, 2, 1, nullptr,0, P.Ph,P.Pl,0, gb2, nullptr, nullptr, mask);

    // ---- att = max over nodes (X3^T contiguous) ----
    colmaxT_kernel<<<(BB*RR*32+255)/256,256>>>(P.Ph, P.Pl, P.attv);

    // ---- language LSTM (split-K FFMA) ----
    concat2_kernel<<<(BB*2048+255)/256,256>>>(P.attv, P.hatt, P.xl);
    sgemm(true, P.xl,2048,   lWih,2048, P.part,           4096, BB,4096,2048, 2);
    sgemm(true, prev_h,1024, lWhh,1024, P.part+2*BB*4096, 4096, BB,4096,1024, 1);
    reduce_kernel<<<(BB*4096+255)/256,256>>>(P.gates2, P.part, BB*4096, 3, 4095, lbih, lbhh);
    lstm_kernel<<<(BR+255)/256,256>>>(P.gates2, c1, P.hlang, P.clang);

    pack_kernel<<<(BR+255)/256,256>>>(P.hatt, P.catt, P.hlang, P.clang, out, out_size);
}

// round 11
// speedup vs baseline: 4.2988x; 1.2500x over previous
#include <cuda_runtime.h>
#include <cuda_fp16.h>
#include <math.h>
#include <stdint.h>

#define BB 64
#define NN 512
#define RR 1024
#define KTOP 256
#define BR (BB*RR)
#define NGE ((long)BB*NN*RR)

// ---------------- device scratch ----------------
__device__ float g_adj[(long)BB*NN*NN];
__device__ unsigned g_minu[BB];
__device__ float g_xcat[BB*3072];
__device__ float g_gates[BB*4096];
__device__ float g_gates2[BB*4096];
__device__ float g_part[4*BB*4096];
__device__ float g_ht1[BB*RR];
__device__ float g_ht2[BB*RR];
__device__ float g_pvec[BB*RR];
__device__ float g_srow[BB*NN];
__device__ float g_dvec[BB*NN];
__device__ float g_attv[BB*RR];
__device__ float g_xl[BB*2048];
__device__ float g_hatt[BR];
__device__ float g_catt[BR];
__device__ float g_hlang[BR];
__device__ float g_clang[BR];

__device__ __half g_Ph[NGE], g_Pl[NGE];   // GEM -> Z1^T -> X3^T(hi)
__device__ __half g_Qh[NGE], g_Ql[NGE];   // E1 -> Z0^T -> X2
__device__ __half g_Sh[NGE], g_Sl[NGE];   // E2 -> X1 -> Z2^T
__device__ __half g_ADJh[(long)BB*NN*NN];
__device__ __half g_W1h[1048576], g_W1l[1048576];
__device__ __half g_W2h[1048576], g_W2l[1048576];
__device__ __half g_G0h[1048576];
__device__ __half g_G1h[1048576];
__device__ __half g_G2h[1048576];

// monotone uint encoding for float ordering
__device__ __forceinline__ unsigned fenc(float f){
    unsigned u = __float_as_uint(f);
    return (u & 0x80000000u) ? ~u : (u | 0x80000000u);
}
__device__ __forceinline__ float fdec(unsigned v){
    unsigned u = (v & 0x80000000u) ? (v ^ 0x80000000u) : ~v;
    return __uint_as_float(u);
}

// ---------------- warp MMA helpers ----------------
__device__ __forceinline__ uint32_t smem_u32(const void* p){
    uint32_t a;
    asm("{ .reg .u64 t; cvta.to.shared.u64 t, %1; cvt.u32.u64 %0, t; }" : "=r"(a) : "l"(p));
    return a;
}
__device__ __forceinline__ uint32_t swz64(uint32_t x){ return x ^ ((x>>3)&0x30u); }
__device__ __forceinline__ void ldm4(uint32_t* r, uint32_t addr){
    asm volatile("ldmatrix.sync.aligned.m8n8.x4.shared.b16 {%0,%1,%2,%3}, [%4];"
        : "=r"(r[0]),"=r"(r[1]),"=r"(r[2]),"=r"(r[3]) : "r"(addr));
}
__device__ __forceinline__ void mma16816(float* d, const uint32_t* a, const uint32_t* b){
    asm volatile("mma.sync.aligned.m16n8k16.row.col.f32.f16.f16.f32 "
        "{%0,%1,%2,%3}, {%4,%5,%6,%7}, {%8,%9}, {%0,%1,%2,%3};"
        : "+f"(d[0]),"+f"(d[1]),"+f"(d[2]),"+f"(d[3])
        : "r"(a[0]),"r"(a[1]),"r"(a[2]),"r"(a[3]), "r"(b[0]),"r"(b[1]));
}
__device__ __forceinline__ void cpasync16(uint32_t dst, const void* src){
    asm volatile("cp.async.cg.shared.global [%0], [%1], 16;" :: "r"(dst), "l"(src));
}

// ---------------- fp16 hi/lo tensor-core GEMM, 3-stage cp.async ----------------
// PASSES=3: (Ah+Al)@(Bh+Bl)^T approx. PASSES=2: Ah@(Bh+Bl)^T. PASSES=1: Ah@Bh^T.
// K-major, fp32 accum. 128 threads = 4 warps (2x2), warp tile 64x64. BK=32, 3 stages.
#define MMA_SMEM (3*32768+1024)

template<int PASSES>
__global__ void __launch_bounds__(128,2) hmma_gemm(
    const __half* __restrict__ Ah, const __half* __restrict__ Al, int lda, long sA,
    const __half* __restrict__ Bh, const __half* __restrict__ Bl, int ldb, long sB,
    int K, int rowsPerZ, int outMode, int relu,
    float* Cf, int ldc, unsigned* minu,
    __half* Ch, __half* Cl, int ldch,
    const float* __restrict__ bias, const float* __restrict__ addv,
    const float* __restrict__ rs, const float* __restrict__ ps)
{
    extern __shared__ char smraw[];
    uint32_t sb0 = smem_u32(smraw);
    uint32_t sb  = (sb0 + 1023u) & ~1023u;
    const int tid = threadIdx.x, wid = tid>>5, lane = tid&31;

    const __half* A0 = Ah + blockIdx.z*sA;
    const __half* A1 = (PASSES==3) ? (Al + blockIdx.z*sA) : nullptr;
    const __half* B0 = Bh + blockIdx.z*sB;
    const __half* B1 = (PASSES>=2) ? (Bl + blockIdx.z*sB) : nullptr;
    const int rowBase = blockIdx.y*128, colBase = blockIdx.x*128;
    const int NC = K >> 5;

    const int wr = wid>>1, wc = wid&1;
    const int lr = lane&7, q = lane>>3;
    const int aRowOff = ((q&1)<<3) + lr;
    const int aKbOff  = (q>>1)<<4;
    const int bRowOff = ((q>>1)<<3) + lr;
    const int bKbOff  = (q&1)<<4;

    const int cp_row = tid>>2;
    const int cp_u   = tid&3;

    float acc[4][8][4];
    #pragma unroll
    for (int a=0;a<4;a++)
        #pragma unroll
        for (int b=0;b<8;b++)
            #pragma unroll
            for (int c=0;c<4;c++) acc[a][b][c]=0.f;

    auto load_chunk = [&](int ci, int s){
        const int k0 = ci<<5;
        const uint32_t st = sb + s*32768;
        #pragma unroll
        for (int j=0;j<4;j++){
            int r = cp_row + j*32;
            uint32_t doff = swz64((uint32_t)(r*64 + cp_u*16));
            long aoff = (long)(rowBase+r)*lda + k0 + cp_u*8;
            long boff = (long)(colBase+r)*ldb + k0 + cp_u*8;
            cpasync16(st +         doff, A0 + aoff);
            if (PASSES==3) cpasync16(st + 8192 + doff, A1 + aoff);
            cpasync16(st + 16384 + doff, B0 + boff);
            if (PASSES>=2) cpasync16(st + 24576 + doff, B1 + boff);
        }
        asm volatile("cp.async.commit_group;" ::: "memory");
    };

    load_chunk(0, 0);
    if (NC > 1) load_chunk(1, 1);

    int sidx = 0;
    int nidx = (NC > 2) ? 2 : 0;
    for (int i=0;i<NC;i++){
        if (i+1 < NC) asm volatile("cp.async.wait_group 1;" ::: "memory");
        else          asm volatile("cp.async.wait_group 0;" ::: "memory");
        __syncthreads();
        if (i+2 < NC){
            load_chunk(i+2, nidx);
            nidx = (nidx==2)?0:nidx+1;
        }
        const uint32_t st = sb + sidx*32768;
        sidx = (sidx==2)?0:sidx+1;
        #pragma unroll
        for (int ks=0;ks<2;ks++){
            const uint32_t kb = ks<<5;
            uint32_t bh[4][4], bl[4][4], af[4][4];
            #pragma unroll
            for (int t=0;t<4;t++){
                uint32_t ro = (uint32_t)((wc*64 + t*16 + bRowOff)*64) + kb + bKbOff;
                ldm4(bh[t], st + 16384 + swz64(ro));
                if (PASSES>=2) ldm4(bl[t], st + 24576 + swz64(ro));
            }
            #pragma unroll
            for (int mi=0;mi<4;mi++){
                uint32_t ro = (uint32_t)((wr*64 + mi*16 + aRowOff)*64) + kb + aKbOff;
                ldm4(af[mi], st + swz64(ro));
            }
            #pragma unroll
            for (int mi=0;mi<4;mi++)
                #pragma unroll
                for (int t=0;t<4;t++){
                    mma16816(acc[mi][2*t],   af[mi], &bh[t][0]);
                    mma16816(acc[mi][2*t+1], af[mi], &bh[t][2]);
                }
            if (PASSES>=2){
                #pragma unroll
                for (int mi=0;mi<4;mi++)
                    #pragma unroll
                    for (int t=0;t<4;t++){
                        mma16816(acc[mi][2*t],   af[mi], &bl[t][0]);
                        mma16816(acc[mi][2*t+1], af[mi], &bl[t][2]);
                    }
            }
            if (PASSES==3){
                #pragma unroll
                for (int mi=0;mi<4;mi++){
                    uint32_t ro = (uint32_t)((wr*64 + mi*16 + aRowOff)*64) + kb + aKbOff;
                    ldm4(af[mi], st + 8192 + swz64(ro));
                }
                #pragma unroll
                for (int mi=0;mi<4;mi++)
                    #pragma unroll
                    for (int t=0;t<4;t++){
                        mma16816(acc[mi][2*t],   af[mi], &bh[t][0]);
                        mma16816(acc[mi][2*t+1], af[mi], &bh[t][2]);
                    }
            }
        }
    }

    // ---- epilogue ----
    const int cpair = (lane&3)*2;
    float lmin = INFINITY;
    #pragma unroll
    for (int mi=0;mi<4;mi++){
        #pragma unroll
        for (int rr=0;rr<2;rr++){
            const int r  = rowBase + wr*64 + mi*16 + (lane>>2) + rr*8;
            const int gr = blockIdx.z*rowsPerZ + r;
            const float rsv = rs ? rs[gr] : 1.f;
            const float psv = ps ? ps[gr] : 1.f;
            const float* avp = addv ? addv + (long)(gr>>9)*RR : nullptr;
            #pragma unroll
            for (int ni=0;ni<8;ni++){
                const int c = colBase + wc*64 + ni*8 + cpair;
                float x0 = acc[mi][ni][rr*2+0];
                float x1 = acc[mi][ni][rr*2+1];
                if (avp){ x0 += rsv*avp[c]; x1 += rsv*avp[c+1]; }
                if (bias){ x0 += bias[c]; x1 += bias[c+1]; }
                if (relu){ x0 = fmaxf(x0,0.f); x1 = fmaxf(x1,0.f); }
                x0 *= psv; x1 *= psv;
                if (outMode==0){
                    *(float2*)(Cf + (long)gr*ldc + c) = make_float2(x0,x1);
                    lmin = fminf(lmin, fminf(x0,x1));
                } else {
                    __half h0 = __float2half_rn(x0);
                    __half h1 = __float2half_rn(x1);
                    if (outMode==1){
                        long o = (long)gr*ldch + c;
                        *(__half2*)(Ch+o) = __halves2half2(h0,h1);
                        if (Cl){
                            __half l0 = __float2half_rn(x0-__half2float(h0));
                            __half l1 = __float2half_rn(x1-__half2float(h1));
                            *(__half2*)(Cl+o) = __halves2half2(l0,l1);
                        }
                    } else { // transposed: out[b][feat][node]
                        long base = (long)(gr>>9)*((long)RR*NN) + (gr&511);
                        long o0 = base + (long)c*NN;
                        Ch[o0]=h0; Ch[o0+NN]=h1;
                        if (Cl){
                            Cl[o0]   = __float2half_rn(x0-__half2float(h0));
                            Cl[o0+NN]= __float2half_rn(x1-__half2float(h1));
                        }
                    }
                }
            }
        }
    }
    if (outMode==0 && minu){
        #pragma unroll
        for (int o=16;o;o>>=1) lmin = fminf(lmin, __shfl_xor_sync(0xffffffffu, lmin, o));
        if (lane==0) atomicMin(&minu[blockIdx.z], fenc(lmin));
    }
}

// ---------------- FFMA split-K GEMM for small (B=64) matmuls ----------------
template<bool BT>
__global__ void __launch_bounds__(256) gemm_part(
    const float* __restrict__ A,int lda,
    const float* __restrict__ B,int ldb,
    float* __restrict__ C,int ldc,long partStride,int chunkK)
{
    __shared__ float As[16][64];
    __shared__ float Bs[16][64];
    const int tid = threadIdx.x;
    const int rowBase = blockIdx.y*64, colBase = blockIdx.x*64;
    const int kbeg = blockIdx.z*chunkK, kend = kbeg + chunkK;
    const int tx = tid & 15, ty = tid >> 4;
    float acc[4][4];
#pragma unroll
    for (int i=0;i<4;i++)
#pragma unroll
        for (int j=0;j<4;j++) acc[i][j]=0.f;

    for (int k0=kbeg;k0<kend;k0+=16){
#pragma unroll
        for (int i=tid*4;i<64*16;i+=256*4){
            int r=i>>4, kk=i&15;
            float4 v = *(const float4*)(A + (long)(rowBase+r)*lda + k0 + kk);
            As[kk+0][r]=v.x; As[kk+1][r]=v.y; As[kk+2][r]=v.z; As[kk+3][r]=v.w;
        }
        if (BT){
#pragma unroll
            for (int i=tid*4;i<64*16;i+=256*4){
                int r=i>>4, kk=i&15;
                float4 v = *(const float4*)(B + (long)(colBase+r)*ldb + k0 + kk);
                Bs[kk+0][r]=v.x; Bs[kk+1][r]=v.y; Bs[kk+2][r]=v.z; Bs[kk+3][r]=v.w;
            }
        } else {
#pragma unroll
            for (int i=tid*4;i<16*64;i+=256*4){
                int r=i>>6, cc=i&63;
                *(float4*)&Bs[r][cc] = *(const float4*)(B + (long)(k0+r)*ldb + colBase + cc);
            }
        }
        __syncthreads();
#pragma unroll
        for (int k=0;k<16;k++){
            float a[4], b[4];
            *(float4*)a = *(const float4*)&As[k][ty*4];
            *(float4*)b = *(const float4*)&Bs[k][tx*4];
#pragma unroll
            for (int i=0;i<4;i++)
#pragma unroll
                for (int j=0;j<4;j++) acc[i][j] = fmaf(a[i], b[j], acc[i][j]);
        }
        __syncthreads();
    }
    float* Cp = C + (long)blockIdx.z*partStride;
#pragma unroll
    for (int i=0;i<4;i++){
        int r = rowBase + ty*4 + i;
#pragma unroll
        for (int j=0;j<4;j++)
            Cp[(long)r*ldc + colBase + tx*4 + j] = acc[i][j];
    }
}
static void sgemm(bool BT,const float* A,int lda,const float* B,int ldb,float* Cpart,int ldc,
                  int M,int N,int K,int splits){
    dim3 g(N/64, M/64, splits);
    int chunkK = K/splits;
    if (BT) gemm_part<true ><<<g,256>>>(A,lda,B,ldb,Cpart,ldc,(long)M*ldc,chunkK);
    else    gemm_part<false><<<g,256>>>(A,lda,B,ldb,Cpart,ldc,(long)M*ldc,chunkK);
}
__global__ void reduce_kernel(float* dst,const float* src,long len,int splits,int colmask,
                              const float* b1,const float* b2){
    long i = (long)blockIdx.x*blockDim.x+threadIdx.x;
    if (i >= len) return;
    float s = 0.f;
    for (int z=0;z<splits;z++) s += src[z*len+i];
    int col = (int)(i & colmask);
    if (b1) s += b1[col];
    if (b2) s += b2[col];
    dst[i] = s;
}

// ---------------- conversions ----------------
__device__ __forceinline__ void split1(float v, __half& h, __half& l){
    h = __float2half_rn(v);
    l = __float2half_rn(v - __half2float(h));
}

__global__ void conv_mask_kernel(const float* __restrict__ src, const float* __restrict__ mask,
                                 __half* __restrict__ dh, __half* __restrict__ dl, long n4,
                                 unsigned* minu){
    long i = (long)blockIdx.x*blockDim.x + threadIdx.x;
    if (i < BB && minu) minu[i] = 0xFFFFFFFFu;   // init batch-min encodings
    if (i >= n4) return;
    float4 v = ((const float4*)src)[i];
    float m = mask[i >> 8];
    v.x*=m; v.y*=m; v.z*=m; v.w*=m;
    __align__(8) __half h[4], l[4];
    split1(v.x,h[0],l[0]); split1(v.y,h[1],l[1]); split1(v.z,h[2],l[2]); split1(v.w,h[3],l[3]);
    ((uint2*)dh)[i] = *(uint2*)h;
    ((uint2*)dl)[i] = *(uint2*)l;
}

__global__ void conv_slice_kernel(const float* __restrict__ src, int ldsrc,
                                  __half* __restrict__ dh, __half* __restrict__ dl,
                                  int cols, int n4){
    int i = blockIdx.x*blockDim.x + threadIdx.x;
    if (i >= n4) return;
    int c4pr = cols/4;
    int r = i / c4pr, c4 = i % c4pr;
    float4 v = *(const float4*)(src + (long)r*ldsrc + c4*4);
    __align__(8) __half h[4], l[4];
    split1(v.x,h[0],l[0]); split1(v.y,h[1],l[1]); split1(v.z,h[2],l[2]); split1(v.w,h[3],l[3]);
    long o = (long)r*c4pr + c4;
    ((uint2*)dh)[o] = *(uint2*)h;
    ((uint2*)dl)[o] = *(uint2*)l;
}

// transpose+convert (weights, hi only): src [rows,cols] fp32 -> dst [cols,rows] half
__global__ void tconv_kernel(const float* __restrict__ src, int rows, int cols,
                             __half* __restrict__ dh){
    __shared__ float t[32][33];
    int r0 = blockIdx.y*32, c0 = blockIdx.x*32;
    int tx = threadIdx.x, ty = threadIdx.y;
    for (int i=ty;i<32;i+=8)
        t[i][tx] = src[(long)(r0+i)*cols + c0+tx];
    __syncthreads();
    for (int i=ty;i<32;i+=8){
        long o = (long)(c0+i)*rows + r0+tx;
        dh[o] = __float2half_rn(t[tx][i]);
    }
}

// ---------------- pointwise / reductions ----------------
__device__ __forceinline__ float sigm(float x){ return 1.f/(1.f+__expf(-x)); }

__global__ void concat3_kernel(const float* a,const float* b,const float* c,float* out){
    int idx = blockIdx.x*blockDim.x+threadIdx.x;
    if (idx >= BB*3072) return;
    int bb = idx/3072, j = idx%3072;
    out[idx] = (j<1024) ? a[bb*1024+j] : (j<2048 ? b[bb*1024+j-1024] : c[bb*1024+j-2048]);
}
__global__ void concat2_kernel(const float* a,const float* b,float* out){
    int idx = blockIdx.x*blockDim.x+threadIdx.x;
    if (idx >= BB*2048) return;
    int bb = idx/2048, j = idx%2048;
    out[idx] = (j<1024) ? a[bb*1024+j] : b[bb*1024+j-1024];
}
__global__ void lstm_kernel(const float* gates,const float* c_prev,float* h_out,float* c_out){
    int idx = blockIdx.x*blockDim.x+threadIdx.x;
    if (idx >= BR) return;
    int bb = idx >> 10, r = idx & 1023;
    const float* g = gates + bb*4096;
    float c = sigm(g[1024+r])*c_prev[idx] + sigm(g[r])*tanhf(g[2048+r]);
    h_out[idx] = sigm(g[3072+r])*tanhf(c);
    c_out[idx] = c;
}
__global__ void __launch_bounds__(512) topk_kernel(float* Adj,const unsigned* minu,
                                                   const float* mask,float* dvec){
    __shared__ unsigned long long keys[NN];
    __shared__ float red[NN];
    int row = blockIdx.x, t = threadIdx.x, bb = row >> 9;
    float mrow = mask[row];
    float mn = fdec(minu[bb]);
    float* arow = Adj + (long)row*NN;
    float v = (arow[t] - mn) * mrow;
    keys[t] = ((unsigned long long)__float_as_uint(v) << 32) | (unsigned)(NN-1-t);
    __syncthreads();
    for (unsigned k2=2;k2<=NN;k2<<=1)
        for (unsigned j=k2>>1;j>0;j>>=1){
            unsigned ixj = t ^ j;
            if (ixj > (unsigned)t){
                unsigned long long x=keys[t], y=keys[ixj];
                bool desc = ((t & k2) == 0);
                if (desc ? (x<y) : (x>y)){ keys[t]=y; keys[ixj]=x; }
            }
            __syncthreads();
        }
    unsigned long long kk = keys[t];
    arow[t] = 0.f;
    __syncthreads();
    float s = 0.f;
    if (t < KTOP){
        int col = (NN-1) - (int)(unsigned)(kk & 0xffffffffu);
        float val = __uint_as_float((unsigned)(kk >> 32));
        arow[col] = val;
        s = val;
    }
    red[t]=s; __syncthreads();
    for (int st=NN/2;st>0;st>>=1){ if (t<st) red[t]+=red[t+st]; __syncthreads(); }
    if (t==0) dvec[row] = (red[0] > 0.f) ? rsqrtf(red[0]) : 0.f;
}
// fused: Adj *= d_r*d_c, write fp16 hi (A-side of 1-pass), srow[r] = sum_c Adj_norm*mask_c
__global__ void rowfinal_kernel(const float* __restrict__ adj, const float* __restrict__ dvec,
                                const float* __restrict__ mask,
                                __half* __restrict__ Ah, float* __restrict__ srow){
    int row = blockIdx.x*8 + (threadIdx.x>>5);
    int lane = threadIdx.x & 31;
    int bb = row >> 9;
    const float* a = adj + (long)row*NN;
    const float dr = dvec[row];
    const float* dc = dvec + (bb<<9);
    const float* m  = mask + (bb<<9);
    float s = 0.f;
    for (int k=lane*4; k<NN; k+=128){
        float4 v  = *(const float4*)(a+k);
        float4 d4 = *(const float4*)(dc+k);
        float4 m4 = *(const float4*)(m+k);
        float x0=v.x*dr*d4.x, x1=v.y*dr*d4.y, x2=v.z*dr*d4.z, x3=v.w*dr*d4.w;
        s += x0*m4.x + x1*m4.y + x2*m4.z + x3*m4.w;
        __align__(8) __half h[4];
        h[0]=__float2half_rn(x0); h[1]=__float2half_rn(x1);
        h[2]=__float2half_rn(x2); h[3]=__float2half_rn(x3);
        long o = ((long)row*NN + k) >> 2;
        ((uint2*)Ah)[o] = *(uint2*)h;
    }
    for (int o=16;o;o>>=1) s += __shfl_xor_sync(0xffffffffu, s, o);
    if (lane==0) srow[row] = s;
}
__global__ void colmaxT_kernel(const __half* Xh,float* att){
    int warp = (blockIdx.x*blockDim.x+threadIdx.x) >> 5;
    int lane = threadIdx.x & 31;
    if (warp >= BB*RR) return;
    long base = (long)warp*NN;
    float mx = -INFINITY;
    for (int k=lane;k<NN;k+=32)
        mx = fmaxf(mx, __half2float(Xh[base+k]));
    for (int o=16;o;o>>=1) mx = fmaxf(mx, __shfl_xor_sync(0xffffffffu, mx, o));
    if (lane==0) att[warp] = mx;
}
__global__ void pack_kernel(const float* hatt,const float* catt,
                            const float* hlang,const float* clang,float* out,int out_size){
    int i = blockIdx.x*blockDim.x+threadIdx.x;
    if (i >= BR) return;
    out[i] = hlang[i];
    if (out_size >= 5*BR){
        out[1*BR+i] = hatt[i];
        out[2*BR+i] = hlang[i];
        out[3*BR+i] = catt[i];
        out[4*BR+i] = clang[i];
    }
}

// ---------------- host driver ----------------
struct Ptrs {
    float *adj,*xcat,*gates,*gates2,*part,*ht1,*ht2,*pvec,*srow,*dvec,*attv,*xl,*hatt,*catt,*hlang,*clang;
    unsigned* minu;
    __half *Ph,*Pl,*Qh,*Ql,*Sh,*Sl,*ADJh;
    __half *W1h,*W1l,*W2h,*W2l,*G0h,*G1h,*G2h;
};
static Ptrs P;
static bool g_init = false;

extern "C" void kernel_launch(void* const* d_in, const int* in_sizes, int n_in,
                              void* d_out, int out_size)
{
    const float* xt   = (const float*)d_in[0];
    const float* fc   = (const float*)d_in[1];
    const float* ge   = (const float*)d_in[2];
    const float* sh   = (const float*)d_in[4];
    const float* sc   = (const float*)d_in[5];
    const float* mask = (const float*)d_in[6];
    const float* aWih = (const float*)d_in[7];
    const float* aWhh = (const float*)d_in[8];
    const float* abih = (const float*)d_in[9];
    const float* abhh = (const float*)d_in[10];
    const float* lWih = (const float*)d_in[11];
    const float* lWhh = (const float*)d_in[12];
    const float* lbih = (const float*)d_in[13];
    const float* lbhh = (const float*)d_in[14];
    const float* e1W  = (const float*)d_in[15];
    const float* e1b  = (const float*)d_in[16];
    const float* e2W  = (const float*)d_in[17];
    const float* e2b  = (const float*)d_in[18];
    const float* gW0  = (const float*)d_in[19];
    const float* gb0  = (const float*)d_in[20];
    const float* gW1  = (const float*)d_in[21];
    const float* gb1  = (const float*)d_in[22];
    const float* gW2  = (const float*)d_in[23];
    const float* gb2  = (const float*)d_in[24];
    (void)in_sizes; (void)n_in;
    float* out = (float*)d_out;

    if (!g_init){
        cudaGetSymbolAddress((void**)&P.adj,  g_adj);
        cudaGetSymbolAddress((void**)&P.minu, g_minu);
        cudaGetSymbolAddress((void**)&P.xcat, g_xcat);
        cudaGetSymbolAddress((void**)&P.gates,g_gates);
        cudaGetSymbolAddress((void**)&P.gates2,g_gates2);
        cudaGetSymbolAddress((void**)&P.part, g_part);
        cudaGetSymbolAddress((void**)&P.ht1,  g_ht1);
        cudaGetSymbolAddress((void**)&P.ht2,  g_ht2);
        cudaGetSymbolAddress((void**)&P.pvec, g_pvec);
        cudaGetSymbolAddress((void**)&P.srow, g_srow);
        cudaGetSymbolAddress((void**)&P.dvec, g_dvec);
        cudaGetSymbolAddress((void**)&P.attv, g_attv);
        cudaGetSymbolAddress((void**)&P.xl,   g_xl);
        cudaGetSymbolAddress((void**)&P.hatt, g_hatt);
        cudaGetSymbolAddress((void**)&P.catt, g_catt);
        cudaGetSymbolAddress((void**)&P.hlang,g_hlang);
        cudaGetSymbolAddress((void**)&P.clang,g_clang);
        cudaGetSymbolAddress((void**)&P.Ph, g_Ph); cudaGetSymbolAddress((void**)&P.Pl, g_Pl);
        cudaGetSymbolAddress((void**)&P.Qh, g_Qh); cudaGetSymbolAddress((void**)&P.Ql, g_Ql);
        cudaGetSymbolAddress((void**)&P.Sh, g_Sh); cudaGetSymbolAddress((void**)&P.Sl, g_Sl);
        cudaGetSymbolAddress((void**)&P.ADJh, g_ADJh);
        cudaGetSymbolAddress((void**)&P.W1h, g_W1h); cudaGetSymbolAddress((void**)&P.W1l, g_W1l);
        cudaGetSymbolAddress((void**)&P.W2h, g_W2h); cudaGetSymbolAddress((void**)&P.W2l, g_W2l);
        cudaGetSymbolAddress((void**)&P.G0h, g_G0h);
        cudaGetSymbolAddress((void**)&P.G1h, g_G1h);
        cudaGetSymbolAddress((void**)&P.G2h, g_G2h);
        cudaFuncSetAttribute(hmma_gemm<3>, cudaFuncAttributeMaxDynamicSharedMemorySize, MMA_SMEM);
        cudaFuncSetAttribute(hmma_gemm<1>, cudaFuncAttributeMaxDynamicSharedMemorySize, MMA_SMEM);
        g_init = true;
    }

    const float* prev_h = sh + BR;
    const float* h0 = sh;
    const float* c0 = sc;
    const float* c1 = sc + BR;

    // ---- conversions (+ batch-min init) ----
    conv_mask_kernel<<<(int)((NGE/4+255)/256),256>>>(ge, mask, P.Ph, P.Pl, NGE/4, P.minu);
    conv_slice_kernel<<<(1048576/4+255)/256,256>>>(e1W, 2048, P.W1h, P.W1l, 1024, 1048576/4);
    conv_slice_kernel<<<(1048576/4+255)/256,256>>>(e2W, 2048, P.W2h, P.W2l, 1024, 1048576/4);
    tconv_kernel<<<dim3(32,32),dim3(32,8)>>>(gW0, 1024, 1024, P.G0h);
    tconv_kernel<<<dim3(32,32),dim3(32,8)>>>(gW1, 1024, 1024, P.G1h);
    tconv_kernel<<<dim3(32,32),dim3(32,8)>>>(gW2, 1024, 1024, P.G2h);

    // ---- attention LSTM (split-K FFMA) ----
    concat3_kernel<<<(BB*3072+255)/256,256>>>(prev_h, fc, xt, P.xcat);
    sgemm(true, P.xcat,3072, aWih,3072, P.part,            4096, BB,4096,3072, 3);
    sgemm(true, h0,1024,     aWhh,1024, P.part+3*BB*4096,  4096, BB,4096,1024, 1);
    reduce_kernel<<<(BB*4096+255)/256,256>>>(P.gates, P.part, BB*4096, 4, 4095, abih, abhh);
    lstm_kernel<<<(BR+255)/256,256>>>(P.gates, c0, P.hatt, P.catt);

    // ---- h-terms (split-K FFMA) ----
    sgemm(true, P.hatt,1024, e1W+1024,2048, P.part, 1024, BB,1024,1024, 4);
    reduce_kernel<<<(BB*1024+255)/256,256>>>(P.ht1, P.part, BB*1024, 4, 1023, nullptr, nullptr);
    sgemm(true, P.hatt,1024, e2W+1024,2048, P.part, 1024, BB,1024,1024, 4);
    reduce_kernel<<<(BB*1024+255)/256,256>>>(P.ht2, P.part, BB*1024, 4, 1023, nullptr, nullptr);
    sgemm(false, prev_h,1024, gW0+1024*1024,1024, P.part, 1024, BB,1024,1024, 4);
    reduce_kernel<<<(BB*1024+255)/256,256>>>(P.pvec, P.part, BB*1024, 4, 1023, nullptr, nullptr);

    // ---- E1/E2 (3-pass: protects topk ranking) ----
    hmma_gemm<3><<<dim3(8,256,1),128,MMA_SMEM>>>(P.Ph,P.Pl,1024,0, P.W1h,P.W1l,1024,0,
        1024, 0, 1, 0, nullptr,0,nullptr, P.Qh,P.Ql,1024, e1b, P.ht1, mask, nullptr);
    hmma_gemm<3><<<dim3(8,256,1),128,MMA_SMEM>>>(P.Ph,P.Pl,1024,0, P.W2h,P.W2l,1024,0,
        1024, 0, 1, 0, nullptr,0,nullptr, P.Sh,P.Sl,1024, e2b, P.ht2, mask, nullptr);

    // ---- Adj = E1 @ E2^T (3-pass, fused batch-min) ----
    hmma_gemm<3><<<dim3(4,4,64),128,MMA_SMEM>>>(P.Qh,P.Ql,1024,(long)NN*RR, P.Sh,P.Sl,1024,(long)NN*RR,
        1024, 512, 0, 0, P.adj,512,P.minu, nullptr,nullptr,0, nullptr,nullptr,nullptr,nullptr);

    // ---- Adj post-processing ----
    topk_kernel<<<BB*NN,512>>>(P.adj, P.minu, mask, P.dvec);
    rowfinal_kernel<<<BB*NN/8,256>>>(P.adj, P.dvec, mask, P.ADJh, P.srow);

    // ---- GCN layer 0 (1-pass): Z0 = GEM@G0 (->Qh^T), X1 = relu(Adj@Z0 + srow*pvec + b0)*m (->Sh)
    hmma_gemm<1><<<dim3(8,256,1),128,MMA_SMEM>>>(P.Ph,nullptr,1024,0, P.G0h,nullptr,1024,0,
        1024, 0, 2, 0, nullptr,0,nullptr, P.Qh,nullptr,0, nullptr, nullptr, nullptr, nullptr);
    hmma_gemm<1><<<dim3(8,4,64),128,MMA_SMEM>>>(P.ADJh,nullptr,512,(long)NN*NN, P.Qh,nullptr,512,(long)RR*NN,
        512, 512, 1, 1, nullptr,0,nullptr, P.Sh,nullptr,1024, gb0, P.pvec, P.srow, mask);

    // ---- GCN layer 1 (1-pass): Z1 = X1@G1 (->Ph^T), X2 = relu(Adj@Z1 + b1)*m (->Qh)
    hmma_gemm<1><<<dim3(8,256,1),128,MMA_SMEM>>>(P.Sh,nullptr,1024,0, P.G1h,nullptr,1024,0,
        1024, 0, 2, 0, nullptr,0,nullptr, P.Ph,nullptr,0, nullptr, nullptr, nullptr, nullptr);
    hmma_gemm<1><<<dim3(8,4,64),128,MMA_SMEM>>>(P.ADJh,nullptr,512,(long)NN*NN, P.Ph,nullptr,512,(long)RR*NN,
        512, 512, 1, 1, nullptr,0,nullptr, P.Qh,nullptr,1024, gb1, nullptr, nullptr, mask);

    // ---- GCN layer 2 (1-pass): Z2 = X2@G2 (->Sh^T), X3^T = relu(Adj@Z2 + b2)*m (->Ph^T)
    hmma_gemm<1><<<dim3(8,256,1),128,MMA_SMEM>>>(P.Qh,nullptr,1024,0, P.G2h,nullptr,1024,0,
        1024, 0, 2, 0, nullptr,0,nullptr, P.Sh,nullptr,0, nullptr, nullptr, nullptr, nullptr);
    hmma_gemm<1><<<dim3(8,4,64),128,MMA_SMEM>>>(P.ADJh,nullptr,512,(long)NN*NN, P.Sh,nullptr,512,(long)RR*NN,
        512, 512, 2, 1, nullptr,0,nullptr, P.Ph,nullptr,0, gb2, nullptr, nullptr, mask);

    // ---- att = max over nodes (X3^T contiguous, hi only) ----
    colmaxT_kernel<<<(BB*RR*32+255)/256,256>>>(P.Ph, P.attv);

    // ---- language LSTM (split-K FFMA) ----
    concat2_kernel<<<(BB*2048+255)/256,256>>>(P.attv, P.hatt, P.xl);
    sgemm(true, P.xl,2048,   lWih,2048, P.part,           4096, BB,4096,2048, 2);
    sgemm(true, prev_h,1024, lWhh,1024, P.part+2*BB*4096, 4096, BB,4096,1024, 1);
    reduce_kernel<<<(BB*4096+255)/256,256>>>(P.gates2, P.part, BB*4096, 3, 4095, lbih, lbhh);
    lstm_kernel<<<(BR+255)/256,256>>>(P.gates2, c1, P.hlang, P.clang);

    pack_kernel<<<(BR+255)/256,256>>>(P.hatt, P.catt, P.hlang, P.clang, out, out_size);
}

// round 12
// speedup vs baseline: 4.5832x; 1.0662x over previous
#include <cuda_runtime.h>
#include <cuda_fp16.h>
#include <math.h>
#include <stdint.h>

#define BB 64
#define NN 512
#define RR 1024
#define KTOP 256
#define BR (BB*RR)
#define NGE ((long)BB*NN*RR)

// ---------------- device scratch ----------------
__device__ float g_adj[(long)BB*NN*NN];
__device__ unsigned g_minu[BB];
__device__ float g_xcat[BB*3072];
__device__ float g_gates[BB*4096];
__device__ float g_gates2[BB*4096];
__device__ float g_part[4*BB*4096];
__device__ float g_ht1[BB*RR];
__device__ float g_ht2[BB*RR];
__device__ float g_pvec[BB*RR];
__device__ float g_srow[BB*NN];
__device__ float g_dvec[BB*NN];
__device__ float g_attv[BB*RR];
__device__ float g_xl[BB*2048];
__device__ float g_hatt[BR];
__device__ float g_catt[BR];
__device__ float g_hlang[BR];
__device__ float g_clang[BR];

__device__ __half g_Ph[NGE];              // GEM(hi) -> Z1^T -> X3^T
__device__ __half g_Qh[NGE], g_Ql[NGE];   // E1 -> Z0^T -> X2
__device__ __half g_Sh[NGE], g_Sl[NGE];   // E2 -> X1 -> Z2^T
__device__ __half g_ADJh[(long)BB*NN*NN];
__device__ __half g_W1h[1048576], g_W1l[1048576];
__device__ __half g_W2h[1048576], g_W2l[1048576];
__device__ __half g_G0h[1048576];
__device__ __half g_G1h[1048576];
__device__ __half g_G2h[1048576];

// monotone uint encoding for float ordering
__device__ __forceinline__ unsigned fenc(float f){
    unsigned u = __float_as_uint(f);
    return (u & 0x80000000u) ? ~u : (u | 0x80000000u);
}
__device__ __forceinline__ float fdec(unsigned v){
    unsigned u = (v & 0x80000000u) ? (v ^ 0x80000000u) : ~v;
    return __uint_as_float(u);
}

// ---------------- warp MMA helpers ----------------
__device__ __forceinline__ uint32_t smem_u32(const void* p){
    uint32_t a;
    asm("{ .reg .u64 t; cvta.to.shared.u64 t, %1; cvt.u32.u64 %0, t; }" : "=r"(a) : "l"(p));
    return a;
}
__device__ __forceinline__ uint32_t swz64(uint32_t x){ return x ^ ((x>>3)&0x30u); }
__device__ __forceinline__ void ldm4(uint32_t* r, uint32_t addr){
    asm volatile("ldmatrix.sync.aligned.m8n8.x4.shared.b16 {%0,%1,%2,%3}, [%4];"
        : "=r"(r[0]),"=r"(r[1]),"=r"(r[2]),"=r"(r[3]) : "r"(addr));
}
__device__ __forceinline__ void mma16816(float* d, const uint32_t* a, const uint32_t* b){
    asm volatile("mma.sync.aligned.m16n8k16.row.col.f32.f16.f16.f32 "
        "{%0,%1,%2,%3}, {%4,%5,%6,%7}, {%8,%9}, {%0,%1,%2,%3};"
        : "+f"(d[0]),"+f"(d[1]),"+f"(d[2]),"+f"(d[3])
        : "r"(a[0]),"r"(a[1]),"r"(a[2]),"r"(a[3]), "r"(b[0]),"r"(b[1]));
}
__device__ __forceinline__ void cpasync16(uint32_t dst, const void* src){
    asm volatile("cp.async.cg.shared.global [%0], [%1], 16;" :: "r"(dst), "l"(src));
}

// ---------------- fp16 hi/lo tensor-core GEMM, 3-stage cp.async ----------------
// PASSES=3: (Ah+Al)@(Bh+Bl)^T approx. PASSES=2: Ah@(Bh+Bl)^T. PASSES=1: Ah@Bh^T.
#define MMA_SMEM (3*32768+1024)

template<int PASSES>
__global__ void __launch_bounds__(128,2) hmma_gemm(
    const __half* __restrict__ Ah, const __half* __restrict__ Al, int lda, long sA,
    const __half* __restrict__ Bh, const __half* __restrict__ Bl, int ldb, long sB,
    int K, int rowsPerZ, int outMode, int relu,
    float* Cf, int ldc, unsigned* minu,
    __half* Ch, __half* Cl, int ldch,
    const float* __restrict__ bias, const float* __restrict__ addv,
    const float* __restrict__ rs, const float* __restrict__ ps)
{
    extern __shared__ char smraw[];
    uint32_t sb0 = smem_u32(smraw);
    uint32_t sb  = (sb0 + 1023u) & ~1023u;
    const int tid = threadIdx.x, wid = tid>>5, lane = tid&31;

    const __half* A0 = Ah + blockIdx.z*sA;
    const __half* A1 = (PASSES==3) ? (Al + blockIdx.z*sA) : nullptr;
    const __half* B0 = Bh + blockIdx.z*sB;
    const __half* B1 = (PASSES>=2) ? (Bl + blockIdx.z*sB) : nullptr;
    const int rowBase = blockIdx.y*128, colBase = blockIdx.x*128;
    const int NC = K >> 5;

    const int wr = wid>>1, wc = wid&1;
    const int lr = lane&7, q = lane>>3;
    const int aRowOff = ((q&1)<<3) + lr;
    const int aKbOff  = (q>>1)<<4;
    const int bRowOff = ((q>>1)<<3) + lr;
    const int bKbOff  = (q&1)<<4;

    const int cp_row = tid>>2;
    const int cp_u   = tid&3;

    float acc[4][8][4];
    #pragma unroll
    for (int a=0;a<4;a++)
        #pragma unroll
        for (int b=0;b<8;b++)
            #pragma unroll
            for (int c=0;c<4;c++) acc[a][b][c]=0.f;

    auto load_chunk = [&](int ci, int s){
        const int k0 = ci<<5;
        const uint32_t st = sb + s*32768;
        #pragma unroll
        for (int j=0;j<4;j++){
            int r = cp_row + j*32;
            uint32_t doff = swz64((uint32_t)(r*64 + cp_u*16));
            long aoff = (long)(rowBase+r)*lda + k0 + cp_u*8;
            long boff = (long)(colBase+r)*ldb + k0 + cp_u*8;
            cpasync16(st +         doff, A0 + aoff);
            if (PASSES==3) cpasync16(st + 8192 + doff, A1 + aoff);
            cpasync16(st + 16384 + doff, B0 + boff);
            if (PASSES>=2) cpasync16(st + 24576 + doff, B1 + boff);
        }
        asm volatile("cp.async.commit_group;" ::: "memory");
    };

    load_chunk(0, 0);
    if (NC > 1) load_chunk(1, 1);

    int sidx = 0;
    int nidx = (NC > 2) ? 2 : 0;
    for (int i=0;i<NC;i++){
        if (i+1 < NC) asm volatile("cp.async.wait_group 1;" ::: "memory");
        else          asm volatile("cp.async.wait_group 0;" ::: "memory");
        __syncthreads();
        if (i+2 < NC){
            load_chunk(i+2, nidx);
            nidx = (nidx==2)?0:nidx+1;
        }
        const uint32_t st = sb + sidx*32768;
        sidx = (sidx==2)?0:sidx+1;
        #pragma unroll
        for (int ks=0;ks<2;ks++){
            const uint32_t kb = ks<<5;
            uint32_t bh[4][4], bl[4][4], af[4][4];
            #pragma unroll
            for (int t=0;t<4;t++){
                uint32_t ro = (uint32_t)((wc*64 + t*16 + bRowOff)*64) + kb + bKbOff;
                ldm4(bh[t], st + 16384 + swz64(ro));
                if (PASSES>=2) ldm4(bl[t], st + 24576 + swz64(ro));
            }
            #pragma unroll
            for (int mi=0;mi<4;mi++){
                uint32_t ro = (uint32_t)((wr*64 + mi*16 + aRowOff)*64) + kb + aKbOff;
                ldm4(af[mi], st + swz64(ro));
            }
            #pragma unroll
            for (int mi=0;mi<4;mi++)
                #pragma unroll
                for (int t=0;t<4;t++){
                    mma16816(acc[mi][2*t],   af[mi], &bh[t][0]);
                    mma16816(acc[mi][2*t+1], af[mi], &bh[t][2]);
                }
            if (PASSES>=2){
                #pragma unroll
                for (int mi=0;mi<4;mi++)
                    #pragma unroll
                    for (int t=0;t<4;t++){
                        mma16816(acc[mi][2*t],   af[mi], &bl[t][0]);
                        mma16816(acc[mi][2*t+1], af[mi], &bl[t][2]);
                    }
            }
            if (PASSES==3){
                #pragma unroll
                for (int mi=0;mi<4;mi++){
                    uint32_t ro = (uint32_t)((wr*64 + mi*16 + aRowOff)*64) + kb + aKbOff;
                    ldm4(af[mi], st + 8192 + swz64(ro));
                }
                #pragma unroll
                for (int mi=0;mi<4;mi++)
                    #pragma unroll
                    for (int t=0;t<4;t++){
                        mma16816(acc[mi][2*t],   af[mi], &bh[t][0]);
                        mma16816(acc[mi][2*t+1], af[mi], &bh[t][2]);
                    }
            }
        }
    }

    // ---- epilogue ----
    const int cpair = (lane&3)*2;
    float lmin = INFINITY;
    #pragma unroll
    for (int mi=0;mi<4;mi++){
        #pragma unroll
        for (int rr=0;rr<2;rr++){
            const int r  = rowBase + wr*64 + mi*16 + (lane>>2) + rr*8;
            const int gr = blockIdx.z*rowsPerZ + r;
            const float rsv = rs ? rs[gr] : 1.f;
            const float psv = ps ? ps[gr] : 1.f;
            const float* avp = addv ? addv + (long)(gr>>9)*RR : nullptr;
            #pragma unroll
            for (int ni=0;ni<8;ni++){
                const int c = colBase + wc*64 + ni*8 + cpair;
                float x0 = acc[mi][ni][rr*2+0];
                float x1 = acc[mi][ni][rr*2+1];
                if (avp){ x0 += rsv*avp[c]; x1 += rsv*avp[c+1]; }
                if (bias){ x0 += bias[c]; x1 += bias[c+1]; }
                if (relu){ x0 = fmaxf(x0,0.f); x1 = fmaxf(x1,0.f); }
                x0 *= psv; x1 *= psv;
                if (outMode==0){
                    *(float2*)(Cf + (long)gr*ldc + c) = make_float2(x0,x1);
                    lmin = fminf(lmin, fminf(x0,x1));
                } else {
                    __half h0 = __float2half_rn(x0);
                    __half h1 = __float2half_rn(x1);
                    if (outMode==1){
                        long o = (long)gr*ldch + c;
                        *(__half2*)(Ch+o) = __halves2half2(h0,h1);
                        if (Cl){
                            __half l0 = __float2half_rn(x0-__half2float(h0));
                            __half l1 = __float2half_rn(x1-__half2float(h1));
                            *(__half2*)(Cl+o) = __halves2half2(l0,l1);
                        }
                    } else { // transposed: out[b][feat][node]
                        long base = (long)(gr>>9)*((long)RR*NN) + (gr&511);
                        long o0 = base + (long)c*NN;
                        Ch[o0]=h0; Ch[o0+NN]=h1;
                        if (Cl){
                            Cl[o0]   = __float2half_rn(x0-__half2float(h0));
                            Cl[o0+NN]= __float2half_rn(x1-__half2float(h1));
                        }
                    }
                }
            }
        }
    }
    if (outMode==0 && minu){
        #pragma unroll
        for (int o=16;o;o>>=1) lmin = fminf(lmin, __shfl_xor_sync(0xffffffffu, lmin, o));
        if (lane==0) atomicMin(&minu[blockIdx.z], fenc(lmin));
    }
}

// ---------------- FFMA split-K GEMM for small (B=64) matmuls ----------------
template<bool BT>
__global__ void __launch_bounds__(256) gemm_part(
    const float* __restrict__ A,int lda,
    const float* __restrict__ B,int ldb,
    float* __restrict__ C,int ldc,long partStride,int chunkK)
{
    __shared__ float As[16][64];
    __shared__ float Bs[16][64];
    const int tid = threadIdx.x;
    const int rowBase = blockIdx.y*64, colBase = blockIdx.x*64;
    const int kbeg = blockIdx.z*chunkK, kend = kbeg + chunkK;
    const int tx = tid & 15, ty = tid >> 4;
    float acc[4][4];
#pragma unroll
    for (int i=0;i<4;i++)
#pragma unroll
        for (int j=0;j<4;j++) acc[i][j]=0.f;

    for (int k0=kbeg;k0<kend;k0+=16){
#pragma unroll
        for (int i=tid*4;i<64*16;i+=256*4){
            int r=i>>4, kk=i&15;
            float4 v = *(const float4*)(A + (long)(rowBase+r)*lda + k0 + kk);
            As[kk+0][r]=v.x; As[kk+1][r]=v.y; As[kk+2][r]=v.z; As[kk+3][r]=v.w;
        }
        if (BT){
#pragma unroll
            for (int i=tid*4;i<64*16;i+=256*4){
                int r=i>>4, kk=i&15;
                float4 v = *(const float4*)(B + (long)(colBase+r)*ldb + k0 + kk);
                Bs[kk+0][r]=v.x; Bs[kk+1][r]=v.y; Bs[kk+2][r]=v.z; Bs[kk+3][r]=v.w;
            }
        } else {
#pragma unroll
            for (int i=tid*4;i<16*64;i+=256*4){
                int r=i>>6, cc=i&63;
                *(float4*)&Bs[r][cc] = *(const float4*)(B + (long)(k0+r)*ldb + colBase + cc);
            }
        }
        __syncthreads();
#pragma unroll
        for (int k=0;k<16;k++){
            float a[4], b[4];
            *(float4*)a = *(const float4*)&As[k][ty*4];
            *(float4*)b = *(const float4*)&Bs[k][tx*4];
#pragma unroll
            for (int i=0;i<4;i++)
#pragma unroll
                for (int j=0;j<4;j++) acc[i][j] = fmaf(a[i], b[j], acc[i][j]);
        }
        __syncthreads();
    }
    float* Cp = C + (long)blockIdx.z*partStride;
#pragma unroll
    for (int i=0;i<4;i++){
        int r = rowBase + ty*4 + i;
#pragma unroll
        for (int j=0;j<4;j++)
            Cp[(long)r*ldc + colBase + tx*4 + j] = acc[i][j];
    }
}
static void sgemm(bool BT,const float* A,int lda,const float* B,int ldb,float* Cpart,int ldc,
                  int M,int N,int K,int splits){
    dim3 g(N/64, M/64, splits);
    int chunkK = K/splits;
    if (BT) gemm_part<true ><<<g,256>>>(A,lda,B,ldb,Cpart,ldc,(long)M*ldc,chunkK);
    else    gemm_part<false><<<g,256>>>(A,lda,B,ldb,Cpart,ldc,(long)M*ldc,chunkK);
}
__global__ void reduce_kernel(float* dst,const float* src,long len,int splits,int colmask,
                              const float* b1,const float* b2){
    long i = (long)blockIdx.x*blockDim.x+threadIdx.x;
    if (i >= len) return;
    float s = 0.f;
    for (int z=0;z<splits;z++) s += src[z*len+i];
    int col = (int)(i & colmask);
    if (b1) s += b1[col];
    if (b2) s += b2[col];
    dst[i] = s;
}

// ---------------- conversions ----------------
__device__ __forceinline__ void split1(float v, __half& h, __half& l){
    h = __float2half_rn(v);
    l = __float2half_rn(v - __half2float(h));
}

// GEM: masked, hi only (+ batch-min init)
__global__ void conv_mask_kernel(const float* __restrict__ src, const float* __restrict__ mask,
                                 __half* __restrict__ dh, long n4, unsigned* minu){
    long i = (long)blockIdx.x*blockDim.x + threadIdx.x;
    if (i < BB && minu) minu[i] = 0xFFFFFFFFu;
    if (i >= n4) return;
    float4 v = ((const float4*)src)[i];
    float m = mask[i >> 8];
    __align__(8) __half h[4];
    h[0]=__float2half_rn(v.x*m); h[1]=__float2half_rn(v.y*m);
    h[2]=__float2half_rn(v.z*m); h[3]=__float2half_rn(v.w*m);
    ((uint2*)dh)[i] = *(uint2*)h;
}

__global__ void conv_slice_kernel(const float* __restrict__ src, int ldsrc,
                                  __half* __restrict__ dh, __half* __restrict__ dl,
                                  int cols, int n4){
    int i = blockIdx.x*blockDim.x + threadIdx.x;
    if (i >= n4) return;
    int c4pr = cols/4;
    int r = i / c4pr, c4 = i % c4pr;
    float4 v = *(const float4*)(src + (long)r*ldsrc + c4*4);
    __align__(8) __half h[4], l[4];
    split1(v.x,h[0],l[0]); split1(v.y,h[1],l[1]); split1(v.z,h[2],l[2]); split1(v.w,h[3],l[3]);
    long o = (long)r*c4pr + c4;
    ((uint2*)dh)[o] = *(uint2*)h;
    ((uint2*)dl)[o] = *(uint2*)l;
}

// transpose+convert (weights, hi only)
__global__ void tconv_kernel(const float* __restrict__ src, int rows, int cols,
                             __half* __restrict__ dh){
    __shared__ float t[32][33];
    int r0 = blockIdx.y*32, c0 = blockIdx.x*32;
    int tx = threadIdx.x, ty = threadIdx.y;
    for (int i=ty;i<32;i+=8)
        t[i][tx] = src[(long)(r0+i)*cols + c0+tx];
    __syncthreads();
    for (int i=ty;i<32;i+=8){
        long o = (long)(c0+i)*rows + r0+tx;
        dh[o] = __float2half_rn(t[tx][i]);
    }
}

// ---------------- pointwise / reductions ----------------
__device__ __forceinline__ float sigm(float x){ return 1.f/(1.f+__expf(-x)); }

__global__ void concat3_kernel(const float* a,const float* b,const float* c,float* out){
    int idx = blockIdx.x*blockDim.x+threadIdx.x;
    if (idx >= BB*3072) return;
    int bb = idx/3072, j = idx%3072;
    out[idx] = (j<1024) ? a[bb*1024+j] : (j<2048 ? b[bb*1024+j-1024] : c[bb*1024+j-2048]);
}
__global__ void concat2_kernel(const float* a,const float* b,float* out){
    int idx = blockIdx.x*blockDim.x+threadIdx.x;
    if (idx >= BB*2048) return;
    int bb = idx/2048, j = idx%2048;
    out[idx] = (j<1024) ? a[bb*1024+j] : b[bb*1024+j-1024];
}
__global__ void lstm_kernel(const float* gates,const float* c_prev,float* h_out,float* c_out){
    int idx = blockIdx.x*blockDim.x+threadIdx.x;
    if (idx >= BR) return;
    int bb = idx >> 10, r = idx & 1023;
    const float* g = gates + bb*4096;
    float c = sigm(g[1024+r])*c_prev[idx] + sigm(g[r])*tanhf(g[2048+r]);
    h_out[idx] = sigm(g[3072+r])*tanhf(c);
    c_out[idx] = c;
}
__global__ void __launch_bounds__(512) topk_kernel(float* Adj,const unsigned* minu,
                                                   const float* mask,float* dvec){
    __shared__ unsigned long long keys[NN];
    __shared__ float red[NN];
    int row = blockIdx.x, t = threadIdx.x, bb = row >> 9;
    float mrow = mask[row];
    float mn = fdec(minu[bb]);
    float* arow = Adj + (long)row*NN;
    float v = (arow[t] - mn) * mrow;
    keys[t] = ((unsigned long long)__float_as_uint(v) << 32) | (unsigned)(NN-1-t);
    __syncthreads();
    for (unsigned k2=2;k2<=NN;k2<<=1)
        for (unsigned j=k2>>1;j>0;j>>=1){
            unsigned ixj = t ^ j;
            if (ixj > (unsigned)t){
                unsigned long long x=keys[t], y=keys[ixj];
                bool desc = ((t & k2) == 0);
                if (desc ? (x<y) : (x>y)){ keys[t]=y; keys[ixj]=x; }
            }
            __syncthreads();
        }
    unsigned long long kk = keys[t];
    arow[t] = 0.f;
    __syncthreads();
    float s = 0.f;
    if (t < KTOP){
        int col = (NN-1) - (int)(unsigned)(kk & 0xffffffffu);
        float val = __uint_as_float((unsigned)(kk >> 32));
        arow[col] = val;
        s = val;
    }
    red[t]=s; __syncthreads();
    for (int st=NN/2;st>0;st>>=1){ if (t<st) red[t]+=red[t+st]; __syncthreads(); }
    if (t==0) dvec[row] = (red[0] > 0.f) ? rsqrtf(red[0]) : 0.f;
}
__global__ void rowfinal_kernel(const float* __restrict__ adj, const float* __restrict__ dvec,
                                const float* __restrict__ mask,
                                __half* __restrict__ Ah, float* __restrict__ srow){
    int row = blockIdx.x*8 + (threadIdx.x>>5);
    int lane = threadIdx.x & 31;
    int bb = row >> 9;
    const float* a = adj + (long)row*NN;
    const float dr = dvec[row];
    const float* dc = dvec + (bb<<9);
    const float* m  = mask + (bb<<9);
    float s = 0.f;
    for (int k=lane*4; k<NN; k+=128){
        float4 v  = *(const float4*)(a+k);
        float4 d4 = *(const float4*)(dc+k);
        float4 m4 = *(const float4*)(m+k);
        float x0=v.x*dr*d4.x, x1=v.y*dr*d4.y, x2=v.z*dr*d4.z, x3=v.w*dr*d4.w;
        s += x0*m4.x + x1*m4.y + x2*m4.z + x3*m4.w;
        __align__(8) __half h[4];
        h[0]=__float2half_rn(x0); h[1]=__float2half_rn(x1);
        h[2]=__float2half_rn(x2); h[3]=__float2half_rn(x3);
        long o = ((long)row*NN + k) >> 2;
        ((uint2*)Ah)[o] = *(uint2*)h;
    }
    for (int o=16;o;o>>=1) s += __shfl_xor_sync(0xffffffffu, s, o);
    if (lane==0) srow[row] = s;
}
__global__ void colmaxT_kernel(const __half* Xh,float* att){
    int warp = (blockIdx.x*blockDim.x+threadIdx.x) >> 5;
    int lane = threadIdx.x & 31;
    if (warp >= BB*RR) return;
    long base = (long)warp*NN;
    float mx = -INFINITY;
    for (int k=lane;k<NN;k+=32)
        mx = fmaxf(mx, __half2float(Xh[base+k]));
    for (int o=16;o;o>>=1) mx = fmaxf(mx, __shfl_xor_sync(0xffffffffu, mx, o));
    if (lane==0) att[warp] = mx;
}
__global__ void pack_kernel(const float* hatt,const float* catt,
                            const float* hlang,const float* clang,float* out,int out_size){
    int i = blockIdx.x*blockDim.x+threadIdx.x;
    if (i >= BR) return;
    out[i] = hlang[i];
    if (out_size >= 5*BR){
        out[1*BR+i] = hatt[i];
        out[2*BR+i] = hlang[i];
        out[3*BR+i] = catt[i];
        out[4*BR+i] = clang[i];
    }
}

// ---------------- host driver ----------------
struct Ptrs {
    float *adj,*xcat,*gates,*gates2,*part,*ht1,*ht2,*pvec,*srow,*dvec,*attv,*xl,*hatt,*catt,*hlang,*clang;
    unsigned* minu;
    __half *Ph,*Qh,*Ql,*Sh,*Sl,*ADJh;
    __half *W1h,*W1l,*W2h,*W2l,*G0h,*G1h,*G2h;
};
static Ptrs P;
static bool g_init = false;
static cudaStream_t g_s2;
static cudaEvent_t g_ev1, g_ev2;

extern "C" void kernel_launch(void* const* d_in, const int* in_sizes, int n_in,
                              void* d_out, int out_size)
{
    const float* xt   = (const float*)d_in[0];
    const float* fc   = (const float*)d_in[1];
    const float* ge   = (const float*)d_in[2];
    const float* sh   = (const float*)d_in[4];
    const float* sc   = (const float*)d_in[5];
    const float* mask = (const float*)d_in[6];
    const float* aWih = (const float*)d_in[7];
    const float* aWhh = (const float*)d_in[8];
    const float* abih = (const float*)d_in[9];
    const float* abhh = (const float*)d_in[10];
    const float* lWih = (const float*)d_in[11];
    const float* lWhh = (const float*)d_in[12];
    const float* lbih = (const float*)d_in[13];
    const float* lbhh = (const float*)d_in[14];
    const float* e1W  = (const float*)d_in[15];
    const float* e1b  = (const float*)d_in[16];
    const float* e2W  = (const float*)d_in[17];
    const float* e2b  = (const float*)d_in[18];
    const float* gW0  = (const float*)d_in[19];
    const float* gb0  = (const float*)d_in[20];
    const float* gW1  = (const float*)d_in[21];
    const float* gb1  = (const float*)d_in[22];
    const float* gW2  = (const float*)d_in[23];
    const float* gb2  = (const float*)d_in[24];
    (void)in_sizes; (void)n_in;
    float* out = (float*)d_out;

    if (!g_init){
        cudaGetSymbolAddress((void**)&P.adj,  g_adj);
        cudaGetSymbolAddress((void**)&P.minu, g_minu);
        cudaGetSymbolAddress((void**)&P.xcat, g_xcat);
        cudaGetSymbolAddress((void**)&P.gates,g_gates);
        cudaGetSymbolAddress((void**)&P.gates2,g_gates2);
        cudaGetSymbolAddress((void**)&P.part, g_part);
        cudaGetSymbolAddress((void**)&P.ht1,  g_ht1);
        cudaGetSymbolAddress((void**)&P.ht2,  g_ht2);
        cudaGetSymbolAddress((void**)&P.pvec, g_pvec);
        cudaGetSymbolAddress((void**)&P.srow, g_srow);
        cudaGetSymbolAddress((void**)&P.dvec, g_dvec);
        cudaGetSymbolAddress((void**)&P.attv, g_attv);
        cudaGetSymbolAddress((void**)&P.xl,   g_xl);
        cudaGetSymbolAddress((void**)&P.hatt, g_hatt);
        cudaGetSymbolAddress((void**)&P.catt, g_catt);
        cudaGetSymbolAddress((void**)&P.hlang,g_hlang);
        cudaGetSymbolAddress((void**)&P.clang,g_clang);
        cudaGetSymbolAddress((void**)&P.Ph, g_Ph);
        cudaGetSymbolAddress((void**)&P.Qh, g_Qh); cudaGetSymbolAddress((void**)&P.Ql, g_Ql);
        cudaGetSymbolAddress((void**)&P.Sh, g_Sh); cudaGetSymbolAddress((void**)&P.Sl, g_Sl);
        cudaGetSymbolAddress((void**)&P.ADJh, g_ADJh);
        cudaGetSymbolAddress((void**)&P.W1h, g_W1h); cudaGetSymbolAddress((void**)&P.W1l, g_W1l);
        cudaGetSymbolAddress((void**)&P.W2h, g_W2h); cudaGetSymbolAddress((void**)&P.W2l, g_W2l);
        cudaGetSymbolAddress((void**)&P.G0h, g_G0h);
        cudaGetSymbolAddress((void**)&P.G1h, g_G1h);
        cudaGetSymbolAddress((void**)&P.G2h, g_G2h);
        cudaFuncSetAttribute(hmma_gemm<3>, cudaFuncAttributeMaxDynamicSharedMemorySize, MMA_SMEM);
        cudaFuncSetAttribute(hmma_gemm<2>, cudaFuncAttributeMaxDynamicSharedMemorySize, MMA_SMEM);
        cudaFuncSetAttribute(hmma_gemm<1>, cudaFuncAttributeMaxDynamicSharedMemorySize, MMA_SMEM);
        cudaStreamCreateWithFlags(&g_s2, cudaStreamNonBlocking);
        cudaEventCreateWithFlags(&g_ev1, cudaEventDisableTiming);
        cudaEventCreateWithFlags(&g_ev2, cudaEventDisableTiming);
        g_init = true;
    }

    const float* prev_h = sh + BR;
    const float* h0 = sh;
    const float* c0 = sc;
    const float* c1 = sc + BR;

    // ---- fork: conversion branch on s2, LSTM chain on default stream ----
    cudaEventRecord(g_ev1, 0);
    cudaStreamWaitEvent(g_s2, g_ev1, 0);

    // conversion branch (s2)
    conv_mask_kernel<<<(int)((NGE/4+255)/256),256,0,g_s2>>>(ge, mask, P.Ph, NGE/4, P.minu);
    conv_slice_kernel<<<(1048576/4+255)/256,256,0,g_s2>>>(e1W, 2048, P.W1h, P.W1l, 1024, 1048576/4);
    conv_slice_kernel<<<(1048576/4+255)/256,256,0,g_s2>>>(e2W, 2048, P.W2h, P.W2l, 1024, 1048576/4);
    tconv_kernel<<<dim3(32,32),dim3(32,8),0,g_s2>>>(gW0, 1024, 1024, P.G0h);
    tconv_kernel<<<dim3(32,32),dim3(32,8),0,g_s2>>>(gW1, 1024, 1024, P.G1h);
    tconv_kernel<<<dim3(32,32),dim3(32,8),0,g_s2>>>(gW2, 1024, 1024, P.G2h);

    // LSTM chain (default stream)
    concat3_kernel<<<(BB*3072+255)/256,256>>>(prev_h, fc, xt, P.xcat);
    sgemm(true, P.xcat,3072, aWih,3072, P.part,            4096, BB,4096,3072, 3);
    sgemm(true, h0,1024,     aWhh,1024, P.part+3*BB*4096,  4096, BB,4096,1024, 1);
    reduce_kernel<<<(BB*4096+255)/256,256>>>(P.gates, P.part, BB*4096, 4, 4095, abih, abhh);
    lstm_kernel<<<(BR+255)/256,256>>>(P.gates, c0, P.hatt, P.catt);
    sgemm(true, P.hatt,1024, e1W+1024,2048, P.part, 1024, BB,1024,1024, 4);
    reduce_kernel<<<(BB*1024+255)/256,256>>>(P.ht1, P.part, BB*1024, 4, 1023, nullptr, nullptr);
    sgemm(true, P.hatt,1024, e2W+1024,2048, P.part, 1024, BB,1024,1024, 4);
    reduce_kernel<<<(BB*1024+255)/256,256>>>(P.ht2, P.part, BB*1024, 4, 1023, nullptr, nullptr);
    sgemm(false, prev_h,1024, gW0+1024*1024,1024, P.part, 1024, BB,1024,1024, 4);
    reduce_kernel<<<(BB*1024+255)/256,256>>>(P.pvec, P.part, BB*1024, 4, 1023, nullptr, nullptr);

    // ---- join ----
    cudaEventRecord(g_ev2, g_s2);
    cudaStreamWaitEvent(0, g_ev2, 0);

    // ---- E1/E2 (2-pass: A=GEM hi, B=weights hi+lo) ----
    hmma_gemm<2><<<dim3(8,256,1),128,MMA_SMEM>>>(P.Ph,nullptr,1024,0, P.W1h,P.W1l,1024,0,
        1024, 0, 1, 0, nullptr,0,nullptr, P.Qh,P.Ql,1024, e1b, P.ht1, mask, nullptr);
    hmma_gemm<2><<<dim3(8,256,1),128,MMA_SMEM>>>(P.Ph,nullptr,1024,0, P.W2h,P.W2l,1024,0,
        1024, 0, 1, 0, nullptr,0,nullptr, P.Sh,P.Sl,1024, e2b, P.ht2, mask, nullptr);

    // ---- Adj = E1 @ E2^T (3-pass, fused batch-min) ----
    hmma_gemm<3><<<dim3(4,4,64),128,MMA_SMEM>>>(P.Qh,P.Ql,1024,(long)NN*RR, P.Sh,P.Sl,1024,(long)NN*RR,
        1024, 512, 0, 0, P.adj,512,P.minu, nullptr,nullptr,0, nullptr,nullptr,nullptr,nullptr);

    // ---- Adj post-processing ----
    topk_kernel<<<BB*NN,512>>>(P.adj, P.minu, mask, P.dvec);
    rowfinal_kernel<<<BB*NN/8,256>>>(P.adj, P.dvec, mask, P.ADJh, P.srow);

    // ---- GCN layer 0 (1-pass) ----
    hmma_gemm<1><<<dim3(8,256,1),128,MMA_SMEM>>>(P.Ph,nullptr,1024,0, P.G0h,nullptr,1024,0,
        1024, 0, 2, 0, nullptr,0,nullptr, P.Qh,nullptr,0, nullptr, nullptr, nullptr, nullptr);
    hmma_gemm<1><<<dim3(8,4,64),128,MMA_SMEM>>>(P.ADJh,nullptr,512,(long)NN*NN, P.Qh,nullptr,512,(long)RR*NN,
        512, 512, 1, 1, nullptr,0,nullptr, P.Sh,nullptr,1024, gb0, P.pvec, P.srow, mask);

    // ---- GCN layer 1 (1-pass) ----
    hmma_gemm<1><<<dim3(8,256,1),128,MMA_SMEM>>>(P.Sh,nullptr,1024,0, P.G1h,nullptr,1024,0,
        1024, 0, 2, 0, nullptr,0,nullptr, P.Ph,nullptr,0, nullptr, nullptr, nullptr, nullptr);
    hmma_gemm<1><<<dim3(8,4,64),128,MMA_SMEM>>>(P.ADJh,nullptr,512,(long)NN*NN, P.Ph,nullptr,512,(long)RR*NN,
        512, 512, 1, 1, nullptr,0,nullptr, P.Qh,nullptr,1024, gb1, nullptr, nullptr, mask);

    // ---- GCN layer 2 (1-pass) ----
    hmma_gemm<1><<<dim3(8,256,1),128,MMA_SMEM>>>(P.Qh,nullptr,1024,0, P.G2h,nullptr,1024,0,
        1024, 0, 2, 0, nullptr,0,nullptr, P.Sh,nullptr,0, nullptr, nullptr, nullptr, nullptr);
    hmma_gemm<1><<<dim3(8,4,64),128,MMA_SMEM>>>(P.ADJh,nullptr,512,(long)NN*NN, P.Sh,nullptr,512,(long)RR*NN,
        512, 512, 2, 1, nullptr,0,nullptr, P.Ph,nullptr,0, gb2, nullptr, nullptr, mask);

    // ---- att = max over nodes ----
    colmaxT_kernel<<<(BB*RR*32+255)/256,256>>>(P.Ph, P.attv);

    // ---- language LSTM ----
    concat2_kernel<<<(BB*2048+255)/256,256>>>(P.attv, P.hatt, P.xl);
    sgemm(true, P.xl,2048,   lWih,2048, P.part,           4096, BB,4096,2048, 2);
    sgemm(true, prev_h,1024, lWhh,1024, P.part+2*BB*4096, 4096, BB,4096,1024, 1);
    reduce_kernel<<<(BB*4096+255)/256,256>>>(P.gates2, P.part, BB*4096, 3, 4095, lbih, lbhh);
    lstm_kernel<<<(BR+255)/256,256>>>(P.gates2, c1, P.hlang, P.clang);

    pack_kernel<<<(BR+255)/256,256>>>(P.hatt, P.catt, P.hlang, P.clang, out, out_size);
}

// round 13
// speedup vs baseline: 5.1672x; 1.1274x over previous
#include <cuda_runtime.h>
#include <cuda_fp16.h>
#include <math.h>
#include <stdint.h>

#define BB 64
#define NN 512
#define RR 1024
#define KTOP 256
#define BR (BB*RR)
#define NGE ((long)BB*NN*RR)

// ---------------- device scratch ----------------
__device__ float g_adj[(long)BB*NN*NN];
__device__ unsigned g_minu[BB];
__device__ float g_xcat[BB*3072];
__device__ float g_gates[BB*4096];
__device__ float g_gates2[BB*4096];
__device__ float g_part[4*BB*4096];
__device__ float g_ht1[BB*RR];
__device__ float g_ht2[BB*RR];
__device__ float g_pvec[BB*RR];
__device__ float g_srow[BB*NN];
__device__ float g_dvec[BB*NN];
__device__ float g_attv[BB*RR];
__device__ float g_xl[BB*2048];
__device__ float g_hatt[BR];
__device__ float g_catt[BR];
__device__ float g_hlang[BR];
__device__ float g_clang[BR];

__device__ __half g_Ph[NGE];              // GEM(hi) -> Z1^T -> X3^T
__device__ __half g_Qh[NGE], g_Ql[NGE];   // E1 -> X2
__device__ __half g_Sh[NGE], g_Sl[NGE];   // E2 -> X1 -> Z2^T
__device__ __half g_Z0h[NGE];             // Z0^T (computed on s2)
__device__ __half g_ADJh[(long)BB*NN*NN];
__device__ __half g_W1h[1048576], g_W1l[1048576];
__device__ __half g_W2h[1048576], g_W2l[1048576];
__device__ __half g_G0h[1048576];
__device__ __half g_G1h[1048576];
__device__ __half g_G2h[1048576];

// monotone uint encoding for float ordering
__device__ __forceinline__ unsigned fenc(float f){
    unsigned u = __float_as_uint(f);
    return (u & 0x80000000u) ? ~u : (u | 0x80000000u);
}
__device__ __forceinline__ float fdec(unsigned v){
    unsigned u = (v & 0x80000000u) ? (v ^ 0x80000000u) : ~v;
    return __uint_as_float(u);
}

// ---------------- warp MMA helpers ----------------
__device__ __forceinline__ uint32_t smem_u32(const void* p){
    uint32_t a;
    asm("{ .reg .u64 t; cvta.to.shared.u64 t, %1; cvt.u32.u64 %0, t; }" : "=r"(a) : "l"(p));
    return a;
}
__device__ __forceinline__ uint32_t swz64(uint32_t x){ return x ^ ((x>>3)&0x30u); }
__device__ __forceinline__ void ldm4(uint32_t* r, uint32_t addr){
    asm volatile("ldmatrix.sync.aligned.m8n8.x4.shared.b16 {%0,%1,%2,%3}, [%4];"
        : "=r"(r[0]),"=r"(r[1]),"=r"(r[2]),"=r"(r[3]) : "r"(addr));
}
__device__ __forceinline__ void mma16816(float* d, const uint32_t* a, const uint32_t* b){
    asm volatile("mma.sync.aligned.m16n8k16.row.col.f32.f16.f16.f32 "
        "{%0,%1,%2,%3}, {%4,%5,%6,%7}, {%8,%9}, {%0,%1,%2,%3};"
        : "+f"(d[0]),"+f"(d[1]),"+f"(d[2]),"+f"(d[3])
        : "r"(a[0]),"r"(a[1]),"r"(a[2]),"r"(a[3]), "r"(b[0]),"r"(b[1]));
}
__device__ __forceinline__ void cpasync16(uint32_t dst, const void* src){
    asm volatile("cp.async.cg.shared.global [%0], [%1], 16;" :: "r"(dst), "l"(src));
}

// ---------------- fp16 hi/lo tensor-core GEMM, 3-stage cp.async ----------------
#define MMA_SMEM (3*32768+1024)

template<int PASSES>
__global__ void __launch_bounds__(128,2) hmma_gemm(
    const __half* __restrict__ Ah, const __half* __restrict__ Al, int lda, long sA,
    const __half* __restrict__ Bh, const __half* __restrict__ Bl, int ldb, long sB,
    int K, int rowsPerZ, int outMode, int relu,
    float* Cf, int ldc, unsigned* minu,
    __half* Ch, __half* Cl, int ldch,
    const float* __restrict__ bias, const float* __restrict__ addv,
    const float* __restrict__ rs, const float* __restrict__ ps)
{
    extern __shared__ char smraw[];
    uint32_t sb0 = smem_u32(smraw);
    uint32_t sb  = (sb0 + 1023u) & ~1023u;
    const int tid = threadIdx.x, wid = tid>>5, lane = tid&31;

    const __half* A0 = Ah + blockIdx.z*sA;
    const __half* A1 = (PASSES==3) ? (Al + blockIdx.z*sA) : nullptr;
    const __half* B0 = Bh + blockIdx.z*sB;
    const __half* B1 = (PASSES>=2) ? (Bl + blockIdx.z*sB) : nullptr;
    const int rowBase = blockIdx.y*128, colBase = blockIdx.x*128;
    const int NC = K >> 5;

    const int wr = wid>>1, wc = wid&1;
    const int lr = lane&7, q = lane>>3;
    const int aRowOff = ((q&1)<<3) + lr;
    const int aKbOff  = (q>>1)<<4;
    const int bRowOff = ((q>>1)<<3) + lr;
    const int bKbOff  = (q&1)<<4;

    const int cp_row = tid>>2;
    const int cp_u   = tid&3;

    float acc[4][8][4];
    #pragma unroll
    for (int a=0;a<4;a++)
        #pragma unroll
        for (int b=0;b<8;b++)
            #pragma unroll
            for (int c=0;c<4;c++) acc[a][b][c]=0.f;

    auto load_chunk = [&](int ci, int s){
        const int k0 = ci<<5;
        const uint32_t st = sb + s*32768;
        #pragma unroll
        for (int j=0;j<4;j++){
            int r = cp_row + j*32;
            uint32_t doff = swz64((uint32_t)(r*64 + cp_u*16));
            long aoff = (long)(rowBase+r)*lda + k0 + cp_u*8;
            long boff = (long)(colBase+r)*ldb + k0 + cp_u*8;
            cpasync16(st +         doff, A0 + aoff);
            if (PASSES==3) cpasync16(st + 8192 + doff, A1 + aoff);
            cpasync16(st + 16384 + doff, B0 + boff);
            if (PASSES>=2) cpasync16(st + 24576 + doff, B1 + boff);
        }
        asm volatile("cp.async.commit_group;" ::: "memory");
    };

    load_chunk(0, 0);
    if (NC > 1) load_chunk(1, 1);

    int sidx = 0;
    int nidx = (NC > 2) ? 2 : 0;
    for (int i=0;i<NC;i++){
        if (i+1 < NC) asm volatile("cp.async.wait_group 1;" ::: "memory");
        else          asm volatile("cp.async.wait_group 0;" ::: "memory");
        __syncthreads();
        if (i+2 < NC){
            load_chunk(i+2, nidx);
            nidx = (nidx==2)?0:nidx+1;
        }
        const uint32_t st = sb + sidx*32768;
        sidx = (sidx==2)?0:sidx+1;
        #pragma unroll
        for (int ks=0;ks<2;ks++){
            const uint32_t kb = ks<<5;
            uint32_t bh[4][4], bl[4][4], af[4][4];
            #pragma unroll
            for (int t=0;t<4;t++){
                uint32_t ro = (uint32_t)((wc*64 + t*16 + bRowOff)*64) + kb + bKbOff;
                ldm4(bh[t], st + 16384 + swz64(ro));
                if (PASSES>=2) ldm4(bl[t], st + 24576 + swz64(ro));
            }
            #pragma unroll
            for (int mi=0;mi<4;mi++){
                uint32_t ro = (uint32_t)((wr*64 + mi*16 + aRowOff)*64) + kb + aKbOff;
                ldm4(af[mi], st + swz64(ro));
            }
            #pragma unroll
            for (int mi=0;mi<4;mi++)
                #pragma unroll
                for (int t=0;t<4;t++){
                    mma16816(acc[mi][2*t],   af[mi], &bh[t][0]);
                    mma16816(acc[mi][2*t+1], af[mi], &bh[t][2]);
                }
            if (PASSES>=2){
                #pragma unroll
                for (int mi=0;mi<4;mi++)
                    #pragma unroll
                    for (int t=0;t<4;t++){
                        mma16816(acc[mi][2*t],   af[mi], &bl[t][0]);
                        mma16816(acc[mi][2*t+1], af[mi], &bl[t][2]);
                    }
            }
            if (PASSES==3){
                #pragma unroll
                for (int mi=0;mi<4;mi++){
                    uint32_t ro = (uint32_t)((wr*64 + mi*16 + aRowOff)*64) + kb + aKbOff;
                    ldm4(af[mi], st + 8192 + swz64(ro));
                }
                #pragma unroll
                for (int mi=0;mi<4;mi++)
                    #pragma unroll
                    for (int t=0;t<4;t++){
                        mma16816(acc[mi][2*t],   af[mi], &bh[t][0]);
                        mma16816(acc[mi][2*t+1], af[mi], &bh[t][2]);
                    }
            }
        }
    }

    // ---- epilogue ----
    const int cpair = (lane&3)*2;
    float lmin = INFINITY;
    #pragma unroll
    for (int mi=0;mi<4;mi++){
        #pragma unroll
        for (int rr=0;rr<2;rr++){
            const int r  = rowBase + wr*64 + mi*16 + (lane>>2) + rr*8;
            const int gr = blockIdx.z*rowsPerZ + r;
            const float rsv = rs ? rs[gr] : 1.f;
            const float psv = ps ? ps[gr] : 1.f;
            const float* avp = addv ? addv + (long)(gr>>9)*RR : nullptr;
            #pragma unroll
            for (int ni=0;ni<8;ni++){
                const int c = colBase + wc*64 + ni*8 + cpair;
                float x0 = acc[mi][ni][rr*2+0];
                float x1 = acc[mi][ni][rr*2+1];
                if (avp){ x0 += rsv*avp[c]; x1 += rsv*avp[c+1]; }
                if (bias){ x0 += bias[c]; x1 += bias[c+1]; }
                if (relu){ x0 = fmaxf(x0,0.f); x1 = fmaxf(x1,0.f); }
                x0 *= psv; x1 *= psv;
                if (outMode==0){
                    *(float2*)(Cf + (long)gr*ldc + c) = make_float2(x0,x1);
                    lmin = fminf(lmin, fminf(x0,x1));
                } else {
                    __half h0 = __float2half_rn(x0);
                    __half h1 = __float2half_rn(x1);
                    if (outMode==1){
                        long o = (long)gr*ldch + c;
                        *(__half2*)(Ch+o) = __halves2half2(h0,h1);
                        if (Cl){
                            __half l0 = __float2half_rn(x0-__half2float(h0));
                            __half l1 = __float2half_rn(x1-__half2float(h1));
                            *(__half2*)(Cl+o) = __halves2half2(l0,l1);
                        }
                    } else { // transposed: out[b][feat][node]
                        long base = (long)(gr>>9)*((long)RR*NN) + (gr&511);
                        long o0 = base + (long)c*NN;
                        Ch[o0]=h0; Ch[o0+NN]=h1;
                        if (Cl){
                            Cl[o0]   = __float2half_rn(x0-__half2float(h0));
                            Cl[o0+NN]= __float2half_rn(x1-__half2float(h1));
                        }
                    }
                }
            }
        }
    }
    if (outMode==0 && minu){
        #pragma unroll
        for (int o=16;o;o>>=1) lmin = fminf(lmin, __shfl_xor_sync(0xffffffffu, lmin, o));
        if (lane==0) atomicMin(&minu[blockIdx.z], fenc(lmin));
    }
}

// ---------------- FFMA split-K GEMM for small (B=64) matmuls ----------------
template<bool BT>
__global__ void __launch_bounds__(256) gemm_part(
    const float* __restrict__ A,int lda,
    const float* __restrict__ B,int ldb,
    float* __restrict__ C,int ldc,long partStride,int chunkK)
{
    __shared__ float As[16][64];
    __shared__ float Bs[16][64];
    const int tid = threadIdx.x;
    const int rowBase = blockIdx.y*64, colBase = blockIdx.x*64;
    const int kbeg = blockIdx.z*chunkK, kend = kbeg + chunkK;
    const int tx = tid & 15, ty = tid >> 4;
    float acc[4][4];
#pragma unroll
    for (int i=0;i<4;i++)
#pragma unroll
        for (int j=0;j<4;j++) acc[i][j]=0.f;

    for (int k0=kbeg;k0<kend;k0+=16){
#pragma unroll
        for (int i=tid*4;i<64*16;i+=256*4){
            int r=i>>4, kk=i&15;
            float4 v = *(const float4*)(A + (long)(rowBase+r)*lda + k0 + kk);
            As[kk+0][r]=v.x; As[kk+1][r]=v.y; As[kk+2][r]=v.z; As[kk+3][r]=v.w;
        }
        if (BT){
#pragma unroll
            for (int i=tid*4;i<64*16;i+=256*4){
                int r=i>>4, kk=i&15;
                float4 v = *(const float4*)(B + (long)(colBase+r)*ldb + k0 + kk);
                Bs[kk+0][r]=v.x; Bs[kk+1][r]=v.y; Bs[kk+2][r]=v.z; Bs[kk+3][r]=v.w;
            }
        } else {
#pragma unroll
            for (int i=tid*4;i<16*64;i+=256*4){
                int r=i>>6, cc=i&63;
                *(float4*)&Bs[r][cc] = *(const float4*)(B + (long)(k0+r)*ldb + colBase + cc);
            }
        }
        __syncthreads();
#pragma unroll
        for (int k=0;k<16;k++){
            float a[4], b[4];
            *(float4*)a = *(const float4*)&As[k][ty*4];
            *(float4*)b = *(const float4*)&Bs[k][tx*4];
#pragma unroll
            for (int i=0;i<4;i++)
#pragma unroll
                for (int j=0;j<4;j++) acc[i][j] = fmaf(a[i], b[j], acc[i][j]);
        }
        __syncthreads();
    }
    float* Cp = C + (long)blockIdx.z*partStride;
#pragma unroll
    for (int i=0;i<4;i++){
        int r = rowBase + ty*4 + i;
#pragma unroll
        for (int j=0;j<4;j++)
            Cp[(long)r*ldc + colBase + tx*4 + j] = acc[i][j];
    }
}
static void sgemm(bool BT,const float* A,int lda,const float* B,int ldb,float* Cpart,int ldc,
                  int M,int N,int K,int splits){
    dim3 g(N/64, M/64, splits);
    int chunkK = K/splits;
    if (BT) gemm_part<true ><<<g,256>>>(A,lda,B,ldb,Cpart,ldc,(long)M*ldc,chunkK);
    else    gemm_part<false><<<g,256>>>(A,lda,B,ldb,Cpart,ldc,(long)M*ldc,chunkK);
}
__global__ void reduce_kernel(float* dst,const float* src,long len,int splits,int colmask,
                              const float* b1,const float* b2){
    long i = (long)blockIdx.x*blockDim.x+threadIdx.x;
    if (i >= len) return;
    float s = 0.f;
    for (int z=0;z<splits;z++) s += src[z*len+i];
    int col = (int)(i & colmask);
    if (b1) s += b1[col];
    if (b2) s += b2[col];
    dst[i] = s;
}

// ---------------- conversions ----------------
__device__ __forceinline__ void split1(float v, __half& h, __half& l){
    h = __float2half_rn(v);
    l = __float2half_rn(v - __half2float(h));
}

__global__ void conv_mask_kernel(const float* __restrict__ src, const float* __restrict__ mask,
                                 __half* __restrict__ dh, long n4, unsigned* minu){
    long i = (long)blockIdx.x*blockDim.x + threadIdx.x;
    if (i < BB && minu) minu[i] = 0xFFFFFFFFu;
    if (i >= n4) return;
    float4 v = ((const float4*)src)[i];
    float m = mask[i >> 8];
    __align__(8) __half h[4];
    h[0]=__float2half_rn(v.x*m); h[1]=__float2half_rn(v.y*m);
    h[2]=__float2half_rn(v.z*m); h[3]=__float2half_rn(v.w*m);
    ((uint2*)dh)[i] = *(uint2*)h;
}

__global__ void conv_slice_kernel(const float* __restrict__ src, int ldsrc,
                                  __half* __restrict__ dh, __half* __restrict__ dl,
                                  int cols, int n4){
    int i = blockIdx.x*blockDim.x + threadIdx.x;
    if (i >= n4) return;
    int c4pr = cols/4;
    int r = i / c4pr, c4 = i % c4pr;
    float4 v = *(const float4*)(src + (long)r*ldsrc + c4*4);
    __align__(8) __half h[4], l[4];
    split1(v.x,h[0],l[0]); split1(v.y,h[1],l[1]); split1(v.z,h[2],l[2]); split1(v.w,h[3],l[3]);
    long o = (long)r*c4pr + c4;
    ((uint2*)dh)[o] = *(uint2*)h;
    ((uint2*)dl)[o] = *(uint2*)l;
}

__global__ void tconv_kernel(const float* __restrict__ src, int rows, int cols,
                             __half* __restrict__ dh){
    __shared__ float t[32][33];
    int r0 = blockIdx.y*32, c0 = blockIdx.x*32;
    int tx = threadIdx.x, ty = threadIdx.y;
    for (int i=ty;i<32;i+=8)
        t[i][tx] = src[(long)(r0+i)*cols + c0+tx];
    __syncthreads();
    for (int i=ty;i<32;i+=8){
        long o = (long)(c0+i)*rows + r0+tx;
        dh[o] = __float2half_rn(t[tx][i]);
    }
}

// ---------------- pointwise / reductions ----------------
__device__ __forceinline__ float sigm(float x){ return 1.f/(1.f+__expf(-x)); }

__global__ void concat3_kernel(const float* a,const float* b,const float* c,float* out){
    int idx = blockIdx.x*blockDim.x+threadIdx.x;
    if (idx >= BB*3072) return;
    int bb = idx/3072, j = idx%3072;
    out[idx] = (j<1024) ? a[bb*1024+j] : (j<2048 ? b[bb*1024+j-1024] : c[bb*1024+j-2048]);
}
__global__ void concat2_kernel(const float* a,const float* b,float* out){
    int idx = blockIdx.x*blockDim.x+threadIdx.x;
    if (idx >= BB*2048) return;
    int bb = idx/2048, j = idx%2048;
    out[idx] = (j<1024) ? a[bb*1024+j] : b[bb*1024+j-1024];
}
__global__ void lstm_kernel(const float* gates,const float* c_prev,float* h_out,float* c_out){
    int idx = blockIdx.x*blockDim.x+threadIdx.x;
    if (idx >= BR) return;
    int bb = idx >> 10, r = idx & 1023;
    const float* g = gates + bb*4096;
    float c = sigm(g[1024+r])*c_prev[idx] + sigm(g[r])*tanhf(g[2048+r]);
    h_out[idx] = sigm(g[3072+r])*tanhf(c);
    c_out[idx] = c;
}

// topk: hybrid shfl/smem bitonic sort; writes raw fp16 row (zeroed except kept) + dvec.
__global__ void __launch_bounds__(512) topk_kernel(const float* __restrict__ Adj,
                                                   const unsigned* __restrict__ minu,
                                                   const float* __restrict__ mask,
                                                   __half* __restrict__ Araw, float* dvec){
    __shared__ unsigned long long sk[NN];
    __shared__ float red[NN];
    int row = blockIdx.x, t = threadIdx.x, bb = row >> 9;
    float mrow = mask[row];
    float mn = fdec(minu[bb]);
    float v = (Adj[(long)row*NN + t] - mn) * mrow;
    unsigned long long key = ((unsigned long long)__float_as_uint(v) << 32) | (unsigned)(NN-1-t);
    #pragma unroll
    for (unsigned k2=2;k2<=NN;k2<<=1){
        for (unsigned j=k2>>1;j>0;j>>=1){
            unsigned long long other;
            if (j < 32){
                unsigned lo = __shfl_xor_sync(0xffffffffu, (unsigned)key, j);
                unsigned hi = __shfl_xor_sync(0xffffffffu, (unsigned)(key>>32), j);
                other = ((unsigned long long)hi << 32) | lo;
            } else {
                sk[t] = key; __syncthreads();
                other = sk[t ^ j]; __syncthreads();
            }
            bool lower = ((t & j) == 0);
            bool desc  = ((t & k2) == 0);
            unsigned long long mx  = (key > other) ? key : other;
            unsigned long long mnk = (key > other) ? other : key;
            key = (desc == lower) ? mx : mnk;
        }
    }
    // position t holds the t-th largest (ties: smaller original index first)
    int col = (NN-1) - (int)(unsigned)(key & 0xffffffffu);
    float val = __uint_as_float((unsigned)(key >> 32));
    __half* ar = Araw + (long)row*NN;
    ar[t] = __float2half_rn(0.f);
    __syncthreads();
    float s = 0.f;
    if (t < KTOP){
        ar[col] = __float2half_rn(val);
        s = val;
    }
    red[t]=s; __syncthreads();
    for (int st=NN/2;st>0;st>>=1){ if (t<st) red[t]+=red[t+st]; __syncthreads(); }
    if (t==0) dvec[row] = (red[0] > 0.f) ? rsqrtf(red[0]) : 0.f;
}

// in-place fp16 scale: Ah[row][c] *= d_r*d_c ; srow[r] = sum_c scaled*mask_c
__global__ void rowfinal_kernel(__half* __restrict__ Ah, const float* __restrict__ dvec,
                                const float* __restrict__ mask, float* __restrict__ srow){
    int row = blockIdx.x*8 + (threadIdx.x>>5);
    int lane = threadIdx.x & 31;
    int bb = row >> 9;
    const float dr = dvec[row];
    const float* dc = dvec + (bb<<9);
    const float* m  = mask + (bb<<9);
    __half* ar = Ah + (long)row*NN;
    float s = 0.f;
    for (int k=lane*4; k<NN; k+=128){
        uint2 raw = *(uint2*)(ar+k);
        __align__(8) __half h[4]; *(uint2*)h = raw;
        float4 d4 = *(const float4*)(dc+k);
        float4 m4 = *(const float4*)(m+k);
        float x0=__half2float(h[0])*dr*d4.x, x1=__half2float(h[1])*dr*d4.y;
        float x2=__half2float(h[2])*dr*d4.z, x3=__half2float(h[3])*dr*d4.w;
        s += x0*m4.x + x1*m4.y + x2*m4.z + x3*m4.w;
        h[0]=__float2half_rn(x0); h[1]=__float2half_rn(x1);
        h[2]=__float2half_rn(x2); h[3]=__float2half_rn(x3);
        *(uint2*)(ar+k) = *(uint2*)h;
    }
    for (int o=16;o;o>>=1) s += __shfl_xor_sync(0xffffffffu, s, o);
    if (lane==0) srow[row] = s;
}
__global__ void colmaxT_kernel(const __half* Xh,float* att){
    int warp = (blockIdx.x*blockDim.x+threadIdx.x) >> 5;
    int lane = threadIdx.x & 31;
    if (warp >= BB*RR) return;
    const __half2* x2 = (const __half2*)(Xh + (long)warp*NN);
    float mx = -INFINITY;
    for (int k=lane;k<NN/2;k+=32){
        __half2 h = x2[k];
        mx = fmaxf(mx, fmaxf(__low2float(h), __high2float(h)));
    }
    for (int o=16;o;o>>=1) mx = fmaxf(mx, __shfl_xor_sync(0xffffffffu, mx, o));
    if (lane==0) att[warp] = mx;
}
__global__ void pack_kernel(const float* hatt,const float* catt,
                            const float* hlang,const float* clang,float* out,int out_size){
    int i = blockIdx.x*blockDim.x+threadIdx.x;
    if (i >= BR) return;
    out[i] = hlang[i];
    if (out_size >= 5*BR){
        out[1*BR+i] = hatt[i];
        out[2*BR+i] = hlang[i];
        out[3*BR+i] = catt[i];
        out[4*BR+i] = clang[i];
    }
}

// ---------------- host driver ----------------
struct Ptrs {
    float *adj,*xcat,*gates,*gates2,*part,*ht1,*ht2,*pvec,*srow,*dvec,*attv,*xl,*hatt,*catt,*hlang,*clang;
    unsigned* minu;
    __half *Ph,*Qh,*Ql,*Sh,*Sl,*Z0h,*ADJh;
    __half *W1h,*W1l,*W2h,*W2l,*G0h,*G1h,*G2h;
};
static Ptrs P;
static bool g_init = false;
static cudaStream_t g_s2;
static cudaEvent_t g_ev1, g_ev2, g_ev3;

extern "C" void kernel_launch(void* const* d_in, const int* in_sizes, int n_in,
                              void* d_out, int out_size)
{
    const float* xt   = (const float*)d_in[0];
    const float* fc   = (const float*)d_in[1];
    const float* ge   = (const float*)d_in[2];
    const float* sh   = (const float*)d_in[4];
    const float* sc   = (const float*)d_in[5];
    const float* mask = (const float*)d_in[6];
    const float* aWih = (const float*)d_in[7];
    const float* aWhh = (const float*)d_in[8];
    const float* abih = (const float*)d_in[9];
    const float* abhh = (const float*)d_in[10];
    const float* lWih = (const float*)d_in[11];
    const float* lWhh = (const float*)d_in[12];
    const float* lbih = (const float*)d_in[13];
    const float* lbhh = (const float*)d_in[14];
    const float* e1W  = (const float*)d_in[15];
    const float* e1b  = (const float*)d_in[16];
    const float* e2W  = (const float*)d_in[17];
    const float* e2b  = (const float*)d_in[18];
    const float* gW0  = (const float*)d_in[19];
    const float* gb0  = (const float*)d_in[20];
    const float* gW1  = (const float*)d_in[21];
    const float* gb1  = (const float*)d_in[22];
    const float* gW2  = (const float*)d_in[23];
    const float* gb2  = (const float*)d_in[24];
    (void)in_sizes; (void)n_in;
    float* out = (float*)d_out;

    if (!g_init){
        cudaGetSymbolAddress((void**)&P.adj,  g_adj);
        cudaGetSymbolAddress((void**)&P.minu, g_minu);
        cudaGetSymbolAddress((void**)&P.xcat, g_xcat);
        cudaGetSymbolAddress((void**)&P.gates,g_gates);
        cudaGetSymbolAddress((void**)&P.gates2,g_gates2);
        cudaGetSymbolAddress((void**)&P.part, g_part);
        cudaGetSymbolAddress((void**)&P.ht1,  g_ht1);
        cudaGetSymbolAddress((void**)&P.ht2,  g_ht2);
        cudaGetSymbolAddress((void**)&P.pvec, g_pvec);
        cudaGetSymbolAddress((void**)&P.srow, g_srow);
        cudaGetSymbolAddress((void**)&P.dvec, g_dvec);
        cudaGetSymbolAddress((void**)&P.attv, g_attv);
        cudaGetSymbolAddress((void**)&P.xl,   g_xl);
        cudaGetSymbolAddress((void**)&P.hatt, g_hatt);
        cudaGetSymbolAddress((void**)&P.catt, g_catt);
        cudaGetSymbolAddress((void**)&P.hlang,g_hlang);
        cudaGetSymbolAddress((void**)&P.clang,g_clang);
        cudaGetSymbolAddress((void**)&P.Ph, g_Ph);
        cudaGetSymbolAddress((void**)&P.Qh, g_Qh); cudaGetSymbolAddress((void**)&P.Ql, g_Ql);
        cudaGetSymbolAddress((void**)&P.Sh, g_Sh); cudaGetSymbolAddress((void**)&P.Sl, g_Sl);
        cudaGetSymbolAddress((void**)&P.Z0h, g_Z0h);
        cudaGetSymbolAddress((void**)&P.ADJh, g_ADJh);
        cudaGetSymbolAddress((void**)&P.W1h, g_W1h); cudaGetSymbolAddress((void**)&P.W1l, g_W1l);
        cudaGetSymbolAddress((void**)&P.W2h, g_W2h); cudaGetSymbolAddress((void**)&P.W2l, g_W2l);
        cudaGetSymbolAddress((void**)&P.G0h, g_G0h);
        cudaGetSymbolAddress((void**)&P.G1h, g_G1h);
        cudaGetSymbolAddress((void**)&P.G2h, g_G2h);
        cudaFuncSetAttribute(hmma_gemm<3>, cudaFuncAttributeMaxDynamicSharedMemorySize, MMA_SMEM);
        cudaFuncSetAttribute(hmma_gemm<2>, cudaFuncAttributeMaxDynamicSharedMemorySize, MMA_SMEM);
        cudaFuncSetAttribute(hmma_gemm<1>, cudaFuncAttributeMaxDynamicSharedMemorySize, MMA_SMEM);
        cudaStreamCreateWithFlags(&g_s2, cudaStreamNonBlocking);
        cudaEventCreateWithFlags(&g_ev1, cudaEventDisableTiming);
        cudaEventCreateWithFlags(&g_ev2, cudaEventDisableTiming);
        cudaEventCreateWithFlags(&g_ev3, cudaEventDisableTiming);
        g_init = true;
    }

    const float* prev_h = sh + BR;
    const float* h0 = sh;
    const float* c0 = sc;
    const float* c1 = sc + BR;

    // ---- fork ----
    cudaEventRecord(g_ev1, 0);
    cudaStreamWaitEvent(g_s2, g_ev1, 0);

    // s2: conversions needed by E1/E2 first, then Z0 GEMM (independent of Adj)
    conv_mask_kernel<<<(int)((NGE/4+255)/256),256,0,g_s2>>>(ge, mask, P.Ph, NGE/4, P.minu);
    conv_slice_kernel<<<(1048576/4+255)/256,256,0,g_s2>>>(e1W, 2048, P.W1h, P.W1l, 1024, 1048576/4);
    conv_slice_kernel<<<(1048576/4+255)/256,256,0,g_s2>>>(e2W, 2048, P.W2h, P.W2l, 1024, 1048576/4);
    cudaEventRecord(g_ev2, g_s2);                 // E1/E2 prerequisites ready
    tconv_kernel<<<dim3(32,32),dim3(32,8),0,g_s2>>>(gW0, 1024, 1024, P.G0h);
    hmma_gemm<1><<<dim3(8,256,1),128,MMA_SMEM,g_s2>>>(P.Ph,nullptr,1024,0, P.G0h,nullptr,1024,0,
        1024, 0, 2, 0, nullptr,0,nullptr, P.Z0h,nullptr,0, nullptr, nullptr, nullptr, nullptr);
    tconv_kernel<<<dim3(32,32),dim3(32,8),0,g_s2>>>(gW1, 1024, 1024, P.G1h);
    tconv_kernel<<<dim3(32,32),dim3(32,8),0,g_s2>>>(gW2, 1024, 1024, P.G2h);
    cudaEventRecord(g_ev3, g_s2);                 // Z0 + G1/G2 ready

    // default stream: LSTM chain
    concat3_kernel<<<(BB*3072+255)/256,256>>>(prev_h, fc, xt, P.xcat);
    sgemm(true, P.xcat,3072, aWih,3072, P.part,            4096, BB,4096,3072, 3);
    sgemm(true, h0,1024,     aWhh,1024, P.part+3*BB*4096,  4096, BB,4096,1024, 1);
    reduce_kernel<<<(BB*4096+255)/256,256>>>(P.gates, P.part, BB*4096, 4, 4095, abih, abhh);
    lstm_kernel<<<(BR+255)/256,256>>>(P.gates, c0, P.hatt, P.catt);
    sgemm(true, P.hatt,1024, e1W+1024,2048, P.part, 1024, BB,1024,1024, 4);
    reduce_kernel<<<(BB*1024+255)/256,256>>>(P.ht1, P.part, BB*1024, 4, 1023, nullptr, nullptr);
    sgemm(true, P.hatt,1024, e2W+1024,2048, P.part, 1024, BB,1024,1024, 4);
    reduce_kernel<<<(BB*1024+255)/256,256>>>(P.ht2, P.part, BB*1024, 4, 1023, nullptr, nullptr);
    sgemm(false, prev_h,1024, gW0+1024*1024,1024, P.part, 1024, BB,1024,1024, 4);
    reduce_kernel<<<(BB*1024+255)/256,256>>>(P.pvec, P.part, BB*1024, 4, 1023, nullptr, nullptr);

    cudaStreamWaitEvent(0, g_ev2, 0);

    // ---- E1/E2 (2-pass) ----
    hmma_gemm<2><<<dim3(8,256,1),128,MMA_SMEM>>>(P.Ph,nullptr,1024,0, P.W1h,P.W1l,1024,0,
        1024, 0, 1, 0, nullptr,0,nullptr, P.Qh,P.Ql,1024, e1b, P.ht1, mask, nullptr);
    hmma_gemm<2><<<dim3(8,256,1),128,MMA_SMEM>>>(P.Ph,nullptr,1024,0, P.W2h,P.W2l,1024,0,
        1024, 0, 1, 0, nullptr,0,nullptr, P.Sh,P.Sl,1024, e2b, P.ht2, mask, nullptr);

    // ---- Adj = E1 @ E2^T (3-pass, fused batch-min) ----
    hmma_gemm<3><<<dim3(4,4,64),128,MMA_SMEM>>>(P.Qh,P.Ql,1024,(long)NN*RR, P.Sh,P.Sl,1024,(long)NN*RR,
        1024, 512, 0, 0, P.adj,512,P.minu, nullptr,nullptr,0, nullptr,nullptr,nullptr,nullptr);

    // ---- Adj post-processing (raw fp16 out) ----
    topk_kernel<<<BB*NN,512>>>(P.adj, P.minu, mask, P.ADJh, P.dvec);
    rowfinal_kernel<<<BB*NN/8,256>>>(P.ADJh, P.dvec, mask, P.srow);

    cudaStreamWaitEvent(0, g_ev3, 0);

    // ---- GCN layer 0: X1 = relu(Adj@Z0 + srow*pvec + b0)*m ----
    hmma_gemm<1><<<dim3(8,4,64),128,MMA_SMEM>>>(P.ADJh,nullptr,512,(long)NN*NN, P.Z0h,nullptr,512,(long)RR*NN,
        512, 512, 1, 1, nullptr,0,nullptr, P.Sh,nullptr,1024, gb0, P.pvec, P.srow, mask);

    // ---- GCN layer 1 ----
    hmma_gemm<1><<<dim3(8,256,1),128,MMA_SMEM>>>(P.Sh,nullptr,1024,0, P.G1h,nullptr,1024,0,
        1024, 0, 2, 0, nullptr,0,nullptr, P.Ph,nullptr,0, nullptr, nullptr, nullptr, nullptr);
    hmma_gemm<1><<<dim3(8,4,64),128,MMA_SMEM>>>(P.ADJh,nullptr,512,(long)NN*NN, P.Ph,nullptr,512,(long)RR*NN,
        512, 512, 1, 1, nullptr,0,nullptr, P.Qh,nullptr,1024, gb1, nullptr, nullptr, mask);

    // ---- GCN layer 2 ----
    hmma_gemm<1><<<dim3(8,256,1),128,MMA_SMEM>>>(P.Qh,nullptr,1024,0, P.G2h,nullptr,1024,0,
        1024, 0, 2, 0, nullptr,0,nullptr, P.Sh,nullptr,0, nullptr, nullptr, nullptr, nullptr);
    hmma_gemm<1><<<dim3(8,4,64),128,MMA_SMEM>>>(P.ADJh,nullptr,512,(long)NN*NN, P.Sh,nullptr,512,(long)RR*NN,
        512, 512, 2, 1, nullptr,0,nullptr, P.Ph,nullptr,0, gb2, nullptr, nullptr, mask);

    // ---- att = max over nodes ----
    colmaxT_kernel<<<(BB*RR*32+255)/256,256>>>(P.Ph, P.attv);

    // ---- language LSTM ----
    concat2_kernel<<<(BB*2048+255)/256,256>>>(P.attv, P.hatt, P.xl);
    sgemm(true, P.xl,2048,   lWih,2048, P.part,           4096, BB,4096,2048, 2);
    sgemm(true, prev_h,1024, lWhh,1024, P.part+2*BB*4096, 4096, BB,4096,1024, 1);
    reduce_kernel<<<(BB*4096+255)/256,256>>>(P.gates2, P.part, BB*4096, 3, 4095, lbih, lbhh);
    lstm_kernel<<<(BR+255)/256,256>>>(P.gates2, c1, P.hlang, P.clang);

    pack_kernel<<<(BR+255)/256,256>>>(P.hatt, P.catt, P.hlang, P.clang, out, out_size);
}

// round 14
// speedup vs baseline: 5.8691x; 1.1358x over previous
#include <cuda_runtime.h>
#include <cuda_fp16.h>
#include <math.h>
#include <stdint.h>

#define BB 64
#define NN 512
#define RR 1024
#define KTOP 256
#define BR (BB*RR)
#define NGE ((long)BB*NN*RR)

// ---------------- device scratch ----------------
__device__ float g_adj[(long)BB*NN*NN];
__device__ unsigned g_minu[BB];
__device__ float g_xcat[BB*3072];
__device__ float g_gates[BB*4096];
__device__ float g_gates2[BB*4096];
__device__ float g_part[4*BB*4096];
__device__ float g_ht1[BB*RR];
__device__ float g_ht2[BB*RR];
__device__ float g_pvec[BB*RR];
__device__ float g_srow[BB*NN];
__device__ float g_dvec[BB*NN];
__device__ unsigned g_attu[BB*RR];
__device__ float g_xl[BB*2048];
__device__ float g_hatt[BR];
__device__ float g_catt[BR];
__device__ float g_hlang[BR];
__device__ float g_clang[BR];
// rank-1 machinery
__device__ float g_Vra[BB*RR], g_Vca[BB*RR];
__device__ float g_Vrb[RR], g_Vcb[RR];
__device__ float g_smm[BB], g_sm1[BB], g_s1m[BB], g_s11[1];
__device__ float g_ra[BB*NN], g_rb[BB*NN], g_ca[BB*NN], g_cb[BB*NN];

__device__ __half g_Ph[NGE];              // GEM(hi) -> Z1^T
__device__ __half g_Qh[NGE], g_Ql[NGE];   // U -> X2
__device__ __half g_Sh[NGE], g_Sl[NGE];   // X1 -> Z2^T
__device__ __half g_Z0h[NGE];
__device__ __half g_ADJh[(long)BB*NN*NN];
__device__ __half g_W1h[1048576], g_W1l[1048576];  // TA = tconv(e1W left)
__device__ __half g_W2h[1048576], g_W2l[1048576];  // TB = tconv(e2W left)
__device__ __half g_Wmh[1048576], g_Wml[1048576];  // Wmt
__device__ __half g_G0h[1048576];
__device__ __half g_G1h[1048576];
__device__ __half g_G2h[1048576];

__device__ __forceinline__ unsigned fenc(float f){
    unsigned u = __float_as_uint(f);
    return (u & 0x80000000u) ? ~u : (u | 0x80000000u);
}
__device__ __forceinline__ float fdec(unsigned v){
    unsigned u = (v & 0x80000000u) ? (v ^ 0x80000000u) : ~v;
    return __uint_as_float(u);
}

// ---------------- warp MMA helpers ----------------
__device__ __forceinline__ uint32_t smem_u32(const void* p){
    uint32_t a;
    asm("{ .reg .u64 t; cvta.to.shared.u64 t, %1; cvt.u32.u64 %0, t; }" : "=r"(a) : "l"(p));
    return a;
}
__device__ __forceinline__ uint32_t swz64(uint32_t x){ return x ^ ((x>>3)&0x30u); }
__device__ __forceinline__ void ldm4(uint32_t* r, uint32_t addr){
    asm volatile("ldmatrix.sync.aligned.m8n8.x4.shared.b16 {%0,%1,%2,%3}, [%4];"
        : "=r"(r[0]),"=r"(r[1]),"=r"(r[2]),"=r"(r[3]) : "r"(addr));
}
__device__ __forceinline__ void mma16816(float* d, const uint32_t* a, const uint32_t* b){
    asm volatile("mma.sync.aligned.m16n8k16.row.col.f32.f16.f16.f32 "
        "{%0,%1,%2,%3}, {%4,%5,%6,%7}, {%8,%9}, {%0,%1,%2,%3};"
        : "+f"(d[0]),"+f"(d[1]),"+f"(d[2]),"+f"(d[3])
        : "r"(a[0]),"r"(a[1]),"r"(a[2]),"r"(a[3]), "r"(b[0]),"r"(b[1]));
}
__device__ __forceinline__ void cpasync16(uint32_t dst, const void* src){
    asm volatile("cp.async.cg.shared.global [%0], [%1], 16;" :: "r"(dst), "l"(src));
}

// ---------------- fp16 hi/lo tensor-core GEMM ----------------
// PASSES: 1 = Ah@Bh; 2 = Ah@(Bh+Bl); 3 = AhBh+AhBl+AlBh; 4 = (Ah+Al)@Bh.
// outMode: 0 = fp32 + rank-1 Adj epilogue + batch-min; 1 = fp16 hi(/lo) row-major;
//          2 = fp16 hi(/lo) transposed per batch; 3 = atomicMax into attu (no store).
#define MMA_SMEM (3*32768+1024)

template<int PASSES>
__global__ void __launch_bounds__(128,2) hmma_gemm(
    const __half* __restrict__ Ah, const __half* __restrict__ Al, int lda, long sA,
    const __half* __restrict__ Bh, const __half* __restrict__ Bl, int ldb, long sB,
    int K, int rowsPerZ, int outMode, int relu,
    float* Cf, int ldc, unsigned* minu,
    __half* Ch, __half* Cl, int ldch,
    const float* __restrict__ bias, const float* __restrict__ addv,
    const float* __restrict__ rs, const float* __restrict__ ps,
    const float* __restrict__ mk, unsigned* __restrict__ attu)
{
    constexpr bool A_LO = (PASSES==3 || PASSES==4);
    constexpr bool B_LO = (PASSES==2 || PASSES==3);
    extern __shared__ char smraw[];
    uint32_t sb0 = smem_u32(smraw);
    uint32_t sb  = (sb0 + 1023u) & ~1023u;
    const int tid = threadIdx.x, wid = tid>>5, lane = tid&31;

    const __half* A0 = Ah + blockIdx.z*sA;
    const __half* A1 = A_LO ? (Al + blockIdx.z*sA) : nullptr;
    const __half* B0 = Bh + blockIdx.z*sB;
    const __half* B1 = B_LO ? (Bl + blockIdx.z*sB) : nullptr;
    const int rowBase = blockIdx.y*128, colBase = blockIdx.x*128;
    const int NC = K >> 5;

    const int wr = wid>>1, wc = wid&1;
    const int lr = lane&7, q = lane>>3;
    const int aRowOff = ((q&1)<<3) + lr;
    const int aKbOff  = (q>>1)<<4;
    const int bRowOff = ((q>>1)<<3) + lr;
    const int bKbOff  = (q&1)<<4;

    const int cp_row = tid>>2;
    const int cp_u   = tid&3;

    float acc[4][8][4];
    #pragma unroll
    for (int a=0;a<4;a++)
        #pragma unroll
        for (int b=0;b<8;b++)
            #pragma unroll
            for (int c=0;c<4;c++) acc[a][b][c]=0.f;

    auto load_chunk = [&](int ci, int s){
        const int k0 = ci<<5;
        const uint32_t st = sb + s*32768;
        #pragma unroll
        for (int j=0;j<4;j++){
            int r = cp_row + j*32;
            uint32_t doff = swz64((uint32_t)(r*64 + cp_u*16));
            long aoff = (long)(rowBase+r)*lda + k0 + cp_u*8;
            long boff = (long)(colBase+r)*ldb + k0 + cp_u*8;
            cpasync16(st +         doff, A0 + aoff);
            if (A_LO) cpasync16(st + 8192 + doff, A1 + aoff);
            cpasync16(st + 16384 + doff, B0 + boff);
            if (B_LO) cpasync16(st + 24576 + doff, B1 + boff);
        }
        asm volatile("cp.async.commit_group;" ::: "memory");
    };

    load_chunk(0, 0);
    if (NC > 1) load_chunk(1, 1);

    int sidx = 0;
    int nidx = (NC > 2) ? 2 : 0;
    for (int i=0;i<NC;i++){
        if (i+1 < NC) asm volatile("cp.async.wait_group 1;" ::: "memory");
        else          asm volatile("cp.async.wait_group 0;" ::: "memory");
        __syncthreads();
        if (i+2 < NC){
            load_chunk(i+2, nidx);
            nidx = (nidx==2)?0:nidx+1;
        }
        const uint32_t st = sb + sidx*32768;
        sidx = (sidx==2)?0:sidx+1;
        #pragma unroll
        for (int ks=0;ks<2;ks++){
            const uint32_t kb = ks<<5;
            uint32_t bh[4][4], bl[4][4], af[4][4];
            #pragma unroll
            for (int t=0;t<4;t++){
                uint32_t ro = (uint32_t)((wc*64 + t*16 + bRowOff)*64) + kb + bKbOff;
                ldm4(bh[t], st + 16384 + swz64(ro));
                if (B_LO) ldm4(bl[t], st + 24576 + swz64(ro));
            }
            #pragma unroll
            for (int mi=0;mi<4;mi++){
                uint32_t ro = (uint32_t)((wr*64 + mi*16 + aRowOff)*64) + kb + aKbOff;
                ldm4(af[mi], st + swz64(ro));
            }
            #pragma unroll
            for (int mi=0;mi<4;mi++)
                #pragma unroll
                for (int t=0;t<4;t++){
                    mma16816(acc[mi][2*t],   af[mi], &bh[t][0]);
                    mma16816(acc[mi][2*t+1], af[mi], &bh[t][2]);
                }
            if (B_LO){
                #pragma unroll
                for (int mi=0;mi<4;mi++)
                    #pragma unroll
                    for (int t=0;t<4;t++){
                        mma16816(acc[mi][2*t],   af[mi], &bl[t][0]);
                        mma16816(acc[mi][2*t+1], af[mi], &bl[t][2]);
                    }
            }
            if (A_LO){
                #pragma unroll
                for (int mi=0;mi<4;mi++){
                    uint32_t ro = (uint32_t)((wr*64 + mi*16 + aRowOff)*64) + kb + aKbOff;
                    ldm4(af[mi], st + 8192 + swz64(ro));
                }
                #pragma unroll
                for (int mi=0;mi<4;mi++)
                    #pragma unroll
                    for (int t=0;t<4;t++){
                        mma16816(acc[mi][2*t],   af[mi], &bh[t][0]);
                        mma16816(acc[mi][2*t+1], af[mi], &bh[t][2]);
                    }
            }
        }
    }

    // ---- epilogue ----
    const int cpair = (lane&3)*2;
    if (outMode == 0){
        // Adj: x = acc + ra[gr]*mk[zc] + mk[gr]*ca[zc] + rb[gr] + cb[zc]; fp32 out + batch-min
        float lmin = INFINITY;
        #pragma unroll
        for (int mi=0;mi<4;mi++){
            #pragma unroll
            for (int rr=0;rr<2;rr++){
                const int r  = rowBase + wr*64 + mi*16 + (lane>>2) + rr*8;
                const int gr = blockIdx.z*rowsPerZ + r;
                const int zb = (gr>>9)<<9;
                const float rav = rs[gr], rbv = ps[gr], mrow = mk[gr];
                #pragma unroll
                for (int ni=0;ni<8;ni++){
                    const int c = colBase + wc*64 + ni*8 + cpair;
                    float x0 = acc[mi][ni][rr*2+0] + rav*mk[zb+c]   + mrow*addv[zb+c]   + rbv + bias[zb+c];
                    float x1 = acc[mi][ni][rr*2+1] + rav*mk[zb+c+1] + mrow*addv[zb+c+1] + rbv + bias[zb+c+1];
                    *(float2*)(Cf + (long)gr*ldc + c) = make_float2(x0,x1);
                    lmin = fminf(lmin, fminf(x0,x1));
                }
            }
        }
        #pragma unroll
        for (int o=16;o;o>>=1) lmin = fminf(lmin, __shfl_xor_sync(0xffffffffu, lmin, o));
        if (lane==0) atomicMin(&minu[blockIdx.z], fenc(lmin));
    } else if (outMode == 3){
        // att = max over rows; values >= 0 after relu -> raw-bit atomicMax
        const int b = blockIdx.z;
        #pragma unroll
        for (int ni=0;ni<8;ni++){
            float mx0 = 0.f, mx1 = 0.f;
            const int c = colBase + wc*64 + ni*8 + cpair;
            #pragma unroll
            for (int mi=0;mi<4;mi++){
                #pragma unroll
                for (int rr=0;rr<2;rr++){
                    const int gr = blockIdx.z*rowsPerZ + rowBase + wr*64 + mi*16 + (lane>>2) + rr*8;
                    const float psv = ps ? ps[gr] : 1.f;
                    float x0 = acc[mi][ni][rr*2+0] + bias[c];
                    float x1 = acc[mi][ni][rr*2+1] + bias[c+1];
                    x0 = fmaxf(x0,0.f)*psv; x1 = fmaxf(x1,0.f)*psv;
                    mx0 = fmaxf(mx0,x0); mx1 = fmaxf(mx1,x1);
                }
            }
            atomicMax(&attu[(long)b*RR + c],   __float_as_uint(mx0));
            atomicMax(&attu[(long)b*RR + c+1], __float_as_uint(mx1));
        }
    } else {
        #pragma unroll
        for (int mi=0;mi<4;mi++){
            #pragma unroll
            for (int rr=0;rr<2;rr++){
                const int r  = rowBase + wr*64 + mi*16 + (lane>>2) + rr*8;
                const int gr = blockIdx.z*rowsPerZ + r;
                const float rsv = rs ? rs[gr] : 1.f;
                const float psv = ps ? ps[gr] : 1.f;
                const float* avp = addv ? addv + (long)(gr>>9)*RR : nullptr;
                #pragma unroll
                for (int ni=0;ni<8;ni++){
                    const int c = colBase + wc*64 + ni*8 + cpair;
                    float x0 = acc[mi][ni][rr*2+0];
                    float x1 = acc[mi][ni][rr*2+1];
                    if (avp){ x0 += rsv*avp[c]; x1 += rsv*avp[c+1]; }
                    if (bias){ x0 += bias[c]; x1 += bias[c+1]; }
                    if (relu){ x0 = fmaxf(x0,0.f); x1 = fmaxf(x1,0.f); }
                    x0 *= psv; x1 *= psv;
                    __half h0 = __float2half_rn(x0);
                    __half h1 = __float2half_rn(x1);
                    if (outMode==1){
                        long o = (long)gr*ldch + c;
                        *(__half2*)(Ch+o) = __halves2half2(h0,h1);
                        if (Cl){
                            __half l0 = __float2half_rn(x0-__half2float(h0));
                            __half l1 = __float2half_rn(x1-__half2float(h1));
                            *(__half2*)(Cl+o) = __halves2half2(l0,l1);
                        }
                    } else { // outMode 2: transposed
                        long base = (long)(gr>>9)*((long)RR*NN) + (gr&511);
                        long o0 = base + (long)c*NN;
                        Ch[o0]=h0; Ch[o0+NN]=h1;
                        if (Cl){
                            Cl[o0]   = __float2half_rn(x0-__half2float(h0));
                            Cl[o0+NN]= __float2half_rn(x1-__half2float(h1));
                        }
                    }
                }
            }
        }
    }
}

// ---------------- FFMA split-K GEMM (small matmuls) ----------------
template<bool BT>
__global__ void __launch_bounds__(256) gemm_part(
    const float* __restrict__ A,int lda,
    const float* __restrict__ B,int ldb,
    float* __restrict__ C,int ldc,long partStride,int chunkK)
{
    __shared__ float As[16][64];
    __shared__ float Bs[16][64];
    const int tid = threadIdx.x;
    const int rowBase = blockIdx.y*64, colBase = blockIdx.x*64;
    const int kbeg = blockIdx.z*chunkK, kend = kbeg + chunkK;
    const int tx = tid & 15, ty = tid >> 4;
    float acc[4][4];
#pragma unroll
    for (int i=0;i<4;i++)
#pragma unroll
        for (int j=0;j<4;j++) acc[i][j]=0.f;

    for (int k0=kbeg;k0<kend;k0+=16){
#pragma unroll
        for (int i=tid*4;i<64*16;i+=256*4){
            int r=i>>4, kk=i&15;
            float4 v = *(const float4*)(A + (long)(rowBase+r)*lda + k0 + kk);
            As[kk+0][r]=v.x; As[kk+1][r]=v.y; As[kk+2][r]=v.z; As[kk+3][r]=v.w;
        }
        if (BT){
#pragma unroll
            for (int i=tid*4;i<64*16;i+=256*4){
                int r=i>>4, kk=i&15;
                float4 v = *(const float4*)(B + (long)(colBase+r)*ldb + k0 + kk);
                Bs[kk+0][r]=v.x; Bs[kk+1][r]=v.y; Bs[kk+2][r]=v.z; Bs[kk+3][r]=v.w;
            }
        } else {
#pragma unroll
            for (int i=tid*4;i<16*64;i+=256*4){
                int r=i>>6, cc=i&63;
                *(float4*)&Bs[r][cc] = *(const float4*)(B + (long)(k0+r)*ldb + colBase + cc);
            }
        }
        __syncthreads();
#pragma unroll
        for (int k=0;k<16;k++){
            float a[4], b[4];
            *(float4*)a = *(const float4*)&As[k][ty*4];
            *(float4*)b = *(const float4*)&Bs[k][tx*4];
#pragma unroll
            for (int i=0;i<4;i++)
#pragma unroll
                for (int j=0;j<4;j++) acc[i][j] = fmaf(a[i], b[j], acc[i][j]);
        }
        __syncthreads();
    }
    float* Cp = C + (long)blockIdx.z*partStride;
#pragma unroll
    for (int i=0;i<4;i++){
        int r = rowBase + ty*4 + i;
#pragma unroll
        for (int j=0;j<4;j++)
            Cp[(long)r*ldc + colBase + tx*4 + j] = acc[i][j];
    }
}
static void sgemm(bool BT,const float* A,int lda,const float* B,int ldb,float* Cpart,int ldc,
                  int M,int N,int K,int splits,cudaStream_t st=0){
    dim3 g(N/64, M/64, splits);
    int chunkK = K/splits;
    if (BT) gemm_part<true ><<<g,256,0,st>>>(A,lda,B,ldb,Cpart,ldc,(long)M*ldc,chunkK);
    else    gemm_part<false><<<g,256,0,st>>>(A,lda,B,ldb,Cpart,ldc,(long)M*ldc,chunkK);
}
__global__ void reduce_kernel(float* dst,const float* src,long len,int splits,int colmask,
                              const float* b1,const float* b2){
    long i = (long)blockIdx.x*blockDim.x+threadIdx.x;
    if (i >= len) return;
    float s = 0.f;
    for (int z=0;z<splits;z++) s += src[z*len+i];
    int col = (int)(i & colmask);
    if (b1) s += b1[col];
    if (b2) s += b2[col];
    dst[i] = s;
}

// ---------------- conversions ----------------
__device__ __forceinline__ void split1(float v, __half& h, __half& l){
    h = __float2half_rn(v);
    l = __float2half_rn(v - __half2float(h));
}
__global__ void conv_mask_kernel(const float* __restrict__ src, const float* __restrict__ mask,
                                 __half* __restrict__ dh, long n4, unsigned* minu){
    long i = (long)blockIdx.x*blockDim.x + threadIdx.x;
    if (i < BB && minu) minu[i] = 0xFFFFFFFFu;
    if (i >= n4) return;
    float4 v = ((const float4*)src)[i];
    float m = mask[i >> 8];
    __align__(8) __half h[4];
    h[0]=__float2half_rn(v.x*m); h[1]=__float2half_rn(v.y*m);
    h[2]=__float2half_rn(v.z*m); h[3]=__float2half_rn(v.w*m);
    ((uint2*)dh)[i] = *(uint2*)h;
}
// transpose+convert hi/lo: src [1024 rows, ld cols] left 1024 block -> dst [1024,1024]
__global__ void tconv2_kernel(const float* __restrict__ src, int ld,
                              __half* __restrict__ dh, __half* __restrict__ dl){
    __shared__ float t[32][33];
    int r0 = blockIdx.y*32, c0 = blockIdx.x*32;
    int tx = threadIdx.x, ty = threadIdx.y;
    for (int i=ty;i<32;i+=8)
        t[i][tx] = src[(long)(r0+i)*ld + c0+tx];
    __syncthreads();
    for (int i=ty;i<32;i+=8){
        __half h,l; split1(t[tx][i], h, l);
        long o = (long)(c0+i)*1024 + r0+tx;
        dh[o]=h; dl[o]=l;
    }
}
__global__ void tconv_kernel(const float* __restrict__ src, int rows, int cols,
                             __half* __restrict__ dh){
    __shared__ float t[32][33];
    int r0 = blockIdx.y*32, c0 = blockIdx.x*32;
    int tx = threadIdx.x, ty = threadIdx.y;
    for (int i=ty;i<32;i+=8)
        t[i][tx] = src[(long)(r0+i)*cols + c0+tx];
    __syncthreads();
    for (int i=ty;i<32;i+=8){
        long o = (long)(c0+i)*rows + r0+tx;
        dh[o] = __float2half_rn(t[tx][i]);
    }
}
// out[f] = sum_o b[o] * W[o*ld + f]
__global__ void mv_kernel(const float* __restrict__ b, const float* __restrict__ W, int ld,
                          float* __restrict__ out){
    int f = blockIdx.x*blockDim.x + threadIdx.x;
    if (f >= RR) return;
    float s = 0.f;
    for (int o=0;o<RR;o++) s += b[o]*W[(long)o*ld + f];
    out[f] = s;
}
// scalars: s_mm[b]=g1.g2, s_m1[b]=g1.b2, s_1m[b]=b1.g2, s11=b1.b2
__global__ void scalars_kernel(const float* ht1,const float* ht2,const float* b1,const float* b2,
                               float* smm,float* sm1,float* s1m,float* s11){
    __shared__ float red[3][256];
    int b = blockIdx.x, t = threadIdx.x;
    const float* g1 = ht1 + b*RR;
    const float* g2 = ht2 + b*RR;
    float a0=0,a1=0,a2=0;
    for (int k=t;k<RR;k+=256){
        float x1=g1[k], x2=g2[k];
        a0 += x1*x2; a1 += x1*b2[k]; a2 += b1[k]*x2;
    }
    red[0][t]=a0; red[1][t]=a1; red[2][t]=a2; __syncthreads();
    for (int s=128;s>0;s>>=1){
        if (t<s){ red[0][t]+=red[0][t+s]; red[1][t]+=red[1][t+s]; red[2][t]+=red[2][t+s]; }
        __syncthreads();
    }
    if (t==0){ smm[b]=red[0][0]; sm1[b]=red[1][0]; s1m[b]=red[2][0]; }
    if (b==0){
        __shared__ float r2[256];
        float a=0;
        for (int k=t;k<RR;k+=256) a += b1[k]*b2[k];
        r2[t]=a; __syncthreads();
        for (int s=128;s>0;s>>=1){ if (t<s) r2[t]+=r2[t+s]; __syncthreads(); }
        if (t==0) s11[0]=r2[0];
    }
}
// rank-1 vectors: warp per (b,n): 4 dots of GEMh row with Vra[b]/Vrb/Vca[b]/Vcb
__global__ void ranks_kernel(const __half* __restrict__ G,
                             const float* __restrict__ Vra,const float* __restrict__ Vrb,
                             const float* __restrict__ Vca,const float* __restrict__ Vcb,
                             const float* smm,const float* sm1,const float* s1m,const float* s11,
                             const float* __restrict__ mask,
                             float* ra,float* rb,float* ca,float* cb){
    int row = blockIdx.x*8 + (threadIdx.x>>5);
    int lane = threadIdx.x & 31;
    int b = row >> 9;
    const __half2* g2p = (const __half2*)(G + (long)row*RR);
    const float* vra = Vra + b*RR;
    const float* vca = Vca + b*RR;
    float d1=0,d2=0,d3=0,d4=0;
    for (int k=lane;k<RR/2;k+=32){
        __half2 h = g2p[k];
        float g0 = __low2float(h), g1 = __high2float(h);
        int f = k*2;
        d1 += g0*vra[f] + g1*vra[f+1];
        d2 += g0*Vrb[f] + g1*Vrb[f+1];
        d3 += g0*vca[f] + g1*vca[f+1];
        d4 += g0*Vcb[f] + g1*Vcb[f+1];
    }
    #pragma unroll
    for (int o=16;o;o>>=1){
        d1 += __shfl_xor_sync(0xffffffffu,d1,o);
        d2 += __shfl_xor_sync(0xffffffffu,d2,o);
        d3 += __shfl_xor_sync(0xffffffffu,d3,o);
        d4 += __shfl_xor_sync(0xffffffffu,d4,o);
    }
    if (lane==0){
        ra[row] = d1 + s1m[b];
        rb[row] = d2 + s11[0];
        ca[row] = d3 + smm[b]*mask[row] + sm1[b];
        cb[row] = d4;
    }
}
__global__ void clear_attu(unsigned* attu){
    int i = blockIdx.x*blockDim.x + threadIdx.x;
    if (i < BB*RR) attu[i] = 0u;
}

// ---------------- pointwise / reductions ----------------
__device__ __forceinline__ float sigm(float x){ return 1.f/(1.f+__expf(-x)); }

__global__ void concat3_kernel(const float* a,const float* b,const float* c,float* out){
    int idx = blockIdx.x*blockDim.x+threadIdx.x;
    if (idx >= BB*3072) return;
    int bb = idx/3072, j = idx%3072;
    out[idx] = (j<1024) ? a[bb*1024+j] : (j<2048 ? b[bb*1024+j-1024] : c[bb*1024+j-2048]);
}
__global__ void concat2_kernel(const unsigned* a,const float* b,float* out){
    int idx = blockIdx.x*blockDim.x+threadIdx.x;
    if (idx >= BB*2048) return;
    int bb = idx/2048, j = idx%2048;
    out[idx] = (j<1024) ? __uint_as_float(a[bb*1024+j]) : b[bb*1024+j-1024];
}
__global__ void lstm_kernel(const float* gates,const float* c_prev,float* h_out,float* c_out){
    int idx = blockIdx.x*blockDim.x+threadIdx.x;
    if (idx >= BR) return;
    int bb = idx >> 10, r = idx & 1023;
    const float* g = gates + bb*4096;
    float c = sigm(g[1024+r])*c_prev[idx] + sigm(g[r])*tanhf(g[2048+r]);
    h_out[idx] = sigm(g[3072+r])*tanhf(c);
    c_out[idx] = c;
}
__global__ void __launch_bounds__(512) topk_kernel(const float* __restrict__ Adj,
                                                   const unsigned* __restrict__ minu,
                                                   const float* __restrict__ mask,
                                                   __half* __restrict__ Araw, float* dvec){
    __shared__ unsigned long long sk[NN];
    __shared__ float red[NN];
    int row = blockIdx.x, t = threadIdx.x, bb = row >> 9;
    float mrow = mask[row];
    float mn = fdec(minu[bb]);
    float v = (Adj[(long)row*NN + t] - mn) * mrow;
    unsigned long long key = ((unsigned long long)__float_as_uint(v) << 32) | (unsigned)(NN-1-t);
    #pragma unroll
    for (unsigned k2=2;k2<=NN;k2<<=1){
        for (unsigned j=k2>>1;j>0;j>>=1){
            unsigned long long other;
            if (j < 32){
                unsigned lo = __shfl_xor_sync(0xffffffffu, (unsigned)key, j);
                unsigned hi = __shfl_xor_sync(0xffffffffu, (unsigned)(key>>32), j);
                other = ((unsigned long long)hi << 32) | lo;
            } else {
                sk[t] = key; __syncthreads();
                other = sk[t ^ j]; __syncthreads();
            }
            bool lower = ((t & j) == 0);
            bool desc  = ((t & k2) == 0);
            unsigned long long mx  = (key > other) ? key : other;
            unsigned long long mnk = (key > other) ? other : key;
            key = (desc == lower) ? mx : mnk;
        }
    }
    int col = (NN-1) - (int)(unsigned)(key & 0xffffffffu);
    float val = __uint_as_float((unsigned)(key >> 32));
    __half* ar = Araw + (long)row*NN;
    ar[t] = __float2half_rn(0.f);
    __syncthreads();
    float s = 0.f;
    if (t < KTOP){
        ar[col] = __float2half_rn(val);
        s = val;
    }
    red[t]=s; __syncthreads();
    for (int st=NN/2;st>0;st>>=1){ if (t<st) red[t]+=red[t+st]; __syncthreads(); }
    if (t==0) dvec[row] = (red[0] > 0.f) ? rsqrtf(red[0]) : 0.f;
}
__global__ void rowfinal_kernel(__half* __restrict__ Ah, const float* __restrict__ dvec,
                                const float* __restrict__ mask, float* __restrict__ srow){
    int row = blockIdx.x*8 + (threadIdx.x>>5);
    int lane = threadIdx.x & 31;
    int bb = row >> 9;
    const float dr = dvec[row];
    const float* dc = dvec + (bb<<9);
    const float* m  = mask + (bb<<9);
    __half* ar = Ah + (long)row*NN;
    float s = 0.f;
    for (int k=lane*4; k<NN; k+=128){
        uint2 raw = *(uint2*)(ar+k);
        __align__(8) __half h[4]; *(uint2*)h = raw;
        float4 d4 = *(const float4*)(dc+k);
        float4 m4 = *(const float4*)(m+k);
        float x0=__half2float(h[0])*dr*d4.x, x1=__half2float(h[1])*dr*d4.y;
        float x2=__half2float(h[2])*dr*d4.z, x3=__half2float(h[3])*dr*d4.w;
        s += x0*m4.x + x1*m4.y + x2*m4.z + x3*m4.w;
        h[0]=__float2half_rn(x0); h[1]=__float2half_rn(x1);
        h[2]=__float2half_rn(x2); h[3]=__float2half_rn(x3);
        *(uint2*)(ar+k) = *(uint2*)h;
    }
    for (int o=16;o;o>>=1) s += __shfl_xor_sync(0xffffffffu, s, o);
    if (lane==0) srow[row] = s;
}
__global__ void pack_kernel(const float* hatt,const float* catt,
                            const float* hlang,const float* clang,float* out,int out_size){
    int i = blockIdx.x*blockDim.x+threadIdx.x;
    if (i >= BR) return;
    out[i] = hlang[i];
    if (out_size >= 5*BR){
        out[1*BR+i] = hatt[i];
        out[2*BR+i] = hlang[i];
        out[3*BR+i] = catt[i];
        out[4*BR+i] = clang[i];
    }
}

// ---------------- host driver ----------------
struct Ptrs {
    float *adj,*xcat,*gates,*gates2,*part,*ht1,*ht2,*pvec,*srow,*dvec,*xl,*hatt,*catt,*hlang,*clang;
    float *Vra,*Vca,*Vrb,*Vcb,*smm,*sm1,*s1m,*s11,*ra,*rb,*ca,*cb;
    unsigned *minu,*attu;
    __half *Ph,*Qh,*Ql,*Sh,*Sl,*Z0h,*ADJh;
    __half *W1h,*W1l,*W2h,*W2l,*Wmh,*Wml,*G0h,*G1h,*G2h;
};
static Ptrs P;
static bool g_init = false;
static cudaStream_t g_s2;
static cudaEvent_t g_ev1, g_ev_mv, g_ev_u, g_ev3;

extern "C" void kernel_launch(void* const* d_in, const int* in_sizes, int n_in,
                              void* d_out, int out_size)
{
    const float* xt   = (const float*)d_in[0];
    const float* fc   = (const float*)d_in[1];
    const float* ge   = (const float*)d_in[2];
    const float* sh   = (const float*)d_in[4];
    const float* sc   = (const float*)d_in[5];
    const float* mask = (const float*)d_in[6];
    const float* aWih = (const float*)d_in[7];
    const float* aWhh = (const float*)d_in[8];
    const float* abih = (const float*)d_in[9];
    const float* abhh = (const float*)d_in[10];
    const float* lWih = (const float*)d_in[11];
    const float* lWhh = (const float*)d_in[12];
    const float* lbih = (const float*)d_in[13];
    const float* lbhh = (const float*)d_in[14];
    const float* e1W  = (const float*)d_in[15];
    const float* e1b  = (const float*)d_in[16];
    const float* e2W  = (const float*)d_in[17];
    const float* e2b  = (const float*)d_in[18];
    const float* gW0  = (const float*)d_in[19];
    const float* gb0  = (const float*)d_in[20];
    const float* gW1  = (const float*)d_in[21];
    const float* gb1  = (const float*)d_in[22];
    const float* gW2  = (const float*)d_in[23];
    const float* gb2  = (const float*)d_in[24];
    (void)in_sizes; (void)n_in;
    float* out = (float*)d_out;

    if (!g_init){
        cudaGetSymbolAddress((void**)&P.adj,  g_adj);
        cudaGetSymbolAddress((void**)&P.minu, g_minu);
        cudaGetSymbolAddress((void**)&P.xcat, g_xcat);
        cudaGetSymbolAddress((void**)&P.gates,g_gates);
        cudaGetSymbolAddress((void**)&P.gates2,g_gates2);
        cudaGetSymbolAddress((void**)&P.part, g_part);
        cudaGetSymbolAddress((void**)&P.ht1,  g_ht1);
        cudaGetSymbolAddress((void**)&P.ht2,  g_ht2);
        cudaGetSymbolAddress((void**)&P.pvec, g_pvec);
        cudaGetSymbolAddress((void**)&P.srow, g_srow);
        cudaGetSymbolAddress((void**)&P.dvec, g_dvec);
        cudaGetSymbolAddress((void**)&P.attu, g_attu);
        cudaGetSymbolAddress((void**)&P.xl,   g_xl);
        cudaGetSymbolAddress((void**)&P.hatt, g_hatt);
        cudaGetSymbolAddress((void**)&P.catt, g_catt);
        cudaGetSymbolAddress((void**)&P.hlang,g_hlang);
        cudaGetSymbolAddress((void**)&P.clang,g_clang);
        cudaGetSymbolAddress((void**)&P.Vra, g_Vra); cudaGetSymbolAddress((void**)&P.Vca, g_Vca);
        cudaGetSymbolAddress((void**)&P.Vrb, g_Vrb); cudaGetSymbolAddress((void**)&P.Vcb, g_Vcb);
        cudaGetSymbolAddress((void**)&P.smm, g_smm); cudaGetSymbolAddress((void**)&P.sm1, g_sm1);
        cudaGetSymbolAddress((void**)&P.s1m, g_s1m); cudaGetSymbolAddress((void**)&P.s11, g_s11);
        cudaGetSymbolAddress((void**)&P.ra, g_ra); cudaGetSymbolAddress((void**)&P.rb, g_rb);
        cudaGetSymbolAddress((void**)&P.ca, g_ca); cudaGetSymbolAddress((void**)&P.cb, g_cb);
        cudaGetSymbolAddress((void**)&P.Ph, g_Ph);
        cudaGetSymbolAddress((void**)&P.Qh, g_Qh); cudaGetSymbolAddress((void**)&P.Ql, g_Ql);
        cudaGetSymbolAddress((void**)&P.Sh, g_Sh); cudaGetSymbolAddress((void**)&P.Sl, g_Sl);
        cudaGetSymbolAddress((void**)&P.Z0h, g_Z0h);
        cudaGetSymbolAddress((void**)&P.ADJh, g_ADJh);
        cudaGetSymbolAddress((void**)&P.W1h, g_W1h); cudaGetSymbolAddress((void**)&P.W1l, g_W1l);
        cudaGetSymbolAddress((void**)&P.W2h, g_W2h); cudaGetSymbolAddress((void**)&P.W2l, g_W2l);
        cudaGetSymbolAddress((void**)&P.Wmh, g_Wmh); cudaGetSymbolAddress((void**)&P.Wml, g_Wml);
        cudaGetSymbolAddress((void**)&P.G0h, g_G0h);
        cudaGetSymbolAddress((void**)&P.G1h, g_G1h);
        cudaGetSymbolAddress((void**)&P.G2h, g_G2h);
        cudaFuncSetAttribute(hmma_gemm<1>, cudaFuncAttributeMaxDynamicSharedMemorySize, MMA_SMEM);
        cudaFuncSetAttribute(hmma_gemm<2>, cudaFuncAttributeMaxDynamicSharedMemorySize, MMA_SMEM);
        cudaFuncSetAttribute(hmma_gemm<3>, cudaFuncAttributeMaxDynamicSharedMemorySize, MMA_SMEM);
        cudaFuncSetAttribute(hmma_gemm<4>, cudaFuncAttributeMaxDynamicSharedMemorySize, MMA_SMEM);
        cudaStreamCreateWithFlags(&g_s2, cudaStreamNonBlocking);
        cudaEventCreateWithFlags(&g_ev1, cudaEventDisableTiming);
        cudaEventCreateWithFlags(&g_ev_mv, cudaEventDisableTiming);
        cudaEventCreateWithFlags(&g_ev_u, cudaEventDisableTiming);
        cudaEventCreateWithFlags(&g_ev3, cudaEventDisableTiming);
        g_init = true;
    }

    const float* prev_h = sh + BR;
    const float* h0 = sh;
    const float* c0 = sc;
    const float* c1 = sc + BR;

    // ---- fork ----
    cudaEventRecord(g_ev1, 0);
    cudaStreamWaitEvent(g_s2, g_ev1, 0);

    // s2: GEM conversion, Wmt, matvecs, U, then GCN prep
    conv_mask_kernel<<<(int)((NGE/4+255)/256),256,0,g_s2>>>(ge, mask, P.Ph, NGE/4, P.minu);
    tconv2_kernel<<<dim3(32,32),dim3(32,8),0,g_s2>>>(e1W, 2048, P.W1h, P.W1l);   // TA [f,o]
    tconv2_kernel<<<dim3(32,32),dim3(32,8),0,g_s2>>>(e2W, 2048, P.W2h, P.W2l);   // TB [f',o]
    // Wmt = TB @ TA^T  (3-pass)
    hmma_gemm<3><<<dim3(8,8,1),128,MMA_SMEM,g_s2>>>(P.W2h,P.W2l,1024,0, P.W1h,P.W1l,1024,0,
        1024, 0, 1, 0, nullptr,0,nullptr, P.Wmh,P.Wml,1024, nullptr,nullptr,nullptr,nullptr,nullptr,nullptr);
    mv_kernel<<<4,256,0,g_s2>>>(e2b, e1W, 2048, P.Vrb);
    mv_kernel<<<4,256,0,g_s2>>>(e1b, e2W, 2048, P.Vcb);
    cudaEventRecord(g_ev_mv, g_s2);
    // U = GEM @ Wmt^T  (2-pass) -> Qh/Ql
    hmma_gemm<2><<<dim3(8,256,1),128,MMA_SMEM,g_s2>>>(P.Ph,nullptr,1024,0, P.Wmh,P.Wml,1024,0,
        1024, 0, 1, 0, nullptr,0,nullptr, P.Qh,P.Ql,1024, nullptr,nullptr,nullptr,nullptr,nullptr,nullptr);
    cudaEventRecord(g_ev_u, g_s2);
    tconv_kernel<<<dim3(32,32),dim3(32,8),0,g_s2>>>(gW0, 1024, 1024, P.G0h);
    hmma_gemm<1><<<dim3(8,256,1),128,MMA_SMEM,g_s2>>>(P.Ph,nullptr,1024,0, P.G0h,nullptr,1024,0,
        1024, 0, 2, 0, nullptr,0,nullptr, P.Z0h,nullptr,0, nullptr,nullptr,nullptr,nullptr,nullptr,nullptr);
    tconv_kernel<<<dim3(32,32),dim3(32,8),0,g_s2>>>(gW1, 1024, 1024, P.G1h);
    tconv_kernel<<<dim3(32,32),dim3(32,8),0,g_s2>>>(gW2, 1024, 1024, P.G2h);
    clear_attu<<<BB*RR/256,256,0,g_s2>>>(P.attu);
    cudaEventRecord(g_ev3, g_s2);

    // default stream: LSTM chain + rank-1 prep
    concat3_kernel<<<(BB*3072+255)/256,256>>>(prev_h, fc, xt, P.xcat);
    sgemm(true, P.xcat,3072, aWih,3072, P.part,            4096, BB,4096,3072, 3);
    sgemm(true, h0,1024,     aWhh,1024, P.part+3*BB*4096,  4096, BB,4096,1024, 1);
    reduce_kernel<<<(BB*4096+255)/256,256>>>(P.gates, P.part, BB*4096, 4, 4095, abih, abhh);
    lstm_kernel<<<(BR+255)/256,256>>>(P.gates, c0, P.hatt, P.catt);
    sgemm(true, P.hatt,1024, e1W+1024,2048, P.part, 1024, BB,1024,1024, 4);
    reduce_kernel<<<(BB*1024+255)/256,256>>>(P.ht1, P.part, BB*1024, 4, 1023, nullptr, nullptr);
    sgemm(true, P.hatt,1024, e2W+1024,2048, P.part, 1024, BB,1024,1024, 4);
    reduce_kernel<<<(BB*1024+255)/256,256>>>(P.ht2, P.part, BB*1024, 4, 1023, nullptr, nullptr);
    sgemm(false, prev_h,1024, gW0+1024*1024,1024, P.part, 1024, BB,1024,1024, 4);
    reduce_kernel<<<(BB*1024+255)/256,256>>>(P.pvec, P.part, BB*1024, 4, 1023, nullptr, nullptr);
    // Vra = ht2 @ e1W-left ; Vca = ht1 @ e2W-left
    sgemm(false, P.ht2,1024, e1W,2048, P.Vra, 1024, BB,1024,1024, 1);
    sgemm(false, P.ht1,1024, e2W,2048, P.Vca, 1024, BB,1024,1024, 1);
    scalars_kernel<<<BB,256>>>(P.ht1, P.ht2, e1b, e2b, P.smm, P.sm1, P.s1m, P.s11);
    cudaStreamWaitEvent(0, g_ev_mv, 0);   // GEM + Vrb/Vcb ready
    ranks_kernel<<<BB*NN/8,256>>>(P.Ph, P.Vra, P.Vrb, P.Vca, P.Vcb,
                                  P.smm, P.sm1, P.s1m, P.s11, mask,
                                  P.ra, P.rb, P.ca, P.cb);
    cudaStreamWaitEvent(0, g_ev_u, 0);    // U ready

    // ---- Adj = U @ GEM^T + rank-1s (PASSES=4: (Uh+Ul)@GEMh) ----
    hmma_gemm<4><<<dim3(4,4,64),128,MMA_SMEM>>>(P.Qh,P.Ql,1024,(long)NN*RR, P.Ph,nullptr,1024,(long)NN*RR,
        1024, 512, 0, 0, P.adj,512,P.minu, nullptr,nullptr,0, P.cb, P.ca, P.ra, P.rb, mask, nullptr);

    // ---- Adj post-processing ----
    topk_kernel<<<BB*NN,512>>>(P.adj, P.minu, mask, P.ADJh, P.dvec);
    rowfinal_kernel<<<BB*NN/8,256>>>(P.ADJh, P.dvec, mask, P.srow);

    cudaStreamWaitEvent(0, g_ev3, 0);     // Z0, G1/G2, attu clear ready

    // ---- GCN layer 0: X1 = relu(Adj@Z0 + srow*pvec + b0)*m ----
    hmma_gemm<1><<<dim3(8,4,64),128,MMA_SMEM>>>(P.ADJh,nullptr,512,(long)NN*NN, P.Z0h,nullptr,512,(long)RR*NN,
        512, 512, 1, 1, nullptr,0,nullptr, P.Sh,nullptr,1024, gb0, P.pvec, P.srow, mask, nullptr, nullptr);

    // ---- GCN layer 1 ----
    hmma_gemm<1><<<dim3(8,256,1),128,MMA_SMEM>>>(P.Sh,nullptr,1024,0, P.G1h,nullptr,1024,0,
        1024, 0, 2, 0, nullptr,0,nullptr, P.Ph,nullptr,0, nullptr,nullptr,nullptr,nullptr,nullptr,nullptr);
    hmma_gemm<1><<<dim3(8,4,64),128,MMA_SMEM>>>(P.ADJh,nullptr,512,(long)NN*NN, P.Ph,nullptr,512,(long)RR*NN,
        512, 512, 1, 1, nullptr,0,nullptr, P.Qh,nullptr,1024, gb1, nullptr, nullptr, mask, nullptr, nullptr);

    // ---- GCN layer 2: fused col-max via atomicMax (outMode 3) ----
    hmma_gemm<1><<<dim3(8,256,1),128,MMA_SMEM>>>(P.Qh,nullptr,1024,0, P.G2h,nullptr,1024,0,
        1024, 0, 2, 0, nullptr,0,nullptr, P.Sh,nullptr,0, nullptr,nullptr,nullptr,nullptr,nullptr,nullptr);
    hmma_gemm<1><<<dim3(8,4,64),128,MMA_SMEM>>>(P.ADJh,nullptr,512,(long)NN*NN, P.Sh,nullptr,512,(long)RR*NN,
        512, 512, 3, 1, nullptr,0,nullptr, nullptr,nullptr,0, gb2, nullptr, nullptr, mask, nullptr, P.attu);

    // ---- language LSTM ----
    concat2_kernel<<<(BB*2048+255)/256,256>>>(P.attu, P.hatt, P.xl);
    sgemm(true, P.xl,2048,   lWih,2048, P.part,           4096, BB,4096,2048, 2);
    sgemm(true, prev_h,1024, lWhh,1024, P.part+2*BB*4096, 4096, BB,4096,1024, 1);
    reduce_kernel<<<(BB*4096+255)/256,256>>>(P.gates2, P.part, BB*4096, 3, 4095, lbih, lbhh);
    lstm_kernel<<<(BR+255)/256,256>>>(P.gates2, c1, P.hlang, P.clang);

    pack_kernel<<<(BR+255)/256,256>>>(P.hatt, P.catt, P.hlang, P.clang, out, out_size);
}